// round 1
// baseline (speedup 1.0000x reference)
#include <cuda_runtime.h>
#include <cuda_bf16.h>

// Problem constants
#define BB   2
#define LL   4096
#define DIN  512
#define HH   8
#define DK   64
#define DV   64
#define DOUT 512

// ---------------------------------------------------------------------------
// Scratch (device globals; no allocation allowed in kernel_launch)
// ---------------------------------------------------------------------------
#define GRAM_SPLIT 4
__device__ float g_Gp[GRAM_SPLIT * BB * DIN * DIN]; // gram partials, z = s*BB + b
__device__ float g_G [BB * DIN * DIN];              // G[b] = x_b^T x_b
__device__ float g_T1[BB * HH * DK * DIN];          // T1[b][h] = W_k[h]^T G[b]   (64 x 512)
__device__ float g_M [BB * HH * DK * DV];           // M[b][h]  = T1 W_v[h]       (64 x 64)
__device__ float g_T2[BB * DIN * (HH * DV)];        // T2cat[b][i][h*64+v] = (W_q[h] M[b][h])[i][v]
__device__ float g_U [BB * DIN * DOUT];             // U[b] = T2cat[b] @ Wo_flat  (512 x 512)

// ---------------------------------------------------------------------------
// f32x2 packed-FMA helpers (Blackwell dual-rate fp32 path)
// ---------------------------------------------------------------------------
__device__ __forceinline__ unsigned long long pack2(float a) {
    unsigned long long r;
    asm("mov.b64 %0, {%1, %1};" : "=l"(r) : "f"(a));
    return r;
}
__device__ __forceinline__ void fma2(unsigned long long& acc,
                                     unsigned long long a,
                                     unsigned long long b) {
    asm("fma.rn.f32x2 %0, %1, %2, %0;" : "+l"(acc) : "l"(a), "l"(b));
}
__device__ __forceinline__ float lo32(unsigned long long v) {
    return __uint_as_float((unsigned)(v & 0xffffffffull));
}
__device__ __forceinline__ float hi32(unsigned long long v) {
    return __uint_as_float((unsigned)(v >> 32));
}

// ---------------------------------------------------------------------------
// Generic tiled GEMM: C = op(A) * B, 64x64 output tile, BK=16, 256 threads,
// 4x4 outputs per thread (as 4x2 f32x2 pairs).
//   TA=false: A is (M x K) row-major, element (m,k) = A[m*lda + k]
//   TA=true : A is stored (K x M),  element (m,k) = A[k*lda + m]
//   B is (K x N) row-major (ldb), C is (M x N) row-major (ldc).
// Batch: z = blockIdx.z; offset = (z%zdiv)*|bl| + (z/zdiv)*|bh| per matrix.
// All of M, N must be multiples of 64 and K a multiple of 16 (true for every
// launch below), so there are no bounds checks.
// ---------------------------------------------------------------------------
template <bool TA>
__global__ void __launch_bounds__(256)
gemm64(const float* __restrict__ A, const float* __restrict__ B,
       float* __restrict__ C,
       int K, int lda, int ldb, int ldc, int zdiv,
       long abl, long abh, long bbl, long bbh, long cbl, long cbh)
{
    __shared__ __align__(16) float Asm[TA ? (16 * 64) : (64 * 17)];
    __shared__ __align__(16) float Bsm[16 * 64];

    const int t  = threadIdx.x;
    const int tx = t & 15;        // output column group
    const int ty = t >> 4;        // output row group
    const int z  = blockIdx.z;
    const int m0 = blockIdx.y * 64;
    const int n0 = blockIdx.x * 64;

    A += (long)(z % zdiv) * abl + (long)(z / zdiv) * abh;
    B += (long)(z % zdiv) * bbl + (long)(z / zdiv) * bbh;
    C += (long)(z % zdiv) * cbl + (long)(z / zdiv) * cbh;

    // global-load pointers
    const float* Aptr;
    if (TA) Aptr = A + (long)(t >> 4) * lda + m0 + (t & 15) * 4;     // 16x64 tile, k-major
    else    Aptr = A + (long)(m0 + (t >> 2)) * lda + (t & 3) * 4;    // 64x16 tile, m-major
    const float* Bptr = B + (long)(t >> 4) * ldb + n0 + (t & 15) * 4;

    unsigned long long acc[4][2];
#pragma unroll
    for (int i = 0; i < 4; i++) { acc[i][0] = 0ull; acc[i][1] = 0ull; }

    const int ktiles = K / 16;
    float4 ra = *(const float4*)Aptr;
    float4 rb = *(const float4*)Bptr;

    for (int kt = 0; kt < ktiles; kt++) {
        // stage current tile to smem
        if (TA) {
            *(float4*)&Asm[(t >> 4) * 64 + (t & 15) * 4] = ra;
        } else {
            const int r = (t >> 2), c = (t & 3) * 4;
            Asm[r * 17 + c + 0] = ra.x;
            Asm[r * 17 + c + 1] = ra.y;
            Asm[r * 17 + c + 2] = ra.z;
            Asm[r * 17 + c + 3] = ra.w;
        }
        *(float4*)&Bsm[(t >> 4) * 64 + (t & 15) * 4] = rb;
        __syncthreads();

        // prefetch next tile
        if (kt + 1 < ktiles) {
            Aptr += TA ? 16 * lda : 16;
            Bptr += 16 * ldb;
            ra = *(const float4*)Aptr;
            rb = *(const float4*)Bptr;
        }

        // compute
#pragma unroll
        for (int kk = 0; kk < 16; kk++) {
            float a0, a1, a2, a3;
            if (TA) {
                float4 av = *(const float4*)&Asm[kk * 64 + ty * 4];
                a0 = av.x; a1 = av.y; a2 = av.z; a3 = av.w;
            } else {
                a0 = Asm[(ty * 4 + 0) * 17 + kk];
                a1 = Asm[(ty * 4 + 1) * 17 + kk];
                a2 = Asm[(ty * 4 + 2) * 17 + kk];
                a3 = Asm[(ty * 4 + 3) * 17 + kk];
            }
            ulonglong2 bb = *(const ulonglong2*)&Bsm[kk * 64 + tx * 4];
            unsigned long long p;
            p = pack2(a0); fma2(acc[0][0], p, bb.x); fma2(acc[0][1], p, bb.y);
            p = pack2(a1); fma2(acc[1][0], p, bb.x); fma2(acc[1][1], p, bb.y);
            p = pack2(a2); fma2(acc[2][0], p, bb.x); fma2(acc[2][1], p, bb.y);
            p = pack2(a3); fma2(acc[3][0], p, bb.x); fma2(acc[3][1], p, bb.y);
        }
        __syncthreads();
    }

    // epilogue
#pragma unroll
    for (int i = 0; i < 4; i++) {
        float4 o;
        o.x = lo32(acc[i][0]); o.y = hi32(acc[i][0]);
        o.z = lo32(acc[i][1]); o.w = hi32(acc[i][1]);
        *(float4*)&C[(long)(m0 + ty * 4 + i) * ldc + n0 + tx * 4] = o;
    }
}

// Reduce gram split-K partials: G[b][e] = sum_s Gp[(s*BB + b)][e]
__global__ void __launch_bounds__(256)
reduce_gram(const float* __restrict__ P, float* __restrict__ G)
{
    const int i = blockIdx.x * 256 + threadIdx.x;   // over BB*DIN*DIN
    const int b = i >> 18;                           // / (512*512)
    const int e = i & ((DIN * DIN) - 1);
    float s = 0.f;
#pragma unroll
    for (int sp = 0; sp < GRAM_SPLIT; sp++)
        s += P[(long)(sp * BB + b) * (DIN * DIN) + e];
    G[i] = s;
}

// ---------------------------------------------------------------------------
// kernel_launch: 7 graph-capturable launches, default stream
// ---------------------------------------------------------------------------
extern "C" void kernel_launch(void* const* d_in, const int* in_sizes, int n_in,
                              void* d_out, int out_size)
{
    (void)in_sizes; (void)n_in; (void)out_size;
    const float* x  = (const float*)d_in[0];  // (B, L, DIN)
    const float* Wq = (const float*)d_in[1];  // (H, DIN, DK)
    const float* Wk = (const float*)d_in[2];  // (H, DIN, DK)
    const float* Wv = (const float*)d_in[3];  // (H, DIN, DV)
    const float* Wo = (const float*)d_in[4];  // (H, DV, DOUT)
    float* out = (float*)d_out;               // (B, L, DOUT)

    void* p;
    cudaGetSymbolAddress(&p, g_Gp); float* Gp = (float*)p;
    cudaGetSymbolAddress(&p, g_G ); float* G  = (float*)p;
    cudaGetSymbolAddress(&p, g_T1); float* T1 = (float*)p;
    cudaGetSymbolAddress(&p, g_M ); float* M  = (float*)p;
    cudaGetSymbolAddress(&p, g_T2); float* T2 = (float*)p;
    cudaGetSymbolAddress(&p, g_U ); float* U  = (float*)p;

    const long xB   = (long)LL * DIN;        // 2097152, batch stride of x
    const long GS   = (long)DIN * DIN;       // 262144
    const long WkH  = (long)DIN * DK;        // 32768
    const long T1H  = (long)DK * DIN;        // 32768
    const long T1B  = (long)HH * T1H;        // 262144
    const long MH   = (long)DK * DV;         // 4096
    const long MB   = (long)HH * MH;         // 32768

    // 1) Gram partials: Gp[z=s*BB+b] += x_b[k-range s]^T x_b[k-range s]
    //    A(m,k) = x[b][s*1024 + k][m]  (TA), K=1024 per split
    {
        dim3 grid(DIN / 64, DIN / 64, GRAM_SPLIT * BB);
        gemm64<true><<<grid, 256>>>(x, x, Gp,
            /*K=*/LL / GRAM_SPLIT, /*lda=*/DIN, /*ldb=*/DIN, /*ldc=*/DIN,
            /*zdiv=*/BB,
            /*abl(b)=*/xB, /*abh(s)=*/(long)(LL / GRAM_SPLIT) * DIN,
            /*bbl=*/xB,    /*bbh=*/(long)(LL / GRAM_SPLIT) * DIN,
            /*cbl(b)=*/GS, /*cbh(s)=*/(long)BB * GS);
    }

    // 2) Reduce partials -> G
    reduce_gram<<<(BB * DIN * DIN) / 256, 256>>>(Gp, G);

    // 3) T1[b][h] = W_k[h]^T @ G[b]   (64 x 512), z = b*8 + h
    {
        dim3 grid(DIN / 64, DK / 64, BB * HH);
        gemm64<true><<<grid, 256>>>(Wk, G, T1,
            /*K=*/DIN, /*lda=*/DK, /*ldb=*/DIN, /*ldc=*/DIN, /*zdiv=*/HH,
            /*abl(h)=*/WkH, /*abh(b)=*/0,
            /*bbl(h)=*/0,   /*bbh(b)=*/GS,
            /*cbl(h)=*/T1H, /*cbh(b)=*/T1B);
    }

    // 4) M[b][h] = T1[b][h] @ W_v[h]   (64 x 64)
    {
        dim3 grid(DV / 64, DK / 64, BB * HH);
        gemm64<false><<<grid, 256>>>(T1, Wv, M,
            /*K=*/DIN, /*lda=*/DIN, /*ldb=*/DV, /*ldc=*/DV, /*zdiv=*/HH,
            /*abl(h)=*/T1H, /*abh(b)=*/T1B,
            /*bbl(h)=*/(long)DIN * DV, /*bbh(b)=*/0,
            /*cbl(h)=*/MH, /*cbh(b)=*/MB);
    }

    // 5) T2cat[b][:, h*64 : h*64+64] = W_q[h] @ M[b][h]   (512 x 64)
    {
        dim3 grid(DV / 64, DIN / 64, BB * HH);
        gemm64<false><<<grid, 256>>>(Wq, M, T2,
            /*K=*/DK, /*lda=*/DK, /*ldb=*/DV, /*ldc=*/HH * DV, /*zdiv=*/HH,
            /*abl(h)=*/(long)DIN * DK, /*abh(b)=*/0,
            /*bbl(h)=*/MH, /*bbh(b)=*/MB,
            /*cbl(h)=*/(long)DV, /*cbh(b)=*/(long)DIN * HH * DV);
    }

    // 6) U[b] = T2cat[b] @ Wo_flat    (512 x 512), Wo flat is (H*DV, DOUT)
    {
        dim3 grid(DOUT / 64, DIN / 64, BB);
        gemm64<false><<<grid, 256>>>(T2, Wo, U,
            /*K=*/HH * DV, /*lda=*/HH * DV, /*ldb=*/DOUT, /*ldc=*/DOUT,
            /*zdiv=*/BB,
            /*abl(b)=*/(long)DIN * HH * DV, /*abh=*/0,
            /*bbl=*/0, /*bbh=*/0,
            /*cbl(b)=*/(long)DIN * DOUT, /*cbh=*/0);
    }

    // 7) out[b] = x[b] @ U[b]         (4096 x 512)
    {
        dim3 grid(DOUT / 64, LL / 64, BB);
        gemm64<false><<<grid, 256>>>(x, U, out,
            /*K=*/DIN, /*lda=*/DIN, /*ldb=*/DOUT, /*ldc=*/DOUT, /*zdiv=*/BB,
            /*abl(b)=*/xB, /*abh=*/0,
            /*bbl(b)=*/(long)DIN * DOUT, /*bbh=*/0,
            /*cbl(b)=*/(long)LL * DOUT, /*cbh=*/0);
    }
}

// round 2
// speedup vs baseline: 1.0892x; 1.0892x over previous
#include <cuda_runtime.h>
#include <cuda_bf16.h>

// Problem constants
#define BB   2
#define LL   4096
#define DIN  512
#define HH   8
#define DK   64
#define DV   64
#define DOUT 512

// ---------------------------------------------------------------------------
// Scratch (device globals)
// ---------------------------------------------------------------------------
__device__ float g_Gp [8 * BB * DIN * DIN];     // gram partials [ks][b]
__device__ float g_G  [BB * DIN * DIN];         // G[b] = x_b^T x_b
__device__ float g_T1p[4 * BB * DIN * DIN];     // T1 partials [ks][b]
__device__ float g_T1 [BB * DIN * DIN];         // T1cat[b] = Wkcat^T G[b]
__device__ float g_Mp [8 * BB * HH * DK * DV];  // M partials [ks][b][h]
__device__ float g_M  [BB * HH * DK * DV];      // M[b][h]
__device__ float g_T2 [BB * DIN * (HH * DV)];   // T2cat[b]
__device__ float g_Up [4 * BB * DIN * DOUT];    // U partials [ks][b]
__device__ float g_U  [BB * DIN * DOUT];        // U[b]

// ---------------------------------------------------------------------------
// f32x2 helpers
// ---------------------------------------------------------------------------
__device__ __forceinline__ unsigned long long pack2(float a) {
    unsigned long long r;
    asm("mov.b64 %0, {%1, %1};" : "=l"(r) : "f"(a));
    return r;
}
__device__ __forceinline__ void fma2(unsigned long long& acc,
                                     unsigned long long a,
                                     unsigned long long b) {
    asm("fma.rn.f32x2 %0, %1, %2, %0;" : "+l"(acc) : "l"(a), "l"(b));
}
__device__ __forceinline__ float lo32(unsigned long long v) {
    return __uint_as_float((unsigned)(v & 0xffffffffull));
}
__device__ __forceinline__ float hi32(unsigned long long v) {
    return __uint_as_float((unsigned)(v >> 32));
}

// ---------------------------------------------------------------------------
// gemm128: C = op(A)*B, 128x128 tile, 256 threads, 8x8 per thread,
// BK=16, double-buffered smem, single __syncthreads per k-tile.
//   TA=true : A stored (K x M) k-major; element (m,k) = A[k*lda + colmap(m)]
//             colmap(m) = (m>>6)*a_hs + (m&63)   (a_hs=64 -> identity)
//   TA=false: A stored (M x K) row-major; element (m,k) = A[m*lda + k]
//   B stored (K x N) row-major.
// z decomposition: z0=z%d0, z1=(z/d0)%d1, z2=z/(d0*d1); per-matrix offsets
// z0*s0 + z1*s1 + z2*s2.
// ---------------------------------------------------------------------------
template <bool TA>
__global__ void __launch_bounds__(256)
gemm128(const float* __restrict__ A, const float* __restrict__ B,
        float* __restrict__ C,
        int K, int lda, int ldb, int ldc, long a_hs,
        int d0, int d1,
        long a0, long a1, long a2,
        long b0, long b1, long b2,
        long c0, long c1, long c2)
{
    __shared__ __align__(16) float As[2][16 * 128];
    __shared__ __align__(16) float Bs[2][16 * 128];

    const int t  = threadIdx.x;
    const int tx = t & 15;   // n group (8 cols)
    const int ty = t >> 4;   // m group (8 rows)

    {
        const int z  = blockIdx.z;
        const int z0 = z % d0;
        const int zr = z / d0;
        const int z1 = zr % d1;
        const int z2 = zr / d1;
        A += (long)z0 * a0 + (long)z1 * a1 + (long)z2 * a2;
        B += (long)z0 * b0 + (long)z1 * b1 + (long)z2 * b2;
        C += (long)z0 * c0 + (long)z1 * c1 + (long)z2 * c2;
    }

    const long m0 = (long)blockIdx.y * 128;
    const long n0 = (long)blockIdx.x * 128;

    const float* Ag;
    if (TA) {
        const long mm = m0 + (t & 15) * 8;
        Ag = A + ((mm >> 6) * a_hs + (mm & 63)) + (long)(t >> 4) * lda;
    } else {
        Ag = A + (m0 + (t >> 1)) * lda + (t & 1) * 8;
    }
    const float* Bg = B + (long)(t >> 4) * ldb + n0 + (t & 15) * 8;

    unsigned long long acc[8][4];
#pragma unroll
    for (int i = 0; i < 8; i++)
#pragma unroll
        for (int j = 0; j < 4; j++) acc[i][j] = 0ull;

    const int ktiles = K / 16;

    // prologue: load tile 0
    float4 ra0 = *(const float4*)(Ag);
    float4 ra1 = *(const float4*)(Ag + 4);
    float4 rb0 = *(const float4*)(Bg);
    float4 rb1 = *(const float4*)(Bg + 4);

    // store tile 0 into buffer 0
    if (TA) {
        *(float4*)&As[0][(t >> 4) * 128 + (t & 15) * 8]     = ra0;
        *(float4*)&As[0][(t >> 4) * 128 + (t & 15) * 8 + 4] = ra1;
    } else {
        const int m = t >> 1, ks = (t & 1) * 8;
        As[0][(ks + 0) * 128 + m] = ra0.x;
        As[0][(ks + 1) * 128 + m] = ra0.y;
        As[0][(ks + 2) * 128 + m] = ra0.z;
        As[0][(ks + 3) * 128 + m] = ra0.w;
        As[0][(ks + 4) * 128 + m] = ra1.x;
        As[0][(ks + 5) * 128 + m] = ra1.y;
        As[0][(ks + 6) * 128 + m] = ra1.z;
        As[0][(ks + 7) * 128 + m] = ra1.w;
    }
    *(float4*)&Bs[0][(t >> 4) * 128 + (t & 15) * 8]     = rb0;
    *(float4*)&Bs[0][(t >> 4) * 128 + (t & 15) * 8 + 4] = rb1;
    __syncthreads();

    for (int kt = 0; kt < ktiles; kt++) {
        const int cur = kt & 1;
        const bool more = (kt + 1 < ktiles);
        if (more) {
            Ag += TA ? 16 * lda : 16;
            Bg += 16 * ldb;
            ra0 = *(const float4*)(Ag);
            ra1 = *(const float4*)(Ag + 4);
            rb0 = *(const float4*)(Bg);
            rb1 = *(const float4*)(Bg + 4);
        }

        // compute current buffer
#pragma unroll
        for (int kk = 0; kk < 16; kk++) {
            const float4 av0 = *(const float4*)&As[cur][kk * 128 + ty * 8];
            const float4 av1 = *(const float4*)&As[cur][kk * 128 + ty * 8 + 4];
            const ulonglong2 bv0 = *(const ulonglong2*)&Bs[cur][kk * 128 + tx * 8];
            const ulonglong2 bv1 = *(const ulonglong2*)&Bs[cur][kk * 128 + tx * 8 + 4];
            const unsigned long long bb0 = bv0.x, bb1 = bv0.y, bb2 = bv1.x, bb3 = bv1.y;
            unsigned long long p;
            p = pack2(av0.x); fma2(acc[0][0], p, bb0); fma2(acc[0][1], p, bb1); fma2(acc[0][2], p, bb2); fma2(acc[0][3], p, bb3);
            p = pack2(av0.y); fma2(acc[1][0], p, bb0); fma2(acc[1][1], p, bb1); fma2(acc[1][2], p, bb2); fma2(acc[1][3], p, bb3);
            p = pack2(av0.z); fma2(acc[2][0], p, bb0); fma2(acc[2][1], p, bb1); fma2(acc[2][2], p, bb2); fma2(acc[2][3], p, bb3);
            p = pack2(av0.w); fma2(acc[3][0], p, bb0); fma2(acc[3][1], p, bb1); fma2(acc[3][2], p, bb2); fma2(acc[3][3], p, bb3);
            p = pack2(av1.x); fma2(acc[4][0], p, bb0); fma2(acc[4][1], p, bb1); fma2(acc[4][2], p, bb2); fma2(acc[4][3], p, bb3);
            p = pack2(av1.y); fma2(acc[5][0], p, bb0); fma2(acc[5][1], p, bb1); fma2(acc[5][2], p, bb2); fma2(acc[5][3], p, bb3);
            p = pack2(av1.z); fma2(acc[6][0], p, bb0); fma2(acc[6][1], p, bb1); fma2(acc[6][2], p, bb2); fma2(acc[6][3], p, bb3);
            p = pack2(av1.w); fma2(acc[7][0], p, bb0); fma2(acc[7][1], p, bb1); fma2(acc[7][2], p, bb2); fma2(acc[7][3], p, bb3);
        }

        if (more) {
            const int nxt = cur ^ 1;
            if (TA) {
                *(float4*)&As[nxt][(t >> 4) * 128 + (t & 15) * 8]     = ra0;
                *(float4*)&As[nxt][(t >> 4) * 128 + (t & 15) * 8 + 4] = ra1;
            } else {
                const int m = t >> 1, ks = (t & 1) * 8;
                As[nxt][(ks + 0) * 128 + m] = ra0.x;
                As[nxt][(ks + 1) * 128 + m] = ra0.y;
                As[nxt][(ks + 2) * 128 + m] = ra0.z;
                As[nxt][(ks + 3) * 128 + m] = ra0.w;
                As[nxt][(ks + 4) * 128 + m] = ra1.x;
                As[nxt][(ks + 5) * 128 + m] = ra1.y;
                As[nxt][(ks + 6) * 128 + m] = ra1.z;
                As[nxt][(ks + 7) * 128 + m] = ra1.w;
            }
            *(float4*)&Bs[nxt][(t >> 4) * 128 + (t & 15) * 8]     = rb0;
            *(float4*)&Bs[nxt][(t >> 4) * 128 + (t & 15) * 8 + 4] = rb1;
        }
        __syncthreads();
    }

    // epilogue
#pragma unroll
    for (int i = 0; i < 8; i++) {
        float4 o0, o1;
        o0.x = lo32(acc[i][0]); o0.y = hi32(acc[i][0]);
        o0.z = lo32(acc[i][1]); o0.w = hi32(acc[i][1]);
        o1.x = lo32(acc[i][2]); o1.y = hi32(acc[i][2]);
        o1.z = lo32(acc[i][3]); o1.w = hi32(acc[i][3]);
        float* cp = C + (m0 + ty * 8 + i) * ldc + n0 + tx * 8;
        *(float4*)(cp)     = o0;
        *(float4*)(cp + 4) = o1;
    }
}

// ---------------------------------------------------------------------------
// gemmSmall: C(64x64) = A(64x... rows from blockIdx.y) * B, K=64 fixed.
// A is (M x K) row-major; B is (K=64 x 64) row-major. 256 threads, 4x4/thread.
// Whole K staged once (no k-loop over tiles).
// ---------------------------------------------------------------------------
__global__ void __launch_bounds__(256)
gemmSmall(const float* __restrict__ A, const float* __restrict__ B,
          float* __restrict__ C,
          int lda, int ldb, int ldc,
          int d0, int d1,
          long a0, long a1, long a2,
          long b0, long b1, long b2,
          long c0, long c1, long c2)
{
    __shared__ __align__(16) float As[64 * 68];  // m-major, padded row (68)
    __shared__ __align__(16) float Bs[64 * 64];  // k-major

    const int t  = threadIdx.x;
    const int tx = t & 15;
    const int ty = t >> 4;

    {
        const int z  = blockIdx.z;
        const int z0 = z % d0;
        const int zr = z / d0;
        const int z1 = zr % d1;
        const int z2 = zr / d1;
        A += (long)z0 * a0 + (long)z1 * a1 + (long)z2 * a2;
        B += (long)z0 * b0 + (long)z1 * b1 + (long)z2 * b2;
        C += (long)z0 * c0 + (long)z1 * c1 + (long)z2 * c2;
    }
    const long m0 = (long)blockIdx.y * 64;

    // stage A: 64 rows x 64 k
    {
        const int m = t >> 2, kseg = (t & 3) * 16;
        const float* Ag = A + (m0 + m) * lda + kseg;
#pragma unroll
        for (int s = 0; s < 4; s++)
            *(float4*)&As[m * 68 + kseg + s * 4] = *(const float4*)(Ag + s * 4);
    }
    // stage B: 64 rows (k) x 64 n
    {
        const int r = t >> 2, cs = (t & 3) * 16;
        const float* Bg = B + (long)r * ldb + cs;
#pragma unroll
        for (int s = 0; s < 4; s++)
            *(float4*)&Bs[r * 64 + cs + s * 4] = *(const float4*)(Bg + s * 4);
    }
    __syncthreads();

    unsigned long long acc[4][2];
#pragma unroll
    for (int i = 0; i < 4; i++) { acc[i][0] = 0ull; acc[i][1] = 0ull; }

#pragma unroll 8
    for (int kk = 0; kk < 64; kk++) {
        const ulonglong2 bv = *(const ulonglong2*)&Bs[kk * 64 + tx * 4];
        const unsigned long long bb0 = bv.x, bb1 = bv.y;
        unsigned long long p;
        p = pack2(As[(ty * 4 + 0) * 68 + kk]); fma2(acc[0][0], p, bb0); fma2(acc[0][1], p, bb1);
        p = pack2(As[(ty * 4 + 1) * 68 + kk]); fma2(acc[1][0], p, bb0); fma2(acc[1][1], p, bb1);
        p = pack2(As[(ty * 4 + 2) * 68 + kk]); fma2(acc[2][0], p, bb0); fma2(acc[2][1], p, bb1);
        p = pack2(As[(ty * 4 + 3) * 68 + kk]); fma2(acc[3][0], p, bb0); fma2(acc[3][1], p, bb1);
    }

#pragma unroll
    for (int i = 0; i < 4; i++) {
        float4 o;
        o.x = lo32(acc[i][0]); o.y = hi32(acc[i][0]);
        o.z = lo32(acc[i][1]); o.w = hi32(acc[i][1]);
        *(float4*)&C[(m0 + ty * 4 + i) * ldc + tx * 4] = o;
    }
}

// ---------------------------------------------------------------------------
// reduceP: dst[i] = sum_p src[p*S4 + i]  (float4 elements)
// ---------------------------------------------------------------------------
__global__ void __launch_bounds__(256)
reduceP(const float4* __restrict__ src, float4* __restrict__ dst, int S4, int P)
{
    const int i = blockIdx.x * 256 + threadIdx.x;
    if (i >= S4) return;
    float4 s = src[i];
    for (int p = 1; p < P; p++) {
        const float4 v = src[(long)p * S4 + i];
        s.x += v.x; s.y += v.y; s.z += v.z; s.w += v.w;
    }
    dst[i] = s;
}

// ---------------------------------------------------------------------------
// kernel_launch
// ---------------------------------------------------------------------------
extern "C" void kernel_launch(void* const* d_in, const int* in_sizes, int n_in,
                              void* d_out, int out_size)
{
    (void)in_sizes; (void)n_in; (void)out_size;
    const float* x  = (const float*)d_in[0];  // (B, L, DIN)
    const float* Wq = (const float*)d_in[1];  // (H, DIN, DK)
    const float* Wk = (const float*)d_in[2];  // (H, DIN, DK)
    const float* Wv = (const float*)d_in[3];  // (H, DIN, DV)
    const float* Wo = (const float*)d_in[4];  // (H, DV, DOUT)
    float* out = (float*)d_out;               // (B, L, DOUT)

    void* p;
    cudaGetSymbolAddress(&p, g_Gp ); float* Gp  = (float*)p;
    cudaGetSymbolAddress(&p, g_G  ); float* G   = (float*)p;
    cudaGetSymbolAddress(&p, g_T1p); float* T1p = (float*)p;
    cudaGetSymbolAddress(&p, g_T1 ); float* T1  = (float*)p;
    cudaGetSymbolAddress(&p, g_Mp ); float* Mp  = (float*)p;
    cudaGetSymbolAddress(&p, g_M  ); float* M   = (float*)p;
    cudaGetSymbolAddress(&p, g_T2 ); float* T2  = (float*)p;
    cudaGetSymbolAddress(&p, g_Up ); float* Up  = (float*)p;
    cudaGetSymbolAddress(&p, g_U  ); float* U   = (float*)p;

    const long xB = (long)LL * DIN;      // 2097152
    const long GS = (long)DIN * DIN;     // 262144

    // 1) Gram partials: Gp[ks][b] = x_b[ks-chunk]^T x_b[ks-chunk], K=512 each
    gemm128<true><<<dim3(4, 4, 16), 256>>>(x, x, Gp,
        512, DIN, DIN, DIN, 64,
        /*d0=*/BB, /*d1=*/8,
        /*A:*/ xB, 262144, 0,
        /*B:*/ xB, 262144, 0,
        /*C:*/ GS, BB * GS, 0);

    // 2) G = sum_ks Gp
    reduceP<<<512, 256>>>((const float4*)Gp, (float4*)G, (BB * GS) / 4, 8);

    // 3) T1 partials: T1p[ks][b] = Wkcat^T @ G[b] (K=128 per split)
    gemm128<true><<<dim3(4, 4, 8), 256>>>(Wk, G, T1p,
        128, DK, DIN, DIN, (long)DIN * DK,
        /*d0=*/BB, /*d1=*/4,
        /*A:*/ 0, 128L * DK, 0,
        /*B:*/ GS, 128L * DIN, 0,
        /*C:*/ GS, BB * GS, 0);

    // 4) T1 = sum_ks T1p
    reduceP<<<512, 256>>>((const float4*)T1p, (float4*)T1, (BB * GS) / 4, 4);

    // 5) M partials: Mp[ks][b][h] = T1[b][h-rows, ks-chunk] @ Wv[h][ks-chunk]
    gemmSmall<<<dim3(1, 1, 128), 256>>>(T1, Wv, Mp,
        DIN, DV, DV,
        /*d0=*/HH, /*d1=*/BB,
        /*A:*/ 64L * DIN, GS, 64,
        /*B:*/ (long)DIN * DV, 0, 64L * DV,
        /*C:*/ (long)DK * DV, (long)HH * DK * DV, (long)BB * HH * DK * DV);

    // 6) M = sum_ks Mp
    reduceP<<<64, 256>>>((const float4*)Mp, (float4*)M, (BB * HH * DK * DV) / 4, 8);

    // 7) T2cat[b][:, h*64:+64] = Wq[h] @ M[b][h]
    gemmSmall<<<dim3(1, 8, 16), 256>>>(Wq, M, T2,
        DK, DV, HH * DV,
        /*d0=*/HH, /*d1=*/BB,
        /*A:*/ (long)DIN * DK, 0, 0,
        /*B:*/ (long)DK * DV, (long)HH * DK * DV, 0,
        /*C:*/ DV, (long)DIN * HH * DV, 0);

    // 8) U partials: Up[ks][b] = T2cat[b][:, ks-chunk] @ Wo_flat[ks-chunk, :]
    gemm128<false><<<dim3(4, 4, 8), 256>>>(T2, Wo, Up,
        128, HH * DV, DOUT, DOUT, 0,
        /*d0=*/BB, /*d1=*/4,
        /*A:*/ (long)DIN * HH * DV, 128, 0,
        /*B:*/ 0, 128L * DOUT, 0,
        /*C:*/ GS, BB * GS, 0);

    // 9) U = sum_ks Up
    reduceP<<<512, 256>>>((const float4*)Up, (float4*)U, (BB * GS) / 4, 4);

    // 10) out[b] = x[b] @ U[b]
    gemm128<false><<<dim3(4, 32, BB), 256>>>(x, U, out,
        DIN, DIN, DOUT, DOUT, 0,
        /*d0=*/BB, /*d1=*/1,
        /*A:*/ xB, 0, 0,
        /*B:*/ GS, 0, 0,
        /*C:*/ (long)LL * DOUT, 0, 0);
}

// round 5
// speedup vs baseline: 1.7465x; 1.6035x over previous
#include <cuda_runtime.h>
#include <cuda_bf16.h>
#include <cstdint>

// Problem constants
#define BB   2
#define LL   4096
#define DIN  512
#define HH   8
#define DK   64
#define DV   64
#define DOUT 512

// ---------------------------------------------------------------------------
// Scratch (device globals)
// ---------------------------------------------------------------------------
__device__ float g_Gp [8 * BB * DIN * DIN];     // gram partials [ks][b]
__device__ float g_G  [BB * DIN * DIN];         // G[b] = x_b^T x_b
__device__ float g_T1p[4 * BB * DIN * DIN];     // T1 partials [ks][b]
__device__ float g_T1 [BB * DIN * DIN];         // T1cat[b] = Wkcat^T G[b]
__device__ float g_Mp [8 * BB * HH * DK * DV];  // M partials [ks][b][h]
__device__ float g_M  [BB * HH * DK * DV];      // M[b][h]
__device__ float g_T2 [BB * DIN * (HH * DV)];   // T2cat[b]
__device__ float g_Up [4 * BB * DIN * DOUT];    // U partials [ks][b]
__device__ float g_U  [BB * DIN * DOUT];        // U[b]

// bf16 split buffers
__device__ __nv_bfloat16 g_xrh[BB * LL * DIN];  // x row-major hi
__device__ __nv_bfloat16 g_xrl[BB * LL * DIN];  // x row-major lo
__device__ __nv_bfloat16 g_xth[BB * DIN * LL];  // x^T hi  (channel-major)
__device__ __nv_bfloat16 g_xtl[BB * DIN * LL];  // x^T lo
__device__ __nv_bfloat16 g_uth[BB * DOUT * DIN];// U^T hi  (o-major)
__device__ __nv_bfloat16 g_utl[BB * DOUT * DIN];// U^T lo

// ---------------------------------------------------------------------------
// f32x2 helpers (SIMT mid-chain)
// ---------------------------------------------------------------------------
__device__ __forceinline__ unsigned long long pack2(float a) {
    unsigned long long r;
    asm("mov.b64 %0, {%1, %1};" : "=l"(r) : "f"(a));
    return r;
}
__device__ __forceinline__ void fma2(unsigned long long& acc,
                                     unsigned long long a,
                                     unsigned long long b) {
    asm("fma.rn.f32x2 %0, %1, %2, %0;" : "+l"(acc) : "l"(a), "l"(b));
}
__device__ __forceinline__ float lo32(unsigned long long v) {
    return __uint_as_float((unsigned)(v & 0xffffffffull));
}
__device__ __forceinline__ float hi32(unsigned long long v) {
    return __uint_as_float((unsigned)(v >> 32));
}

// ---------------------------------------------------------------------------
// helpers for mma.sync path (portable ISA — legal at target sm_103)
// ---------------------------------------------------------------------------
__device__ __forceinline__ uint32_t smem_u32(const void* p) {
    uint32_t a;
    asm("{ .reg .u64 t; cvta.to.shared.u64 t, %1; cvt.u32.u64 %0, t; }"
        : "=r"(a) : "l"(p));
    return a;
}
__device__ __forceinline__ void cp_async16(uint32_t dst, const void* src) {
    asm volatile("cp.async.cg.shared.global [%0], [%1], 16;" :: "r"(dst), "l"(src));
}
__device__ __forceinline__ uint32_t lds32(uint32_t addr) {
    uint32_t v;
    asm volatile("ld.shared.b32 %0, [%1];" : "=r"(v) : "r"(addr));
    return v;
}
__device__ __forceinline__ void mma16816(float* c, const uint32_t* a, const uint32_t* b) {
    asm volatile(
        "mma.sync.aligned.m16n8k16.row.col.f32.bf16.bf16.f32 "
        "{%0,%1,%2,%3}, {%4,%5,%6,%7}, {%8,%9}, {%0,%1,%2,%3};"
        : "+f"(c[0]), "+f"(c[1]), "+f"(c[2]), "+f"(c[3])
        : "r"(a[0]), "r"(a[1]), "r"(a[2]), "r"(a[3]), "r"(b[0]), "r"(b[1]));
}

// ---------------------------------------------------------------------------
// mmaT: C[128x128 tile] fp32 = split-bf16 A(M rows,K) @ B(N rows,K)^T
//   A rows K-major (ldA), B rows K-major (ldB). K consumed in chunks of 32.
//   z: z0 = z % d0 (batch), z1 = z / d0 (k-split). kOff = z1*nChunk*32.
// 256 threads = 8 warps, warp tile 64x32 (wm = wid&1, wn = wid>>1).
// 3-term split: AhBh + AhBl + AlBh, fragments loaded once per k-step.
// Smem rows padded to 80B -> conflict-free LDS.32 fragment loads.
// ---------------------------------------------------------------------------
#define ROWB   80
#define MATB   (128 * ROWB)      // 10240 per split matrix
#define BUFB   (4 * MATB)        // 40960 per k-chunk buffer
#define MMA_SMEM (2 * BUFB)      // 81920

__global__ void __launch_bounds__(256)
mmaT(const __nv_bfloat16* __restrict__ Ahi, const __nv_bfloat16* __restrict__ Alo,
     const __nv_bfloat16* __restrict__ Bhi, const __nv_bfloat16* __restrict__ Blo,
     float* __restrict__ C,
     int ldA, int ldB, int ldC, int nChunk, int d0,
     long aB, long bB, long cB, long cS)
{
    extern __shared__ char sm[];
    const uint32_t su = smem_u32(sm);

    const int t    = threadIdx.x;
    const int wid  = t >> 5;
    const int lane = t & 31;
    const int g    = lane >> 2;   // 0..7
    const int tq   = lane & 3;    // 0..3
    const int wm   = wid & 1;     // m warp (64 rows)
    const int wn   = wid >> 1;    // n warp (32 cols)

    const int z  = blockIdx.z;
    const int z0 = z % d0;
    const int z1 = z / d0;
    const long kOff = (long)z1 * nChunk * 32;

    const long m0 = (long)blockIdx.y * 128;
    const long n0 = (long)blockIdx.x * 128;

    const __nv_bfloat16* bAh = Ahi + (long)z0 * aB + kOff + m0 * ldA;
    const __nv_bfloat16* bAl = Alo + (long)z0 * aB + kOff + m0 * ldA;
    const __nv_bfloat16* bBh = Bhi + (long)z0 * bB + kOff + n0 * ldB;
    const __nv_bfloat16* bBl = Blo + (long)z0 * bB + kOff + n0 * ldB;
    C += (long)z0 * cB + (long)z1 * cS;

    // loader: thread handles chunk-ids t and t+256 for each of the 4 matrices
    const int r0 = t >> 2,        s0 = (t & 3) * 16;        // cid = t
    const int r1 = (t + 256) >> 2, s1 = ((t + 256) & 3) * 16; // cid = t+256

    float acc[4][4][4];
#pragma unroll
    for (int i = 0; i < 4; i++)
#pragma unroll
        for (int j = 0; j < 4; j++)
#pragma unroll
            for (int k = 0; k < 4; k++) acc[i][j][k] = 0.f;

#define LOAD_CHUNK(cidx, buf)                                                   \
    do {                                                                        \
        const uint32_t sb_ = su + (buf) * BUFB;                                 \
        const long ko_ = (long)(cidx) * 32;                                     \
        cp_async16(sb_ + 0 * MATB + r0 * ROWB + s0, bAh + (long)r0 * ldA + ko_ + s0 / 2); \
        cp_async16(sb_ + 0 * MATB + r1 * ROWB + s1, bAh + (long)r1 * ldA + ko_ + s1 / 2); \
        cp_async16(sb_ + 1 * MATB + r0 * ROWB + s0, bAl + (long)r0 * ldA + ko_ + s0 / 2); \
        cp_async16(sb_ + 1 * MATB + r1 * ROWB + s1, bAl + (long)r1 * ldA + ko_ + s1 / 2); \
        cp_async16(sb_ + 2 * MATB + r0 * ROWB + s0, bBh + (long)r0 * ldB + ko_ + s0 / 2); \
        cp_async16(sb_ + 2 * MATB + r1 * ROWB + s1, bBh + (long)r1 * ldB + ko_ + s1 / 2); \
        cp_async16(sb_ + 3 * MATB + r0 * ROWB + s0, bBl + (long)r0 * ldB + ko_ + s0 / 2); \
        cp_async16(sb_ + 3 * MATB + r1 * ROWB + s1, bBl + (long)r1 * ldB + ko_ + s1 / 2); \
        asm volatile("cp.async.commit_group;" ::: "memory");                    \
    } while (0)

    LOAD_CHUNK(0, 0);

    for (int c = 0; c < nChunk; c++) {
        const int buf = c & 1;
        if (c + 1 < nChunk) {
            LOAD_CHUNK(c + 1, buf ^ 1);
            asm volatile("cp.async.wait_group 1;" ::: "memory");
        } else {
            asm volatile("cp.async.wait_group 0;" ::: "memory");
        }
        __syncthreads();

        const uint32_t sb = su + buf * BUFB;
#pragma unroll
        for (int s = 0; s < 2; s++) {
            const uint32_t kb = s * 32 + tq * 4;   // byte offset of k-fragment
            uint32_t ah[4][4], al[4][4], bh[4][2], bl[4][2];
#pragma unroll
            for (int mt = 0; mt < 4; mt++) {
                const uint32_t ra = (uint32_t)(wm * 64 + mt * 16 + g) * ROWB + kb;
                ah[mt][0] = lds32(sb + ra);
                ah[mt][1] = lds32(sb + ra + 8 * ROWB);
                ah[mt][2] = lds32(sb + ra + 16);
                ah[mt][3] = lds32(sb + ra + 8 * ROWB + 16);
                al[mt][0] = lds32(sb + MATB + ra);
                al[mt][1] = lds32(sb + MATB + ra + 8 * ROWB);
                al[mt][2] = lds32(sb + MATB + ra + 16);
                al[mt][3] = lds32(sb + MATB + ra + 8 * ROWB + 16);
            }
#pragma unroll
            for (int nt = 0; nt < 4; nt++) {
                const uint32_t rb = (uint32_t)(wn * 32 + nt * 8 + g) * ROWB + kb;
                bh[nt][0] = lds32(sb + 2 * MATB + rb);
                bh[nt][1] = lds32(sb + 2 * MATB + rb + 16);
                bl[nt][0] = lds32(sb + 3 * MATB + rb);
                bl[nt][1] = lds32(sb + 3 * MATB + rb + 16);
            }
#pragma unroll
            for (int mt = 0; mt < 4; mt++)
#pragma unroll
                for (int nt = 0; nt < 4; nt++) {
                    mma16816(acc[mt][nt], ah[mt], bh[nt]);
                    mma16816(acc[mt][nt], ah[mt], bl[nt]);
                    mma16816(acc[mt][nt], al[mt], bh[nt]);
                }
        }
        __syncthreads();
    }

    // epilogue: write fp32 results
#pragma unroll
    for (int mt = 0; mt < 4; mt++) {
#pragma unroll
        for (int nt = 0; nt < 4; nt++) {
            const long row = m0 + wm * 64 + mt * 16 + g;
            const long col = n0 + wn * 32 + nt * 8 + 2 * tq;
            float2 v0 = make_float2(acc[mt][nt][0], acc[mt][nt][1]);
            float2 v1 = make_float2(acc[mt][nt][2], acc[mt][nt][3]);
            *(float2*)&C[row * ldC + col]       = v0;
            *(float2*)&C[(row + 8) * ldC + col] = v1;
        }
    }
}

// ---------------------------------------------------------------------------
// splitRow: elementwise fp32 -> (hi, lo) bf16, row-major preserved
// ---------------------------------------------------------------------------
__device__ __forceinline__ unsigned short bfbits(__nv_bfloat16 h) {
    return ((__nv_bfloat16_raw)h).x;
}
__global__ void __launch_bounds__(256)
splitRow(const float4* __restrict__ in, uint2* __restrict__ oh, uint2* __restrict__ ol, int n4)
{
    const int i = blockIdx.x * 256 + threadIdx.x;
    if (i >= n4) return;
    const float4 v = in[i];
    const __nv_bfloat16 hx = __float2bfloat16(v.x);
    const __nv_bfloat16 hy = __float2bfloat16(v.y);
    const __nv_bfloat16 hz = __float2bfloat16(v.z);
    const __nv_bfloat16 hw = __float2bfloat16(v.w);
    const __nv_bfloat16 lx = __float2bfloat16(v.x - __bfloat162float(hx));
    const __nv_bfloat16 ly = __float2bfloat16(v.y - __bfloat162float(hy));
    const __nv_bfloat16 lz = __float2bfloat16(v.z - __bfloat162float(hz));
    const __nv_bfloat16 lw = __float2bfloat16(v.w - __bfloat162float(hw));
    uint2 H, L;
    H.x = (uint32_t)bfbits(hx) | ((uint32_t)bfbits(hy) << 16);
    H.y = (uint32_t)bfbits(hz) | ((uint32_t)bfbits(hw) << 16);
    L.x = (uint32_t)bfbits(lx) | ((uint32_t)bfbits(ly) << 16);
    L.y = (uint32_t)bfbits(lz) | ((uint32_t)bfbits(lw) << 16);
    oh[i] = H;
    ol[i] = L;
}

// ---------------------------------------------------------------------------
// splitT: in (R x C) fp32 -> out (C x R) bf16 hi/lo (transpose + split)
// grid (C/32, R/32, BB), block (32, 8)
// ---------------------------------------------------------------------------
__global__ void __launch_bounds__(256)
splitT(const float* __restrict__ in, __nv_bfloat16* __restrict__ oh,
       __nv_bfloat16* __restrict__ ol, int R, int C)
{
    __shared__ float tl[32][33];
    const int b = blockIdx.z;
    in += (long)b * R * C;
    oh += (long)b * R * C;
    ol += (long)b * R * C;
    const int c0 = blockIdx.x * 32, r0 = blockIdx.y * 32;
    const int tx = threadIdx.x, ty = threadIdx.y;
#pragma unroll
    for (int i = 0; i < 4; i++)
        tl[ty + 8 * i][tx] = in[(long)(r0 + ty + 8 * i) * C + c0 + tx];
    __syncthreads();
#pragma unroll
    for (int i = 0; i < 4; i++) {
        const float v = tl[tx][ty + 8 * i];
        const __nv_bfloat16 h = __float2bfloat16(v);
        const __nv_bfloat16 l = __float2bfloat16(v - __bfloat162float(h));
        const long o = (long)(c0 + ty + 8 * i) * R + r0 + tx;
        oh[o] = h;
        ol[o] = l;
    }
}

// ---------------------------------------------------------------------------
// SIMT mid-chain kernels (unchanged)
// ---------------------------------------------------------------------------
template <bool TA>
__global__ void __launch_bounds__(256)
gemm128(const float* __restrict__ A, const float* __restrict__ B,
        float* __restrict__ C,
        int K, int lda, int ldb, int ldc, long a_hs,
        int d0, int d1,
        long a0, long a1, long a2,
        long b0, long b1, long b2,
        long c0, long c1, long c2)
{
    __shared__ __align__(16) float As[2][16 * 128];
    __shared__ __align__(16) float Bs[2][16 * 128];

    const int t  = threadIdx.x;
    const int tx = t & 15;
    const int ty = t >> 4;

    {
        const int z  = blockIdx.z;
        const int z0 = z % d0;
        const int zr = z / d0;
        const int z1 = zr % d1;
        const int z2 = zr / d1;
        A += (long)z0 * a0 + (long)z1 * a1 + (long)z2 * a2;
        B += (long)z0 * b0 + (long)z1 * b1 + (long)z2 * b2;
        C += (long)z0 * c0 + (long)z1 * c1 + (long)z2 * c2;
    }

    const long m0 = (long)blockIdx.y * 128;
    const long n0 = (long)blockIdx.x * 128;

    const float* Ag;
    if (TA) {
        const long mm = m0 + (t & 15) * 8;
        Ag = A + ((mm >> 6) * a_hs + (mm & 63)) + (long)(t >> 4) * lda;
    } else {
        Ag = A + (m0 + (t >> 1)) * lda + (t & 1) * 8;
    }
    const float* Bg = B + (long)(t >> 4) * ldb + n0 + (t & 15) * 8;

    unsigned long long acc[8][4];
#pragma unroll
    for (int i = 0; i < 8; i++)
#pragma unroll
        for (int j = 0; j < 4; j++) acc[i][j] = 0ull;

    const int ktiles = K / 16;

    float4 ra0 = *(const float4*)(Ag);
    float4 ra1 = *(const float4*)(Ag + 4);
    float4 rb0 = *(const float4*)(Bg);
    float4 rb1 = *(const float4*)(Bg + 4);

    if (TA) {
        *(float4*)&As[0][(t >> 4) * 128 + (t & 15) * 8]     = ra0;
        *(float4*)&As[0][(t >> 4) * 128 + (t & 15) * 8 + 4] = ra1;
    } else {
        const int m = t >> 1, ks = (t & 1) * 8;
        As[0][(ks + 0) * 128 + m] = ra0.x;
        As[0][(ks + 1) * 128 + m] = ra0.y;
        As[0][(ks + 2) * 128 + m] = ra0.z;
        As[0][(ks + 3) * 128 + m] = ra0.w;
        As[0][(ks + 4) * 128 + m] = ra1.x;
        As[0][(ks + 5) * 128 + m] = ra1.y;
        As[0][(ks + 6) * 128 + m] = ra1.z;
        As[0][(ks + 7) * 128 + m] = ra1.w;
    }
    *(float4*)&Bs[0][(t >> 4) * 128 + (t & 15) * 8]     = rb0;
    *(float4*)&Bs[0][(t >> 4) * 128 + (t & 15) * 8 + 4] = rb1;
    __syncthreads();

    for (int kt = 0; kt < ktiles; kt++) {
        const int cur = kt & 1;
        const bool more = (kt + 1 < ktiles);
        if (more) {
            Ag += TA ? 16 * lda : 16;
            Bg += 16 * ldb;
            ra0 = *(const float4*)(Ag);
            ra1 = *(const float4*)(Ag + 4);
            rb0 = *(const float4*)(Bg);
            rb1 = *(const float4*)(Bg + 4);
        }

#pragma unroll
        for (int kk = 0; kk < 16; kk++) {
            const float4 av0 = *(const float4*)&As[cur][kk * 128 + ty * 8];
            const float4 av1 = *(const float4*)&As[cur][kk * 128 + ty * 8 + 4];
            const ulonglong2 bv0 = *(const ulonglong2*)&Bs[cur][kk * 128 + tx * 8];
            const ulonglong2 bv1 = *(const ulonglong2*)&Bs[cur][kk * 128 + tx * 8 + 4];
            const unsigned long long bb0 = bv0.x, bb1 = bv0.y, bb2 = bv1.x, bb3 = bv1.y;
            unsigned long long p;
            p = pack2(av0.x); fma2(acc[0][0], p, bb0); fma2(acc[0][1], p, bb1); fma2(acc[0][2], p, bb2); fma2(acc[0][3], p, bb3);
            p = pack2(av0.y); fma2(acc[1][0], p, bb0); fma2(acc[1][1], p, bb1); fma2(acc[1][2], p, bb2); fma2(acc[1][3], p, bb3);
            p = pack2(av0.z); fma2(acc[2][0], p, bb0); fma2(acc[2][1], p, bb1); fma2(acc[2][2], p, bb2); fma2(acc[2][3], p, bb3);
            p = pack2(av0.w); fma2(acc[3][0], p, bb0); fma2(acc[3][1], p, bb1); fma2(acc[3][2], p, bb2); fma2(acc[3][3], p, bb3);
            p = pack2(av1.x); fma2(acc[4][0], p, bb0); fma2(acc[4][1], p, bb1); fma2(acc[4][2], p, bb2); fma2(acc[4][3], p, bb3);
            p = pack2(av1.y); fma2(acc[5][0], p, bb0); fma2(acc[5][1], p, bb1); fma2(acc[5][2], p, bb2); fma2(acc[5][3], p, bb3);
            p = pack2(av1.z); fma2(acc[6][0], p, bb0); fma2(acc[6][1], p, bb1); fma2(acc[6][2], p, bb2); fma2(acc[6][3], p, bb3);
            p = pack2(av1.w); fma2(acc[7][0], p, bb0); fma2(acc[7][1], p, bb1); fma2(acc[7][2], p, bb2); fma2(acc[7][3], p, bb3);
        }

        if (more) {
            const int nxt = cur ^ 1;
            if (TA) {
                *(float4*)&As[nxt][(t >> 4) * 128 + (t & 15) * 8]     = ra0;
                *(float4*)&As[nxt][(t >> 4) * 128 + (t & 15) * 8 + 4] = ra1;
            } else {
                const int m = t >> 1, ks = (t & 1) * 8;
                As[nxt][(ks + 0) * 128 + m] = ra0.x;
                As[nxt][(ks + 1) * 128 + m] = ra0.y;
                As[nxt][(ks + 2) * 128 + m] = ra0.z;
                As[nxt][(ks + 3) * 128 + m] = ra0.w;
                As[nxt][(ks + 4) * 128 + m] = ra1.x;
                As[nxt][(ks + 5) * 128 + m] = ra1.y;
                As[nxt][(ks + 6) * 128 + m] = ra1.z;
                As[nxt][(ks + 7) * 128 + m] = ra1.w;
            }
            *(float4*)&Bs[nxt][(t >> 4) * 128 + (t & 15) * 8]     = rb0;
            *(float4*)&Bs[nxt][(t >> 4) * 128 + (t & 15) * 8 + 4] = rb1;
        }
        __syncthreads();
    }

#pragma unroll
    for (int i = 0; i < 8; i++) {
        float4 o0, o1;
        o0.x = lo32(acc[i][0]); o0.y = hi32(acc[i][0]);
        o0.z = lo32(acc[i][1]); o0.w = hi32(acc[i][1]);
        o1.x = lo32(acc[i][2]); o1.y = hi32(acc[i][2]);
        o1.z = lo32(acc[i][3]); o1.w = hi32(acc[i][3]);
        float* cp = C + (m0 + ty * 8 + i) * ldc + n0 + tx * 8;
        *(float4*)(cp)     = o0;
        *(float4*)(cp + 4) = o1;
    }
}

__global__ void __launch_bounds__(256)
gemmSmall(const float* __restrict__ A, const float* __restrict__ B,
          float* __restrict__ C,
          int lda, int ldb, int ldc,
          int d0, int d1,
          long a0, long a1, long a2,
          long b0, long b1, long b2,
          long c0, long c1, long c2)
{
    __shared__ __align__(16) float As[64 * 68];
    __shared__ __align__(16) float Bs[64 * 64];

    const int t  = threadIdx.x;
    const int tx = t & 15;
    const int ty = t >> 4;

    {
        const int z  = blockIdx.z;
        const int z0 = z % d0;
        const int zr = z / d0;
        const int z1 = zr % d1;
        const int z2 = zr / d1;
        A += (long)z0 * a0 + (long)z1 * a1 + (long)z2 * a2;
        B += (long)z0 * b0 + (long)z1 * b1 + (long)z2 * b2;
        C += (long)z0 * c0 + (long)z1 * c1 + (long)z2 * c2;
    }
    const long m0 = (long)blockIdx.y * 64;

    {
        const int m = t >> 2, kseg = (t & 3) * 16;
        const float* Ag = A + (m0 + m) * lda + kseg;
#pragma unroll
        for (int s = 0; s < 4; s++)
            *(float4*)&As[m * 68 + kseg + s * 4] = *(const float4*)(Ag + s * 4);
    }
    {
        const int r = t >> 2, cs = (t & 3) * 16;
        const float* Bg = B + (long)r * ldb + cs;
#pragma unroll
        for (int s = 0; s < 4; s++)
            *(float4*)&Bs[r * 64 + cs + s * 4] = *(const float4*)(Bg + s * 4);
    }
    __syncthreads();

    unsigned long long acc[4][2];
#pragma unroll
    for (int i = 0; i < 4; i++) { acc[i][0] = 0ull; acc[i][1] = 0ull; }

#pragma unroll 8
    for (int kk = 0; kk < 64; kk++) {
        const ulonglong2 bv = *(const ulonglong2*)&Bs[kk * 64 + tx * 4];
        const unsigned long long bb0 = bv.x, bb1 = bv.y;
        unsigned long long p;
        p = pack2(As[(ty * 4 + 0) * 68 + kk]); fma2(acc[0][0], p, bb0); fma2(acc[0][1], p, bb1);
        p = pack2(As[(ty * 4 + 1) * 68 + kk]); fma2(acc[1][0], p, bb0); fma2(acc[1][1], p, bb1);
        p = pack2(As[(ty * 4 + 2) * 68 + kk]); fma2(acc[2][0], p, bb0); fma2(acc[2][1], p, bb1);
        p = pack2(As[(ty * 4 + 3) * 68 + kk]); fma2(acc[3][0], p, bb0); fma2(acc[3][1], p, bb1);
    }

#pragma unroll
    for (int i = 0; i < 4; i++) {
        float4 o;
        o.x = lo32(acc[i][0]); o.y = hi32(acc[i][0]);
        o.z = lo32(acc[i][1]); o.w = hi32(acc[i][1]);
        *(float4*)&C[(m0 + ty * 4 + i) * ldc + tx * 4] = o;
    }
}

__global__ void __launch_bounds__(256)
reduceP(const float4* __restrict__ src, float4* __restrict__ dst, int S4, int P)
{
    const int i = blockIdx.x * 256 + threadIdx.x;
    if (i >= S4) return;
    float4 s = src[i];
    for (int p = 1; p < P; p++) {
        const float4 v = src[(long)p * S4 + i];
        s.x += v.x; s.y += v.y; s.z += v.z; s.w += v.w;
    }
    dst[i] = s;
}

// ---------------------------------------------------------------------------
// kernel_launch
// ---------------------------------------------------------------------------
extern "C" void kernel_launch(void* const* d_in, const int* in_sizes, int n_in,
                              void* d_out, int out_size)
{
    (void)in_sizes; (void)n_in; (void)out_size;
    const float* x  = (const float*)d_in[0];
    const float* Wq = (const float*)d_in[1];
    const float* Wk = (const float*)d_in[2];
    const float* Wv = (const float*)d_in[3];
    const float* Wo = (const float*)d_in[4];
    float* out = (float*)d_out;

    void* p;
    cudaGetSymbolAddress(&p, g_Gp ); float* Gp  = (float*)p;
    cudaGetSymbolAddress(&p, g_G  ); float* G   = (float*)p;
    cudaGetSymbolAddress(&p, g_T1p); float* T1p = (float*)p;
    cudaGetSymbolAddress(&p, g_T1 ); float* T1  = (float*)p;
    cudaGetSymbolAddress(&p, g_Mp ); float* Mp  = (float*)p;
    cudaGetSymbolAddress(&p, g_M  ); float* M   = (float*)p;
    cudaGetSymbolAddress(&p, g_T2 ); float* T2  = (float*)p;
    cudaGetSymbolAddress(&p, g_Up ); float* Up  = (float*)p;
    cudaGetSymbolAddress(&p, g_U  ); float* U   = (float*)p;
    cudaGetSymbolAddress(&p, g_xrh); __nv_bfloat16* xrh = (__nv_bfloat16*)p;
    cudaGetSymbolAddress(&p, g_xrl); __nv_bfloat16* xrl = (__nv_bfloat16*)p;
    cudaGetSymbolAddress(&p, g_xth); __nv_bfloat16* xth = (__nv_bfloat16*)p;
    cudaGetSymbolAddress(&p, g_xtl); __nv_bfloat16* xtl = (__nv_bfloat16*)p;
    cudaGetSymbolAddress(&p, g_uth); __nv_bfloat16* uth = (__nv_bfloat16*)p;
    cudaGetSymbolAddress(&p, g_utl); __nv_bfloat16* utl = (__nv_bfloat16*)p;

    static bool attr_done = false;
    if (!attr_done) {
        cudaFuncSetAttribute(mmaT, cudaFuncAttributeMaxDynamicSharedMemorySize, MMA_SMEM);
        attr_done = true;
    }

    const long xB = (long)LL * DIN;      // 2097152
    const long GS = (long)DIN * DIN;     // 262144

    // A) bf16 splits of x (row-major and transposed)
    splitRow<<<(BB * LL * DIN / 4 + 255) / 256, 256>>>(
        (const float4*)x, (uint2*)xrh, (uint2*)xrl, BB * LL * DIN / 4);
    splitT<<<dim3(DIN / 32, LL / 32, BB), dim3(32, 8)>>>(x, xth, xtl, LL, DIN);

    // B) Gram partials via mma.sync: Gp[ks][b] = xT slice @ slice^T
    //    K per split = 4096/8 = 512 -> nChunk=16
    mmaT<<<dim3(4, 4, 16), 256, MMA_SMEM>>>(
        xth, xtl, xth, xtl, Gp,
        /*ldA=*/LL, /*ldB=*/LL, /*ldC=*/DIN, /*nChunk=*/16, /*d0=*/BB,
        /*aB=*/xB, /*bB=*/xB, /*cB=*/GS, /*cS=*/(long)BB * GS);
    reduceP<<<512, 256>>>((const float4*)Gp, (float4*)G, (BB * GS) / 4, 8);

    // C) mid-chain (SIMT)
    gemm128<true><<<dim3(4, 4, 8), 256>>>(Wk, G, T1p,
        128, DK, DIN, DIN, (long)DIN * DK,
        BB, 4,
        0, 128L * DK, 0,
        GS, 128L * DIN, 0,
        GS, BB * GS, 0);
    reduceP<<<512, 256>>>((const float4*)T1p, (float4*)T1, (BB * GS) / 4, 4);

    gemmSmall<<<dim3(1, 1, 128), 256>>>(T1, Wv, Mp,
        DIN, DV, DV,
        HH, BB,
        64L * DIN, GS, 64,
        (long)DIN * DV, 0, 64L * DV,
        (long)DK * DV, (long)HH * DK * DV, (long)BB * HH * DK * DV);
    reduceP<<<64, 256>>>((const float4*)Mp, (float4*)M, (BB * HH * DK * DV) / 4, 8);

    gemmSmall<<<dim3(1, 8, 16), 256>>>(Wq, M, T2,
        DK, DV, HH * DV,
        HH, BB,
        (long)DIN * DK, 0, 0,
        (long)DK * DV, (long)HH * DK * DV, 0,
        DV, (long)DIN * HH * DV, 0);

    gemm128<false><<<dim3(4, 4, 8), 256>>>(T2, Wo, Up,
        128, HH * DV, DOUT, DOUT, 0,
        BB, 4,
        (long)DIN * HH * DV, 128, 0,
        0, 128L * DOUT, 0,
        GS, BB * GS, 0);
    reduceP<<<512, 256>>>((const float4*)Up, (float4*)U, (BB * GS) / 4, 4);

    // D) U^T bf16 split
    splitT<<<dim3(DOUT / 32, DIN / 32, BB), dim3(32, 8)>>>(U, uth, utl, DIN, DOUT);

    // E) out = x @ U via mma.sync: A = x rows (K=DIN), B = U^T rows (K=DIN)
    mmaT<<<dim3(4, 32, BB), 256, MMA_SMEM>>>(
        xrh, xrl, uth, utl, out,
        /*ldA=*/DIN, /*ldB=*/DIN, /*ldC=*/DOUT, /*nChunk=*/16, /*d0=*/BB,
        /*aB=*/xB, /*bB=*/(long)DOUT * DIN, /*cB=*/(long)LL * DOUT, /*cS=*/0);
}

// round 6
// speedup vs baseline: 1.7580x; 1.0066x over previous
#include <cuda_runtime.h>
#include <cuda_bf16.h>
#include <cstdint>

// Problem constants
#define BB   2
#define LL   4096
#define DIN  512
#define HH   8
#define DK   64
#define DV   64
#define DOUT 512

// ---------------------------------------------------------------------------
// Scratch (device globals)
// ---------------------------------------------------------------------------
__device__ float g_Gp [8 * BB * DIN * DIN];     // gram partials [ks][b] (upper tiles)
__device__ float g_G  [BB * DIN * DIN];         // G[b] full (mirrored)
__device__ float g_T1p[4 * BB * DIN * DIN];     // T1 partials [ks][b]
__device__ float g_T1 [BB * DIN * DIN];         // T1cat[b] = Wkcat^T G[b]
__device__ float g_Mp [8 * BB * HH * DK * DV];  // M partials [ks][b][h]
__device__ float g_M  [BB * HH * DK * DV];      // M[b][h]
__device__ float g_T2 [BB * DIN * (HH * DV)];   // T2cat[b]
__device__ float g_Up [4 * BB * DIN * DOUT];    // U partials [ks][b]

// bf16 split buffers
__device__ __nv_bfloat16 g_xrh[BB * LL * DIN];  // x row-major hi
__device__ __nv_bfloat16 g_xrl[BB * LL * DIN];  // x row-major lo
__device__ __nv_bfloat16 g_xth[BB * DIN * LL];  // x^T hi  (channel-major)
__device__ __nv_bfloat16 g_xtl[BB * DIN * LL];  // x^T lo
__device__ __nv_bfloat16 g_uth[BB * DOUT * DIN];// U^T hi  (o-major)
__device__ __nv_bfloat16 g_utl[BB * DOUT * DIN];// U^T lo

// Upper-triangle tile map for 4x4 tile grid
__constant__ int c_tri_i[10] = {0,0,0,0,1,1,1,2,2,3};
__constant__ int c_tri_j[10] = {0,1,2,3,1,2,3,2,3,3};

// ---------------------------------------------------------------------------
// f32x2 helpers (SIMT mid-chain)
// ---------------------------------------------------------------------------
__device__ __forceinline__ unsigned long long pack2(float a) {
    unsigned long long r;
    asm("mov.b64 %0, {%1, %1};" : "=l"(r) : "f"(a));
    return r;
}
__device__ __forceinline__ void fma2(unsigned long long& acc,
                                     unsigned long long a,
                                     unsigned long long b) {
    asm("fma.rn.f32x2 %0, %1, %2, %0;" : "+l"(acc) : "l"(a), "l"(b));
}
__device__ __forceinline__ float lo32(unsigned long long v) {
    return __uint_as_float((unsigned)(v & 0xffffffffull));
}
__device__ __forceinline__ float hi32(unsigned long long v) {
    return __uint_as_float((unsigned)(v >> 32));
}

// ---------------------------------------------------------------------------
// helpers for mma.sync path
// ---------------------------------------------------------------------------
__device__ __forceinline__ uint32_t smem_u32(const void* p) {
    uint32_t a;
    asm("{ .reg .u64 t; cvta.to.shared.u64 t, %1; cvt.u32.u64 %0, t; }"
        : "=r"(a) : "l"(p));
    return a;
}
__device__ __forceinline__ void cp_async16(uint32_t dst, const void* src) {
    asm volatile("cp.async.cg.shared.global [%0], [%1], 16;" :: "r"(dst), "l"(src));
}
__device__ __forceinline__ uint32_t lds32(uint32_t addr) {
    uint32_t v;
    asm volatile("ld.shared.b32 %0, [%1];" : "=r"(v) : "r"(addr));
    return v;
}
__device__ __forceinline__ void mma16816(float* c, const uint32_t* a, const uint32_t* b) {
    asm volatile(
        "mma.sync.aligned.m16n8k16.row.col.f32.bf16.bf16.f32 "
        "{%0,%1,%2,%3}, {%4,%5,%6,%7}, {%8,%9}, {%0,%1,%2,%3};"
        : "+f"(c[0]), "+f"(c[1]), "+f"(c[2]), "+f"(c[3])
        : "r"(a[0]), "r"(a[1]), "r"(a[2]), "r"(a[3]), "r"(b[0]), "r"(b[1]));
}

// ---------------------------------------------------------------------------
// mmaT: C[128x128 tile] fp32 = split-bf16 A(M rows,K) @ B(N rows,K)^T
//   TRI=true: blockIdx.x in [0,10) selects upper-triangular tile (i,j) of a
//   4x4 tile grid (for symmetric outputs); else tiles from (blockIdx.x, .y).
// 256 threads = 8 warps, warp tile 64x32. 3-term split: AhBh + AhBl + AlBh.
// ---------------------------------------------------------------------------
#define ROWB   80
#define MATB   (128 * ROWB)      // 10240 per split matrix
#define BUFB   (4 * MATB)        // 40960 per k-chunk buffer
#define MMA_SMEM (2 * BUFB)      // 81920

template <bool TRI>
__global__ void __launch_bounds__(256)
mmaT(const __nv_bfloat16* __restrict__ Ahi, const __nv_bfloat16* __restrict__ Alo,
     const __nv_bfloat16* __restrict__ Bhi, const __nv_bfloat16* __restrict__ Blo,
     float* __restrict__ C,
     int ldA, int ldB, int ldC, int nChunk, int d0,
     long aB, long bB, long cB, long cS)
{
    extern __shared__ char sm[];
    const uint32_t su = smem_u32(sm);

    const int t    = threadIdx.x;
    const int wid  = t >> 5;
    const int lane = t & 31;
    const int g    = lane >> 2;   // 0..7
    const int tq   = lane & 3;    // 0..3
    const int wm   = wid & 1;     // m warp (64 rows)
    const int wn   = wid >> 1;    // n warp (32 cols)

    const int z  = blockIdx.z;
    const int z0 = z % d0;
    const int z1 = z / d0;
    const long kOff = (long)z1 * nChunk * 32;

    long m0, n0;
    if (TRI) {
        m0 = (long)c_tri_i[blockIdx.x] * 128;
        n0 = (long)c_tri_j[blockIdx.x] * 128;
    } else {
        m0 = (long)blockIdx.y * 128;
        n0 = (long)blockIdx.x * 128;
    }

    const __nv_bfloat16* bAh = Ahi + (long)z0 * aB + kOff + m0 * ldA;
    const __nv_bfloat16* bAl = Alo + (long)z0 * aB + kOff + m0 * ldA;
    const __nv_bfloat16* bBh = Bhi + (long)z0 * bB + kOff + n0 * ldB;
    const __nv_bfloat16* bBl = Blo + (long)z0 * bB + kOff + n0 * ldB;
    C += (long)z0 * cB + (long)z1 * cS;

    // loader: thread handles chunk-ids t and t+256 for each of the 4 matrices
    const int r0 = t >> 2,        s0 = (t & 3) * 16;
    const int r1 = (t + 256) >> 2, s1 = ((t + 256) & 3) * 16;

    float acc[4][4][4];
#pragma unroll
    for (int i = 0; i < 4; i++)
#pragma unroll
        for (int j = 0; j < 4; j++)
#pragma unroll
            for (int k = 0; k < 4; k++) acc[i][j][k] = 0.f;

#define LOAD_CHUNK(cidx, buf)                                                   \
    do {                                                                        \
        const uint32_t sb_ = su + (buf) * BUFB;                                 \
        const long ko_ = (long)(cidx) * 32;                                     \
        cp_async16(sb_ + 0 * MATB + r0 * ROWB + s0, bAh + (long)r0 * ldA + ko_ + s0 / 2); \
        cp_async16(sb_ + 0 * MATB + r1 * ROWB + s1, bAh + (long)r1 * ldA + ko_ + s1 / 2); \
        cp_async16(sb_ + 1 * MATB + r0 * ROWB + s0, bAl + (long)r0 * ldA + ko_ + s0 / 2); \
        cp_async16(sb_ + 1 * MATB + r1 * ROWB + s1, bAl + (long)r1 * ldA + ko_ + s1 / 2); \
        cp_async16(sb_ + 2 * MATB + r0 * ROWB + s0, bBh + (long)r0 * ldB + ko_ + s0 / 2); \
        cp_async16(sb_ + 2 * MATB + r1 * ROWB + s1, bBh + (long)r1 * ldB + ko_ + s1 / 2); \
        cp_async16(sb_ + 3 * MATB + r0 * ROWB + s0, bBl + (long)r0 * ldB + ko_ + s0 / 2); \
        cp_async16(sb_ + 3 * MATB + r1 * ROWB + s1, bBl + (long)r1 * ldB + ko_ + s1 / 2); \
        asm volatile("cp.async.commit_group;" ::: "memory");                    \
    } while (0)

    LOAD_CHUNK(0, 0);

    for (int c = 0; c < nChunk; c++) {
        const int buf = c & 1;
        if (c + 1 < nChunk) {
            LOAD_CHUNK(c + 1, buf ^ 1);
            asm volatile("cp.async.wait_group 1;" ::: "memory");
        } else {
            asm volatile("cp.async.wait_group 0;" ::: "memory");
        }
        __syncthreads();

        const uint32_t sb = su + buf * BUFB;
#pragma unroll
        for (int s = 0; s < 2; s++) {
            const uint32_t kb = s * 32 + tq * 4;
            uint32_t ah[4][4], al[4][4], bh[4][2], bl[4][2];
#pragma unroll
            for (int mt = 0; mt < 4; mt++) {
                const uint32_t ra = (uint32_t)(wm * 64 + mt * 16 + g) * ROWB + kb;
                ah[mt][0] = lds32(sb + ra);
                ah[mt][1] = lds32(sb + ra + 8 * ROWB);
                ah[mt][2] = lds32(sb + ra + 16);
                ah[mt][3] = lds32(sb + ra + 8 * ROWB + 16);
                al[mt][0] = lds32(sb + MATB + ra);
                al[mt][1] = lds32(sb + MATB + ra + 8 * ROWB);
                al[mt][2] = lds32(sb + MATB + ra + 16);
                al[mt][3] = lds32(sb + MATB + ra + 8 * ROWB + 16);
            }
#pragma unroll
            for (int nt = 0; nt < 4; nt++) {
                const uint32_t rb = (uint32_t)(wn * 32 + nt * 8 + g) * ROWB + kb;
                bh[nt][0] = lds32(sb + 2 * MATB + rb);
                bh[nt][1] = lds32(sb + 2 * MATB + rb + 16);
                bl[nt][0] = lds32(sb + 3 * MATB + rb);
                bl[nt][1] = lds32(sb + 3 * MATB + rb + 16);
            }
#pragma unroll
            for (int mt = 0; mt < 4; mt++)
#pragma unroll
                for (int nt = 0; nt < 4; nt++) {
                    mma16816(acc[mt][nt], ah[mt], bh[nt]);
                    mma16816(acc[mt][nt], ah[mt], bl[nt]);
                    mma16816(acc[mt][nt], al[mt], bh[nt]);
                }
        }
        __syncthreads();
    }

    // epilogue
#pragma unroll
    for (int mt = 0; mt < 4; mt++) {
#pragma unroll
        for (int nt = 0; nt < 4; nt++) {
            const long row = m0 + wm * 64 + mt * 16 + g;
            const long col = n0 + wn * 32 + nt * 8 + 2 * tq;
            float2 v0 = make_float2(acc[mt][nt][0], acc[mt][nt][1]);
            float2 v1 = make_float2(acc[mt][nt][2], acc[mt][nt][3]);
            *(float2*)&C[row * ldC + col]       = v0;
            *(float2*)&C[(row + 8) * ldC + col] = v1;
        }
    }
}

// ---------------------------------------------------------------------------
// sx4: fused row-split + transpose-split of x for one batch / row range.
// grid (DIN/32, nRows/32), block (32, 8)
// ---------------------------------------------------------------------------
__global__ void __launch_bounds__(256)
sx4(const float* __restrict__ x,
    __nv_bfloat16* __restrict__ xrh, __nv_bfloat16* __restrict__ xrl,
    __nv_bfloat16* __restrict__ xth, __nv_bfloat16* __restrict__ xtl,
    int b, int rbase)
{
    __shared__ float tl[32][33];
    const long xoff = (long)b * LL * DIN;
    const int c0 = blockIdx.x * 32;
    const int r0 = rbase + blockIdx.y * 32;
    const int tx = threadIdx.x, ty = threadIdx.y;
#pragma unroll
    for (int i = 0; i < 4; i++) {
        const int r = r0 + ty + 8 * i;
        const long o = xoff + (long)r * DIN + c0 + tx;
        const float v = x[o];
        tl[ty + 8 * i][tx] = v;
        const __nv_bfloat16 h = __float2bfloat16(v);
        const __nv_bfloat16 l = __float2bfloat16(v - __bfloat162float(h));
        xrh[o] = h;
        xrl[o] = l;
    }
    __syncthreads();
#pragma unroll
    for (int i = 0; i < 4; i++) {
        const float v = tl[tx][ty + 8 * i];   // x[r0+tx][c0+ty+8i]
        const __nv_bfloat16 h = __float2bfloat16(v);
        const __nv_bfloat16 l = __float2bfloat16(v - __bfloat162float(h));
        const long o = xoff + (long)(c0 + ty + 8 * i) * LL + r0 + tx;
        xth[o] = h;
        xtl[o] = l;
    }
}

// ---------------------------------------------------------------------------
// reduceGsym: sum 8 gram partials (valid only on upper 128-tiles) into full
// symmetric G. grid (16,16,BB), block (32,8).
// ---------------------------------------------------------------------------
__global__ void __launch_bounds__(256)
reduceGsym(const float* __restrict__ Gp, float* __restrict__ G)
{
    __shared__ float s[32][33];
    const int b  = blockIdx.z;
    const int j0 = blockIdx.x * 32, i0 = blockIdx.y * 32;
    const int tx = threadIdx.x, ty = threadIdx.y;
    const long base = (long)b * DIN * DIN;
    const long PS   = (long)BB * DIN * DIN;

    if ((i0 >> 7) <= (j0 >> 7)) {
#pragma unroll
        for (int i = 0; i < 4; i++) {
            const int r = i0 + ty + 8 * i;
            float sum = 0.f;
#pragma unroll
            for (int p = 0; p < 8; p++)
                sum += Gp[(long)p * PS + base + (long)r * DIN + j0 + tx];
            G[base + (long)r * DIN + j0 + tx] = sum;
        }
    } else {
#pragma unroll
        for (int i = 0; i < 4; i++) {
            const int r = j0 + ty + 8 * i;   // mirrored source row
            float sum = 0.f;
#pragma unroll
            for (int p = 0; p < 8; p++)
                sum += Gp[(long)p * PS + base + (long)r * DIN + i0 + tx];
            s[ty + 8 * i][tx] = sum;
        }
        __syncthreads();
#pragma unroll
        for (int i = 0; i < 4; i++)
            G[base + (long)(i0 + ty + 8 * i) * DIN + j0 + tx] = s[tx][ty + 8 * i];
    }
}

// ---------------------------------------------------------------------------
// redUpSplitT: sum 4 U partials, transpose, bf16-split -> uth/utl.
// Up layout [p][b][DIN][DOUT]; out [b][DOUT][DIN]. grid (16,16,BB), block (32,8)
// ---------------------------------------------------------------------------
__global__ void __launch_bounds__(256)
redUpSplitT(const float* __restrict__ Up,
            __nv_bfloat16* __restrict__ oh, __nv_bfloat16* __restrict__ ol)
{
    __shared__ float tl[32][33];
    const int b  = blockIdx.z;
    const int c0 = blockIdx.x * 32, r0 = blockIdx.y * 32;
    const int tx = threadIdx.x, ty = threadIdx.y;
    const long base = (long)b * DIN * DOUT;
    const long PS   = (long)BB * DIN * DOUT;
#pragma unroll
    for (int i = 0; i < 4; i++) {
        const int r = r0 + ty + 8 * i;
        float sum = 0.f;
#pragma unroll
        for (int p = 0; p < 4; p++)
            sum += Up[(long)p * PS + base + (long)r * DOUT + c0 + tx];
        tl[ty + 8 * i][tx] = sum;
    }
    __syncthreads();
#pragma unroll
    for (int i = 0; i < 4; i++) {
        const float v = tl[tx][ty + 8 * i];
        const __nv_bfloat16 h = __float2bfloat16(v);
        const __nv_bfloat16 l = __float2bfloat16(v - __bfloat162float(h));
        const long o = base + (long)(c0 + ty + 8 * i) * DIN + r0 + tx;
        oh[o] = h;
        ol[o] = l;
    }
}

// ---------------------------------------------------------------------------
// SIMT mid-chain kernels (unchanged)
// ---------------------------------------------------------------------------
template <bool TA>
__global__ void __launch_bounds__(256)
gemm128(const float* __restrict__ A, const float* __restrict__ B,
        float* __restrict__ C,
        int K, int lda, int ldb, int ldc, long a_hs,
        int d0, int d1,
        long a0, long a1, long a2,
        long b0, long b1, long b2,
        long c0, long c1, long c2)
{
    __shared__ __align__(16) float As[2][16 * 128];
    __shared__ __align__(16) float Bs[2][16 * 128];

    const int t  = threadIdx.x;
    const int tx = t & 15;
    const int ty = t >> 4;

    {
        const int z  = blockIdx.z;
        const int z0 = z % d0;
        const int zr = z / d0;
        const int z1 = zr % d1;
        const int z2 = zr / d1;
        A += (long)z0 * a0 + (long)z1 * a1 + (long)z2 * a2;
        B += (long)z0 * b0 + (long)z1 * b1 + (long)z2 * b2;
        C += (long)z0 * c0 + (long)z1 * c1 + (long)z2 * c2;
    }

    const long m0 = (long)blockIdx.y * 128;
    const long n0 = (long)blockIdx.x * 128;

    const float* Ag;
    if (TA) {
        const long mm = m0 + (t & 15) * 8;
        Ag = A + ((mm >> 6) * a_hs + (mm & 63)) + (long)(t >> 4) * lda;
    } else {
        Ag = A + (m0 + (t >> 1)) * lda + (t & 1) * 8;
    }
    const float* Bg = B + (long)(t >> 4) * ldb + n0 + (t & 15) * 8;

    unsigned long long acc[8][4];
#pragma unroll
    for (int i = 0; i < 8; i++)
#pragma unroll
        for (int j = 0; j < 4; j++) acc[i][j] = 0ull;

    const int ktiles = K / 16;

    float4 ra0 = *(const float4*)(Ag);
    float4 ra1 = *(const float4*)(Ag + 4);
    float4 rb0 = *(const float4*)(Bg);
    float4 rb1 = *(const float4*)(Bg + 4);

    if (TA) {
        *(float4*)&As[0][(t >> 4) * 128 + (t & 15) * 8]     = ra0;
        *(float4*)&As[0][(t >> 4) * 128 + (t & 15) * 8 + 4] = ra1;
    } else {
        const int m = t >> 1, ks = (t & 1) * 8;
        As[0][(ks + 0) * 128 + m] = ra0.x;
        As[0][(ks + 1) * 128 + m] = ra0.y;
        As[0][(ks + 2) * 128 + m] = ra0.z;
        As[0][(ks + 3) * 128 + m] = ra0.w;
        As[0][(ks + 4) * 128 + m] = ra1.x;
        As[0][(ks + 5) * 128 + m] = ra1.y;
        As[0][(ks + 6) * 128 + m] = ra1.z;
        As[0][(ks + 7) * 128 + m] = ra1.w;
    }
    *(float4*)&Bs[0][(t >> 4) * 128 + (t & 15) * 8]     = rb0;
    *(float4*)&Bs[0][(t >> 4) * 128 + (t & 15) * 8 + 4] = rb1;
    __syncthreads();

    for (int kt = 0; kt < ktiles; kt++) {
        const int cur = kt & 1;
        const bool more = (kt + 1 < ktiles);
        if (more) {
            Ag += TA ? 16 * lda : 16;
            Bg += 16 * ldb;
            ra0 = *(const float4*)(Ag);
            ra1 = *(const float4*)(Ag + 4);
            rb0 = *(const float4*)(Bg);
            rb1 = *(const float4*)(Bg + 4);
        }

#pragma unroll
        for (int kk = 0; kk < 16; kk++) {
            const float4 av0 = *(const float4*)&As[cur][kk * 128 + ty * 8];
            const float4 av1 = *(const float4*)&As[cur][kk * 128 + ty * 8 + 4];
            const ulonglong2 bv0 = *(const ulonglong2*)&Bs[cur][kk * 128 + tx * 8];
            const ulonglong2 bv1 = *(const ulonglong2*)&Bs[cur][kk * 128 + tx * 8 + 4];
            const unsigned long long bb0 = bv0.x, bb1 = bv0.y, bb2 = bv1.x, bb3 = bv1.y;
            unsigned long long p;
            p = pack2(av0.x); fma2(acc[0][0], p, bb0); fma2(acc[0][1], p, bb1); fma2(acc[0][2], p, bb2); fma2(acc[0][3], p, bb3);
            p = pack2(av0.y); fma2(acc[1][0], p, bb0); fma2(acc[1][1], p, bb1); fma2(acc[1][2], p, bb2); fma2(acc[1][3], p, bb3);
            p = pack2(av0.z); fma2(acc[2][0], p, bb0); fma2(acc[2][1], p, bb1); fma2(acc[2][2], p, bb2); fma2(acc[2][3], p, bb3);
            p = pack2(av0.w); fma2(acc[3][0], p, bb0); fma2(acc[3][1], p, bb1); fma2(acc[3][2], p, bb2); fma2(acc[3][3], p, bb3);
            p = pack2(av1.x); fma2(acc[4][0], p, bb0); fma2(acc[4][1], p, bb1); fma2(acc[4][2], p, bb2); fma2(acc[4][3], p, bb3);
            p = pack2(av1.y); fma2(acc[5][0], p, bb0); fma2(acc[5][1], p, bb1); fma2(acc[5][2], p, bb2); fma2(acc[5][3], p, bb3);
            p = pack2(av1.z); fma2(acc[6][0], p, bb0); fma2(acc[6][1], p, bb1); fma2(acc[6][2], p, bb2); fma2(acc[6][3], p, bb3);
            p = pack2(av1.w); fma2(acc[7][0], p, bb0); fma2(acc[7][1], p, bb1); fma2(acc[7][2], p, bb2); fma2(acc[7][3], p, bb3);
        }

        if (more) {
            const int nxt = cur ^ 1;
            if (TA) {
                *(float4*)&As[nxt][(t >> 4) * 128 + (t & 15) * 8]     = ra0;
                *(float4*)&As[nxt][(t >> 4) * 128 + (t & 15) * 8 + 4] = ra1;
            } else {
                const int m = t >> 1, ks = (t & 1) * 8;
                As[nxt][(ks + 0) * 128 + m] = ra0.x;
                As[nxt][(ks + 1) * 128 + m] = ra0.y;
                As[nxt][(ks + 2) * 128 + m] = ra0.z;
                As[nxt][(ks + 3) * 128 + m] = ra0.w;
                As[nxt][(ks + 4) * 128 + m] = ra1.x;
                As[nxt][(ks + 5) * 128 + m] = ra1.y;
                As[nxt][(ks + 6) * 128 + m] = ra1.z;
                As[nxt][(ks + 7) * 128 + m] = ra1.w;
            }
            *(float4*)&Bs[nxt][(t >> 4) * 128 + (t & 15) * 8]     = rb0;
            *(float4*)&Bs[nxt][(t >> 4) * 128 + (t & 15) * 8 + 4] = rb1;
        }
        __syncthreads();
    }

#pragma unroll
    for (int i = 0; i < 8; i++) {
        float4 o0, o1;
        o0.x = lo32(acc[i][0]); o0.y = hi32(acc[i][0]);
        o0.z = lo32(acc[i][1]); o0.w = hi32(acc[i][1]);
        o1.x = lo32(acc[i][2]); o1.y = hi32(acc[i][2]);
        o1.z = lo32(acc[i][3]); o1.w = hi32(acc[i][3]);
        float* cp = C + (m0 + ty * 8 + i) * ldc + n0 + tx * 8;
        *(float4*)(cp)     = o0;
        *(float4*)(cp + 4) = o1;
    }
}

__global__ void __launch_bounds__(256)
gemmSmall(const float* __restrict__ A, const float* __restrict__ B,
          float* __restrict__ C,
          int lda, int ldb, int ldc,
          int d0, int d1,
          long a0, long a1, long a2,
          long b0, long b1, long b2,
          long c0, long c1, long c2)
{
    __shared__ __align__(16) float As[64 * 68];
    __shared__ __align__(16) float Bs[64 * 64];

    const int t  = threadIdx.x;
    const int tx = t & 15;
    const int ty = t >> 4;

    {
        const int z  = blockIdx.z;
        const int z0 = z % d0;
        const int zr = z / d0;
        const int z1 = zr % d1;
        const int z2 = zr / d1;
        A += (long)z0 * a0 + (long)z1 * a1 + (long)z2 * a2;
        B += (long)z0 * b0 + (long)z1 * b1 + (long)z2 * b2;
        C += (long)z0 * c0 + (long)z1 * c1 + (long)z2 * c2;
    }
    const long m0 = (long)blockIdx.y * 64;

    {
        const int m = t >> 2, kseg = (t & 3) * 16;
        const float* Ag = A + (m0 + m) * lda + kseg;
#pragma unroll
        for (int s = 0; s < 4; s++)
            *(float4*)&As[m * 68 + kseg + s * 4] = *(const float4*)(Ag + s * 4);
    }
    {
        const int r = t >> 2, cs = (t & 3) * 16;
        const float* Bg = B + (long)r * ldb + cs;
#pragma unroll
        for (int s = 0; s < 4; s++)
            *(float4*)&Bs[r * 64 + cs + s * 4] = *(const float4*)(Bg + s * 4);
    }
    __syncthreads();

    unsigned long long acc[4][2];
#pragma unroll
    for (int i = 0; i < 4; i++) { acc[i][0] = 0ull; acc[i][1] = 0ull; }

#pragma unroll 8
    for (int kk = 0; kk < 64; kk++) {
        const ulonglong2 bv = *(const ulonglong2*)&Bs[kk * 64 + tx * 4];
        const unsigned long long bb0 = bv.x, bb1 = bv.y;
        unsigned long long p;
        p = pack2(As[(ty * 4 + 0) * 68 + kk]); fma2(acc[0][0], p, bb0); fma2(acc[0][1], p, bb1);
        p = pack2(As[(ty * 4 + 1) * 68 + kk]); fma2(acc[1][0], p, bb0); fma2(acc[1][1], p, bb1);
        p = pack2(As[(ty * 4 + 2) * 68 + kk]); fma2(acc[2][0], p, bb0); fma2(acc[2][1], p, bb1);
        p = pack2(As[(ty * 4 + 3) * 68 + kk]); fma2(acc[3][0], p, bb0); fma2(acc[3][1], p, bb1);
    }

#pragma unroll
    for (int i = 0; i < 4; i++) {
        float4 o;
        o.x = lo32(acc[i][0]); o.y = hi32(acc[i][0]);
        o.z = lo32(acc[i][1]); o.w = hi32(acc[i][1]);
        *(float4*)&C[(m0 + ty * 4 + i) * ldc + tx * 4] = o;
    }
}

__global__ void __launch_bounds__(256)
reduceP(const float4* __restrict__ src, float4* __restrict__ dst, int S4, int P)
{
    const int i = blockIdx.x * 256 + threadIdx.x;
    if (i >= S4) return;
    float4 s = src[i];
    for (int p = 1; p < P; p++) {
        const float4 v = src[(long)p * S4 + i];
        s.x += v.x; s.y += v.y; s.z += v.z; s.w += v.w;
    }
    dst[i] = s;
}

// ---------------------------------------------------------------------------
// kernel_launch
// ---------------------------------------------------------------------------
extern "C" void kernel_launch(void* const* d_in, const int* in_sizes, int n_in,
                              void* d_out, int out_size)
{
    (void)in_sizes; (void)n_in; (void)out_size;
    const float* x  = (const float*)d_in[0];
    const float* Wq = (const float*)d_in[1];
    const float* Wk = (const float*)d_in[2];
    const float* Wv = (const float*)d_in[3];
    const float* Wo = (const float*)d_in[4];
    float* out = (float*)d_out;

    void* p;
    cudaGetSymbolAddress(&p, g_Gp ); float* Gp  = (float*)p;
    cudaGetSymbolAddress(&p, g_G  ); float* G   = (float*)p;
    cudaGetSymbolAddress(&p, g_T1p); float* T1p = (float*)p;
    cudaGetSymbolAddress(&p, g_T1 ); float* T1  = (float*)p;
    cudaGetSymbolAddress(&p, g_Mp ); float* Mp  = (float*)p;
    cudaGetSymbolAddress(&p, g_M  ); float* M   = (float*)p;
    cudaGetSymbolAddress(&p, g_T2 ); float* T2  = (float*)p;
    cudaGetSymbolAddress(&p, g_Up ); float* Up  = (float*)p;
    cudaGetSymbolAddress(&p, g_xrh); __nv_bfloat16* xrh = (__nv_bfloat16*)p;
    cudaGetSymbolAddress(&p, g_xrl); __nv_bfloat16* xrl = (__nv_bfloat16*)p;
    cudaGetSymbolAddress(&p, g_xth); __nv_bfloat16* xth = (__nv_bfloat16*)p;
    cudaGetSymbolAddress(&p, g_xtl); __nv_bfloat16* xtl = (__nv_bfloat16*)p;
    cudaGetSymbolAddress(&p, g_uth); __nv_bfloat16* uth = (__nv_bfloat16*)p;
    cudaGetSymbolAddress(&p, g_utl); __nv_bfloat16* utl = (__nv_bfloat16*)p;

    static bool attr_done = false;
    if (!attr_done) {
        cudaFuncSetAttribute(mmaT<true>,  cudaFuncAttributeMaxDynamicSharedMemorySize, MMA_SMEM);
        cudaFuncSetAttribute(mmaT<false>, cudaFuncAttributeMaxDynamicSharedMemorySize, MMA_SMEM);
        attr_done = true;
    }

    const long xB = (long)LL * DIN;      // 2097152
    const long GS = (long)DIN * DIN;     // 262144

    // 0-4) fused x splits (5 row-range pieces so launch #5 is the gram mma)
    sx4<<<dim3(16, 1376 / 32), dim3(32, 8)>>>(x, xrh, xrl, xth, xtl, 0, 0);
    sx4<<<dim3(16, 1376 / 32), dim3(32, 8)>>>(x, xrh, xrl, xth, xtl, 0, 1376);
    sx4<<<dim3(16, 1344 / 32), dim3(32, 8)>>>(x, xrh, xrl, xth, xtl, 0, 2752);
    sx4<<<dim3(16, 2048 / 32), dim3(32, 8)>>>(x, xrh, xrl, xth, xtl, 1, 0);
    sx4<<<dim3(16, 2048 / 32), dim3(32, 8)>>>(x, xrh, xrl, xth, xtl, 1, 2048);

    // 5) Gram partials (upper-triangular tiles only): 10 tiles x (b, ks=8)
    mmaT<true><<<dim3(10, 1, 16), 256, MMA_SMEM>>>(
        xth, xtl, xth, xtl, Gp,
        /*ldA=*/LL, /*ldB=*/LL, /*ldC=*/DIN, /*nChunk=*/16, /*d0=*/BB,
        /*aB=*/xB, /*bB=*/xB, /*cB=*/GS, /*cS=*/(long)BB * GS);

    // 6) G = sum_ks Gp, mirrored to full symmetric matrix
    reduceGsym<<<dim3(16, 16, BB), dim3(32, 8)>>>(Gp, G);

    // 7) T1 partials: T1p[ks][b] = Wkcat^T @ G[b] (K=128 per split)
    gemm128<true><<<dim3(4, 4, 8), 256>>>(Wk, G, T1p,
        128, DK, DIN, DIN, (long)DIN * DK,
        BB, 4,
        0, 128L * DK, 0,
        GS, 128L * DIN, 0,
        GS, BB * GS, 0);
    reduceP<<<512, 256>>>((const float4*)T1p, (float4*)T1, (BB * GS) / 4, 4);

    // 8) M partials + reduce
    gemmSmall<<<dim3(1, 1, 128), 256>>>(T1, Wv, Mp,
        DIN, DV, DV,
        HH, BB,
        64L * DIN, GS, 64,
        (long)DIN * DV, 0, 64L * DV,
        (long)DK * DV, (long)HH * DK * DV, (long)BB * HH * DK * DV);
    reduceP<<<64, 256>>>((const float4*)Mp, (float4*)M, (BB * HH * DK * DV) / 4, 8);

    // 9) T2cat[b][:, h*64:+64] = Wq[h] @ M[b][h]
    gemmSmall<<<dim3(1, 8, 16), 256>>>(Wq, M, T2,
        DK, DV, HH * DV,
        HH, BB,
        (long)DIN * DK, 0, 0,
        (long)DK * DV, (long)HH * DK * DV, 0,
        DV, (long)DIN * HH * DV, 0);

    // 10) U partials: Up[ks][b] = T2cat[b][:, ks-chunk] @ Wo_flat[ks-chunk, :]
    gemm128<false><<<dim3(4, 4, 8), 256>>>(T2, Wo, Up,
        128, HH * DV, DOUT, DOUT, 0,
        BB, 4,
        (long)DIN * HH * DV, 128, 0,
        0, 128L * DOUT, 0,
        GS, BB * GS, 0);

    // 11) fused: U = sum_ks Up, transpose + bf16 split -> uth/utl
    redUpSplitT<<<dim3(16, 16, BB), dim3(32, 8)>>>(Up, uth, utl);

    // 12) out = x @ U via mma.sync
    mmaT<false><<<dim3(4, 32, BB), 256, MMA_SMEM>>>(
        xrh, xrl, uth, utl, out,
        /*ldA=*/DIN, /*ldB=*/DIN, /*ldC=*/DOUT, /*nChunk=*/16, /*d0=*/BB,
        /*aB=*/xB, /*bB=*/(long)DOUT * DIN, /*cB=*/(long)LL * DOUT, /*cS=*/0);
}

// round 8
// speedup vs baseline: 1.8209x; 1.0358x over previous
#include <cuda_runtime.h>
#include <cuda_bf16.h>
#include <cstdint>

// Problem constants
#define BB   2
#define LL   4096
#define DIN  512
#define HH   8
#define DK   64
#define DV   64
#define DOUT 512

// ---------------------------------------------------------------------------
// Scratch (device globals)
// ---------------------------------------------------------------------------
__device__ float g_Gp [8 * BB * DIN * DIN];     // gram partials [ks][b] (upper tiles)
__device__ float g_G  [BB * DIN * DIN];         // G[b] full (mirrored)
__device__ float g_T1p[4 * BB * DIN * DIN];     // T1 partials [ks][b]
__device__ float g_Mp [8 * BB * HH * DK * DV];  // M partials [ks][b][h]
__device__ float g_T2 [BB * DIN * (HH * DV)];   // T2cat[b]
__device__ float g_Up [4 * BB * DIN * DOUT];    // U partials [ks][b]

// bf16 split buffers
__device__ __nv_bfloat16 g_xrh[BB * LL * DIN];  // x row-major hi
__device__ __nv_bfloat16 g_xrl[BB * LL * DIN];  // x row-major lo
__device__ __nv_bfloat16 g_xth[BB * DIN * LL];  // x^T hi  (channel-major)
__device__ __nv_bfloat16 g_xtl[BB * DIN * LL];  // x^T lo
__device__ __nv_bfloat16 g_uth[BB * DOUT * DIN];// U^T hi  (o-major)
__device__ __nv_bfloat16 g_utl[BB * DOUT * DIN];// U^T lo

// Upper-triangle tile map for 4x4 tile grid
__constant__ int c_tri_i[10] = {0,0,0,0,1,1,1,2,2,3};
__constant__ int c_tri_j[10] = {0,1,2,3,1,2,3,2,3,3};

// ---------------------------------------------------------------------------
// f32x2 helpers (SIMT mid-chain)
// ---------------------------------------------------------------------------
__device__ __forceinline__ unsigned long long pack2(float a) {
    unsigned long long r;
    asm("mov.b64 %0, {%1, %1};" : "=l"(r) : "f"(a));
    return r;
}
__device__ __forceinline__ void fma2(unsigned long long& acc,
                                     unsigned long long a,
                                     unsigned long long b) {
    asm("fma.rn.f32x2 %0, %1, %2, %0;" : "+l"(acc) : "l"(a), "l"(b));
}
__device__ __forceinline__ float lo32(unsigned long long v) {
    return __uint_as_float((unsigned)(v & 0xffffffffull));
}
__device__ __forceinline__ float hi32(unsigned long long v) {
    return __uint_as_float((unsigned)(v >> 32));
}

// ---------------------------------------------------------------------------
// helpers for mma.sync path
// ---------------------------------------------------------------------------
__device__ __forceinline__ uint32_t smem_u32(const void* p) {
    uint32_t a;
    asm("{ .reg .u64 t; cvta.to.shared.u64 t, %1; cvt.u32.u64 %0, t; }"
        : "=r"(a) : "l"(p));
    return a;
}
__device__ __forceinline__ void cp_async16(uint32_t dst, const void* src) {
    asm volatile("cp.async.cg.shared.global [%0], [%1], 16;" :: "r"(dst), "l"(src));
}
__device__ __forceinline__ uint32_t lds32(uint32_t addr) {
    uint32_t v;
    asm volatile("ld.shared.b32 %0, [%1];" : "=r"(v) : "r"(addr));
    return v;
}
__device__ __forceinline__ void mma16816(float* c, const uint32_t* a, const uint32_t* b) {
    asm volatile(
        "mma.sync.aligned.m16n8k16.row.col.f32.bf16.bf16.f32 "
        "{%0,%1,%2,%3}, {%4,%5,%6,%7}, {%8,%9}, {%0,%1,%2,%3};"
        : "+f"(c[0]), "+f"(c[1]), "+f"(c[2]), "+f"(c[3])
        : "r"(a[0]), "r"(a[1]), "r"(a[2]), "r"(a[3]), "r"(b[0]), "r"(b[1]));
}

// ---------------------------------------------------------------------------
// mmaT: C[128x128 tile] fp32 = split-bf16 A(M rows,K) @ B(N rows,K)^T
// ---------------------------------------------------------------------------
#define ROWB   80
#define MATB   (128 * ROWB)
#define BUFB   (4 * MATB)
#define MMA_SMEM (2 * BUFB)

template <bool TRI>
__global__ void __launch_bounds__(256)
mmaT(const __nv_bfloat16* __restrict__ Ahi, const __nv_bfloat16* __restrict__ Alo,
     const __nv_bfloat16* __restrict__ Bhi, const __nv_bfloat16* __restrict__ Blo,
     float* __restrict__ C,
     int ldA, int ldB, int ldC, int nChunk, int d0,
     long aB, long bB, long cB, long cS)
{
    extern __shared__ char sm[];
    const uint32_t su = smem_u32(sm);

    const int t    = threadIdx.x;
    const int wid  = t >> 5;
    const int lane = t & 31;
    const int g    = lane >> 2;
    const int tq   = lane & 3;
    const int wm   = wid & 1;
    const int wn   = wid >> 1;

    const int z  = blockIdx.z;
    const int z0 = z % d0;
    const int z1 = z / d0;
    const long kOff = (long)z1 * nChunk * 32;

    long m0, n0;
    if (TRI) {
        m0 = (long)c_tri_i[blockIdx.x] * 128;
        n0 = (long)c_tri_j[blockIdx.x] * 128;
    } else {
        m0 = (long)blockIdx.y * 128;
        n0 = (long)blockIdx.x * 128;
    }

    const __nv_bfloat16* bAh = Ahi + (long)z0 * aB + kOff + m0 * ldA;
    const __nv_bfloat16* bAl = Alo + (long)z0 * aB + kOff + m0 * ldA;
    const __nv_bfloat16* bBh = Bhi + (long)z0 * bB + kOff + n0 * ldB;
    const __nv_bfloat16* bBl = Blo + (long)z0 * bB + kOff + n0 * ldB;
    C += (long)z0 * cB + (long)z1 * cS;

    const int r0 = t >> 2,        s0 = (t & 3) * 16;
    const int r1 = (t + 256) >> 2, s1 = ((t + 256) & 3) * 16;

    float acc[4][4][4];
#pragma unroll
    for (int i = 0; i < 4; i++)
#pragma unroll
        for (int j = 0; j < 4; j++)
#pragma unroll
            for (int k = 0; k < 4; k++) acc[i][j][k] = 0.f;

#define LOAD_CHUNK(cidx, buf)                                                   \
    do {                                                                        \
        const uint32_t sb_ = su + (buf) * BUFB;                                 \
        const long ko_ = (long)(cidx) * 32;                                     \
        cp_async16(sb_ + 0 * MATB + r0 * ROWB + s0, bAh + (long)r0 * ldA + ko_ + s0 / 2); \
        cp_async16(sb_ + 0 * MATB + r1 * ROWB + s1, bAh + (long)r1 * ldA + ko_ + s1 / 2); \
        cp_async16(sb_ + 1 * MATB + r0 * ROWB + s0, bAl + (long)r0 * ldA + ko_ + s0 / 2); \
        cp_async16(sb_ + 1 * MATB + r1 * ROWB + s1, bAl + (long)r1 * ldA + ko_ + s1 / 2); \
        cp_async16(sb_ + 2 * MATB + r0 * ROWB + s0, bBh + (long)r0 * ldB + ko_ + s0 / 2); \
        cp_async16(sb_ + 2 * MATB + r1 * ROWB + s1, bBh + (long)r1 * ldB + ko_ + s1 / 2); \
        cp_async16(sb_ + 3 * MATB + r0 * ROWB + s0, bBl + (long)r0 * ldB + ko_ + s0 / 2); \
        cp_async16(sb_ + 3 * MATB + r1 * ROWB + s1, bBl + (long)r1 * ldB + ko_ + s1 / 2); \
        asm volatile("cp.async.commit_group;" ::: "memory");                    \
    } while (0)

    LOAD_CHUNK(0, 0);

    for (int c = 0; c < nChunk; c++) {
        const int buf = c & 1;
        if (c + 1 < nChunk) {
            LOAD_CHUNK(c + 1, buf ^ 1);
            asm volatile("cp.async.wait_group 1;" ::: "memory");
        } else {
            asm volatile("cp.async.wait_group 0;" ::: "memory");
        }
        __syncthreads();

        const uint32_t sb = su + buf * BUFB;
#pragma unroll
        for (int s = 0; s < 2; s++) {
            const uint32_t kb = s * 32 + tq * 4;
            uint32_t ah[4][4], al[4][4], bh[4][2], bl[4][2];
#pragma unroll
            for (int mt = 0; mt < 4; mt++) {
                const uint32_t ra = (uint32_t)(wm * 64 + mt * 16 + g) * ROWB + kb;
                ah[mt][0] = lds32(sb + ra);
                ah[mt][1] = lds32(sb + ra + 8 * ROWB);
                ah[mt][2] = lds32(sb + ra + 16);
                ah[mt][3] = lds32(sb + ra + 8 * ROWB + 16);
                al[mt][0] = lds32(sb + MATB + ra);
                al[mt][1] = lds32(sb + MATB + ra + 8 * ROWB);
                al[mt][2] = lds32(sb + MATB + ra + 16);
                al[mt][3] = lds32(sb + MATB + ra + 8 * ROWB + 16);
            }
#pragma unroll
            for (int nt = 0; nt < 4; nt++) {
                const uint32_t rb = (uint32_t)(wn * 32 + nt * 8 + g) * ROWB + kb;
                bh[nt][0] = lds32(sb + 2 * MATB + rb);
                bh[nt][1] = lds32(sb + 2 * MATB + rb + 16);
                bl[nt][0] = lds32(sb + 3 * MATB + rb);
                bl[nt][1] = lds32(sb + 3 * MATB + rb + 16);
            }
#pragma unroll
            for (int mt = 0; mt < 4; mt++)
#pragma unroll
                for (int nt = 0; nt < 4; nt++) {
                    mma16816(acc[mt][nt], ah[mt], bh[nt]);
                    mma16816(acc[mt][nt], ah[mt], bl[nt]);
                    mma16816(acc[mt][nt], al[mt], bh[nt]);
                }
        }
        __syncthreads();
    }

#pragma unroll
    for (int mt = 0; mt < 4; mt++) {
#pragma unroll
        for (int nt = 0; nt < 4; nt++) {
            const long row = m0 + wm * 64 + mt * 16 + g;
            const long col = n0 + wn * 32 + nt * 8 + 2 * tq;
            float2 v0 = make_float2(acc[mt][nt][0], acc[mt][nt][1]);
            float2 v1 = make_float2(acc[mt][nt][2], acc[mt][nt][3]);
            *(float2*)&C[row * ldC + col]       = v0;
            *(float2*)&C[(row + 8) * ldC + col] = v1;
        }
    }
}

// ---------------------------------------------------------------------------
// sx4: fused row-split + transpose-split of x, full tensor in one launch.
// grid (DIN/32, LL/32, BB), block (32, 8)
// ---------------------------------------------------------------------------
__global__ void __launch_bounds__(256)
sx4(const float* __restrict__ x,
    __nv_bfloat16* __restrict__ xrh, __nv_bfloat16* __restrict__ xrl,
    __nv_bfloat16* __restrict__ xth, __nv_bfloat16* __restrict__ xtl)
{
    __shared__ float tl[32][33];
    const int b = blockIdx.z;
    const long xoff = (long)b * LL * DIN;
    const int c0 = blockIdx.x * 32;
    const int r0 = blockIdx.y * 32;
    const int tx = threadIdx.x, ty = threadIdx.y;
#pragma unroll
    for (int i = 0; i < 4; i++) {
        const int r = r0 + ty + 8 * i;
        const long o = xoff + (long)r * DIN + c0 + tx;
        const float v = x[o];
        tl[ty + 8 * i][tx] = v;
        const __nv_bfloat16 h = __float2bfloat16(v);
        const __nv_bfloat16 l = __float2bfloat16(v - __bfloat162float(h));
        xrh[o] = h;
        xrl[o] = l;
    }
    __syncthreads();
#pragma unroll
    for (int i = 0; i < 4; i++) {
        const float v = tl[tx][ty + 8 * i];
        const __nv_bfloat16 h = __float2bfloat16(v);
        const __nv_bfloat16 l = __float2bfloat16(v - __bfloat162float(h));
        const long o = xoff + (long)(c0 + ty + 8 * i) * LL + r0 + tx;
        xth[o] = h;
        xtl[o] = l;
    }
}

// ---------------------------------------------------------------------------
// reduceGsym: sum 8 gram partials (valid on upper 128-tiles) into full G.
// ---------------------------------------------------------------------------
__global__ void __launch_bounds__(256)
reduceGsym(const float* __restrict__ Gp, float* __restrict__ G)
{
    __shared__ float s[32][33];
    const int b  = blockIdx.z;
    const int j0 = blockIdx.x * 32, i0 = blockIdx.y * 32;
    const int tx = threadIdx.x, ty = threadIdx.y;
    const long base = (long)b * DIN * DIN;
    const long PS   = (long)BB * DIN * DIN;

    if ((i0 >> 7) <= (j0 >> 7)) {
#pragma unroll
        for (int i = 0; i < 4; i++) {
            const int r = i0 + ty + 8 * i;
            float sum = 0.f;
#pragma unroll
            for (int p = 0; p < 8; p++)
                sum += Gp[(long)p * PS + base + (long)r * DIN + j0 + tx];
            G[base + (long)r * DIN + j0 + tx] = sum;
        }
    } else {
#pragma unroll
        for (int i = 0; i < 4; i++) {
            const int r = j0 + ty + 8 * i;
            float sum = 0.f;
#pragma unroll
            for (int p = 0; p < 8; p++)
                sum += Gp[(long)p * PS + base + (long)r * DIN + i0 + tx];
            s[ty + 8 * i][tx] = sum;
        }
        __syncthreads();
#pragma unroll
        for (int i = 0; i < 4; i++)
            G[base + (long)(i0 + ty + 8 * i) * DIN + j0 + tx] = s[tx][ty + 8 * i];
    }
}

// ---------------------------------------------------------------------------
// redUpSplitT: sum 4 U partials, transpose, bf16-split -> uth/utl.
// ---------------------------------------------------------------------------
__global__ void __launch_bounds__(256)
redUpSplitT(const float* __restrict__ Up,
            __nv_bfloat16* __restrict__ oh, __nv_bfloat16* __restrict__ ol)
{
    __shared__ float tl[32][33];
    const int b  = blockIdx.z;
    const int c0 = blockIdx.x * 32, r0 = blockIdx.y * 32;
    const int tx = threadIdx.x, ty = threadIdx.y;
    const long base = (long)b * DIN * DOUT;
    const long PS   = (long)BB * DIN * DOUT;
#pragma unroll
    for (int i = 0; i < 4; i++) {
        const int r = r0 + ty + 8 * i;
        float sum = 0.f;
#pragma unroll
        for (int p = 0; p < 4; p++)
            sum += Up[(long)p * PS + base + (long)r * DOUT + c0 + tx];
        tl[ty + 8 * i][tx] = sum;
    }
    __syncthreads();
#pragma unroll
    for (int i = 0; i < 4; i++) {
        const float v = tl[tx][ty + 8 * i];
        const __nv_bfloat16 h = __float2bfloat16(v);
        const __nv_bfloat16 l = __float2bfloat16(v - __bfloat162float(h));
        const long o = base + (long)(c0 + ty + 8 * i) * DIN + r0 + tx;
        oh[o] = h;
        ol[o] = l;
    }
}

// ---------------------------------------------------------------------------
// SIMT mid-chain kernels
// ---------------------------------------------------------------------------
template <bool TA>
__global__ void __launch_bounds__(256)
gemm128(const float* __restrict__ A, const float* __restrict__ B,
        float* __restrict__ C,
        int K, int lda, int ldb, int ldc, long a_hs,
        int d0, int d1,
        long a0, long a1, long a2,
        long b0, long b1, long b2,
        long c0, long c1, long c2)
{
    __shared__ __align__(16) float As[2][16 * 128];
    __shared__ __align__(16) float Bs[2][16 * 128];

    const int t  = threadIdx.x;
    const int tx = t & 15;
    const int ty = t >> 4;

    {
        const int z  = blockIdx.z;
        const int z0 = z % d0;
        const int zr = z / d0;
        const int z1 = zr % d1;
        const int z2 = zr / d1;
        A += (long)z0 * a0 + (long)z1 * a1 + (long)z2 * a2;
        B += (long)z0 * b0 + (long)z1 * b1 + (long)z2 * b2;
        C += (long)z0 * c0 + (long)z1 * c1 + (long)z2 * c2;
    }

    const long m0 = (long)blockIdx.y * 128;
    const long n0 = (long)blockIdx.x * 128;

    const float* Ag;
    if (TA) {
        const long mm = m0 + (t & 15) * 8;
        Ag = A + ((mm >> 6) * a_hs + (mm & 63)) + (long)(t >> 4) * lda;
    } else {
        Ag = A + (m0 + (t >> 1)) * lda + (t & 1) * 8;
    }
    const float* Bg = B + (long)(t >> 4) * ldb + n0 + (t & 15) * 8;

    unsigned long long acc[8][4];
#pragma unroll
    for (int i = 0; i < 8; i++)
#pragma unroll
        for (int j = 0; j < 4; j++) acc[i][j] = 0ull;

    const int ktiles = K / 16;

    float4 ra0 = *(const float4*)(Ag);
    float4 ra1 = *(const float4*)(Ag + 4);
    float4 rb0 = *(const float4*)(Bg);
    float4 rb1 = *(const float4*)(Bg + 4);

    if (TA) {
        *(float4*)&As[0][(t >> 4) * 128 + (t & 15) * 8]     = ra0;
        *(float4*)&As[0][(t >> 4) * 128 + (t & 15) * 8 + 4] = ra1;
    } else {
        const int m = t >> 1, ks = (t & 1) * 8;
        As[0][(ks + 0) * 128 + m] = ra0.x;
        As[0][(ks + 1) * 128 + m] = ra0.y;
        As[0][(ks + 2) * 128 + m] = ra0.z;
        As[0][(ks + 3) * 128 + m] = ra0.w;
        As[0][(ks + 4) * 128 + m] = ra1.x;
        As[0][(ks + 5) * 128 + m] = ra1.y;
        As[0][(ks + 6) * 128 + m] = ra1.z;
        As[0][(ks + 7) * 128 + m] = ra1.w;
    }
    *(float4*)&Bs[0][(t >> 4) * 128 + (t & 15) * 8]     = rb0;
    *(float4*)&Bs[0][(t >> 4) * 128 + (t & 15) * 8 + 4] = rb1;
    __syncthreads();

    for (int kt = 0; kt < ktiles; kt++) {
        const int cur = kt & 1;
        const bool more = (kt + 1 < ktiles);
        if (more) {
            Ag += TA ? 16 * lda : 16;
            Bg += 16 * ldb;
            ra0 = *(const float4*)(Ag);
            ra1 = *(const float4*)(Ag + 4);
            rb0 = *(const float4*)(Bg);
            rb1 = *(const float4*)(Bg + 4);
        }

#pragma unroll
        for (int kk = 0; kk < 16; kk++) {
            const float4 av0 = *(const float4*)&As[cur][kk * 128 + ty * 8];
            const float4 av1 = *(const float4*)&As[cur][kk * 128 + ty * 8 + 4];
            const ulonglong2 bv0 = *(const ulonglong2*)&Bs[cur][kk * 128 + tx * 8];
            const ulonglong2 bv1 = *(const ulonglong2*)&Bs[cur][kk * 128 + tx * 8 + 4];
            const unsigned long long bb0 = bv0.x, bb1 = bv0.y, bb2 = bv1.x, bb3 = bv1.y;
            unsigned long long p;
            p = pack2(av0.x); fma2(acc[0][0], p, bb0); fma2(acc[0][1], p, bb1); fma2(acc[0][2], p, bb2); fma2(acc[0][3], p, bb3);
            p = pack2(av0.y); fma2(acc[1][0], p, bb0); fma2(acc[1][1], p, bb1); fma2(acc[1][2], p, bb2); fma2(acc[1][3], p, bb3);
            p = pack2(av0.z); fma2(acc[2][0], p, bb0); fma2(acc[2][1], p, bb1); fma2(acc[2][2], p, bb2); fma2(acc[2][3], p, bb3);
            p = pack2(av0.w); fma2(acc[3][0], p, bb0); fma2(acc[3][1], p, bb1); fma2(acc[3][2], p, bb2); fma2(acc[3][3], p, bb3);
            p = pack2(av1.x); fma2(acc[4][0], p, bb0); fma2(acc[4][1], p, bb1); fma2(acc[4][2], p, bb2); fma2(acc[4][3], p, bb3);
            p = pack2(av1.y); fma2(acc[5][0], p, bb0); fma2(acc[5][1], p, bb1); fma2(acc[5][2], p, bb2); fma2(acc[5][3], p, bb3);
            p = pack2(av1.z); fma2(acc[6][0], p, bb0); fma2(acc[6][1], p, bb1); fma2(acc[6][2], p, bb2); fma2(acc[6][3], p, bb3);
            p = pack2(av1.w); fma2(acc[7][0], p, bb0); fma2(acc[7][1], p, bb1); fma2(acc[7][2], p, bb2); fma2(acc[7][3], p, bb3);
        }

        if (more) {
            const int nxt = cur ^ 1;
            if (TA) {
                *(float4*)&As[nxt][(t >> 4) * 128 + (t & 15) * 8]     = ra0;
                *(float4*)&As[nxt][(t >> 4) * 128 + (t & 15) * 8 + 4] = ra1;
            } else {
                const int m = t >> 1, ks = (t & 1) * 8;
                As[nxt][(ks + 0) * 128 + m] = ra0.x;
                As[nxt][(ks + 1) * 128 + m] = ra0.y;
                As[nxt][(ks + 2) * 128 + m] = ra0.z;
                As[nxt][(ks + 3) * 128 + m] = ra0.w;
                As[nxt][(ks + 4) * 128 + m] = ra1.x;
                As[nxt][(ks + 5) * 128 + m] = ra1.y;
                As[nxt][(ks + 6) * 128 + m] = ra1.z;
                As[nxt][(ks + 7) * 128 + m] = ra1.w;
            }
            *(float4*)&Bs[nxt][(t >> 4) * 128 + (t & 15) * 8]     = rb0;
            *(float4*)&Bs[nxt][(t >> 4) * 128 + (t & 15) * 8 + 4] = rb1;
        }
        __syncthreads();
    }

#pragma unroll
    for (int i = 0; i < 8; i++) {
        float4 o0, o1;
        o0.x = lo32(acc[i][0]); o0.y = hi32(acc[i][0]);
        o0.z = lo32(acc[i][1]); o0.w = hi32(acc[i][1]);
        o1.x = lo32(acc[i][2]); o1.y = hi32(acc[i][2]);
        o1.z = lo32(acc[i][3]); o1.w = hi32(acc[i][3]);
        float* cp = C + (m0 + ty * 8 + i) * ldc + n0 + tx * 8;
        *(float4*)(cp)     = o0;
        *(float4*)(cp + 4) = o1;
    }
}

// gemmSmall with partial-sum fusion: A summed over NPA partials (stride pSA),
// B summed over NPB partials (stride pSB), during smem staging.
template <int NPA, int NPB>
__global__ void __launch_bounds__(256)
gemmSmall(const float* __restrict__ A, const float* __restrict__ B,
          float* __restrict__ C,
          int lda, int ldb, int ldc,
          int d0, int d1,
          long a0, long a1, long a2,
          long b0, long b1, long b2,
          long c0, long c1, long c2,
          long pSA, long pSB)
{
    __shared__ __align__(16) float As[64 * 68];
    __shared__ __align__(16) float Bs[64 * 64];

    const int t  = threadIdx.x;
    const int tx = t & 15;
    const int ty = t >> 4;

    {
        const int z  = blockIdx.z;
        const int z0 = z % d0;
        const int zr = z / d0;
        const int z1 = zr % d1;
        const int z2 = zr / d1;
        A += (long)z0 * a0 + (long)z1 * a1 + (long)z2 * a2;
        B += (long)z0 * b0 + (long)z1 * b1 + (long)z2 * b2;
        C += (long)z0 * c0 + (long)z1 * c1 + (long)z2 * c2;
    }
    const long m0 = (long)blockIdx.y * 64;

    {
        const int m = t >> 2, kseg = (t & 3) * 16;
        const float* Ag = A + (m0 + m) * lda + kseg;
#pragma unroll
        for (int s = 0; s < 4; s++) {
            float4 v = *(const float4*)(Ag + s * 4);
#pragma unroll
            for (int pp = 1; pp < NPA; pp++) {
                const float4 w = *(const float4*)(Ag + (long)pp * pSA + s * 4);
                v.x += w.x; v.y += w.y; v.z += w.z; v.w += w.w;
            }
            *(float4*)&As[m * 68 + kseg + s * 4] = v;
        }
    }
    {
        const int r = t >> 2, cs = (t & 3) * 16;
        const float* Bg = B + (long)r * ldb + cs;
#pragma unroll
        for (int s = 0; s < 4; s++) {
            float4 v = *(const float4*)(Bg + s * 4);
#pragma unroll
            for (int pp = 1; pp < NPB; pp++) {
                const float4 w = *(const float4*)(Bg + (long)pp * pSB + s * 4);
                v.x += w.x; v.y += w.y; v.z += w.z; v.w += w.w;
            }
            *(float4*)&Bs[r * 64 + cs + s * 4] = v;
        }
    }
    __syncthreads();

    unsigned long long acc[4][2];
#pragma unroll
    for (int i = 0; i < 4; i++) { acc[i][0] = 0ull; acc[i][1] = 0ull; }

#pragma unroll 8
    for (int kk = 0; kk < 64; kk++) {
        const ulonglong2 bv = *(const ulonglong2*)&Bs[kk * 64 + tx * 4];
        const unsigned long long bb0 = bv.x, bb1 = bv.y;
        unsigned long long p;
        p = pack2(As[(ty * 4 + 0) * 68 + kk]); fma2(acc[0][0], p, bb0); fma2(acc[0][1], p, bb1);
        p = pack2(As[(ty * 4 + 1) * 68 + kk]); fma2(acc[1][0], p, bb0); fma2(acc[1][1], p, bb1);
        p = pack2(As[(ty * 4 + 2) * 68 + kk]); fma2(acc[2][0], p, bb0); fma2(acc[2][1], p, bb1);
        p = pack2(As[(ty * 4 + 3) * 68 + kk]); fma2(acc[3][0], p, bb0); fma2(acc[3][1], p, bb1);
    }

#pragma unroll
    for (int i = 0; i < 4; i++) {
        float4 o;
        o.x = lo32(acc[i][0]); o.y = hi32(acc[i][0]);
        o.z = lo32(acc[i][1]); o.w = hi32(acc[i][1]);
        *(float4*)&C[(m0 + ty * 4 + i) * ldc + tx * 4] = o;
    }
}

// ---------------------------------------------------------------------------
// kernel_launch: 9 launches
// ---------------------------------------------------------------------------
extern "C" void kernel_launch(void* const* d_in, const int* in_sizes, int n_in,
                              void* d_out, int out_size)
{
    (void)in_sizes; (void)n_in; (void)out_size;
    const float* x  = (const float*)d_in[0];
    const float* Wq = (const float*)d_in[1];
    const float* Wk = (const float*)d_in[2];
    const float* Wv = (const float*)d_in[3];
    const float* Wo = (const float*)d_in[4];
    float* out = (float*)d_out;

    void* p;
    cudaGetSymbolAddress(&p, g_Gp ); float* Gp  = (float*)p;
    cudaGetSymbolAddress(&p, g_G  ); float* G   = (float*)p;
    cudaGetSymbolAddress(&p, g_T1p); float* T1p = (float*)p;
    cudaGetSymbolAddress(&p, g_Mp ); float* Mp  = (float*)p;
    cudaGetSymbolAddress(&p, g_T2 ); float* T2  = (float*)p;
    cudaGetSymbolAddress(&p, g_Up ); float* Up  = (float*)p;
    cudaGetSymbolAddress(&p, g_xrh); __nv_bfloat16* xrh = (__nv_bfloat16*)p;
    cudaGetSymbolAddress(&p, g_xrl); __nv_bfloat16* xrl = (__nv_bfloat16*)p;
    cudaGetSymbolAddress(&p, g_xth); __nv_bfloat16* xth = (__nv_bfloat16*)p;
    cudaGetSymbolAddress(&p, g_xtl); __nv_bfloat16* xtl = (__nv_bfloat16*)p;
    cudaGetSymbolAddress(&p, g_uth); __nv_bfloat16* uth = (__nv_bfloat16*)p;
    cudaGetSymbolAddress(&p, g_utl); __nv_bfloat16* utl = (__nv_bfloat16*)p;

    static bool attr_done = false;
    if (!attr_done) {
        cudaFuncSetAttribute(mmaT<true>,  cudaFuncAttributeMaxDynamicSharedMemorySize, MMA_SMEM);
        cudaFuncSetAttribute(mmaT<false>, cudaFuncAttributeMaxDynamicSharedMemorySize, MMA_SMEM);
        attr_done = true;
    }

    const long xB = (long)LL * DIN;      // 2097152
    const long GS = (long)DIN * DIN;     // 262144

    // 1) fused x splits, one launch
    sx4<<<dim3(16, 128, BB), dim3(32, 8)>>>(x, xrh, xrl, xth, xtl);

    // 2) Gram partials (upper-triangular tiles): 10 tiles x (b, ks=8)
    mmaT<true><<<dim3(10, 1, 16), 256, MMA_SMEM>>>(
        xth, xtl, xth, xtl, Gp,
        LL, LL, DIN, /*nChunk=*/16, /*d0=*/BB,
        xB, xB, GS, (long)BB * GS);

    // 3) G = sum_ks Gp, mirrored to full symmetric matrix
    reduceGsym<<<dim3(16, 16, BB), dim3(32, 8)>>>(Gp, G);

    // 4) T1 partials: T1p[ks][b] = Wkcat^T @ G[b] (K=128 per split)
    gemm128<true><<<dim3(4, 4, 8), 256>>>(Wk, G, T1p,
        128, DK, DIN, DIN, (long)DIN * DK,
        BB, 4,
        0, 128L * DK, 0,
        GS, 128L * DIN, 0,
        GS, BB * GS, 0);

    // 5) M partials: Mp[ks][b][h] = (sum_p T1p)[b][h-rows, ks-chunk] @ Wv[h][ks-chunk]
    //    A-partials summed in staging (NPA=4)
    gemmSmall<4, 1><<<dim3(1, 1, 128), 256>>>(T1p, Wv, Mp,
        DIN, DV, DV,
        HH, BB,
        64L * DIN, GS, 64,
        (long)DIN * DV, 0, 64L * DV,
        (long)DK * DV, (long)HH * DK * DV, (long)BB * HH * DK * DV,
        /*pSA=*/(long)BB * GS, /*pSB=*/0);

    // 6) T2cat[b][:, h*64:+64] = Wq[h] @ (sum_p Mp)[b][h]  (NPB=8)
    gemmSmall<1, 8><<<dim3(1, 8, 16), 256>>>(Wq, Mp, T2,
        DK, DV, HH * DV,
        HH, BB,
        (long)DIN * DK, 0, 0,
        (long)DK * DV, (long)HH * DK * DV, 0,
        DV, (long)DIN * HH * DV, 0,
        /*pSA=*/0, /*pSB=*/(long)BB * HH * DK * DV);

    // 7) U partials: Up[ks][b] = T2cat[b][:, ks-chunk] @ Wo_flat[ks-chunk, :]
    gemm128<false><<<dim3(4, 4, 8), 256>>>(T2, Wo, Up,
        128, HH * DV, DOUT, DOUT, 0,
        BB, 4,
        (long)DIN * HH * DV, 128, 0,
        0, 128L * DOUT, 0,
        GS, BB * GS, 0);

    // 8) fused: U = sum_ks Up, transpose + bf16 split -> uth/utl
    redUpSplitT<<<dim3(16, 16, BB), dim3(32, 8)>>>(Up, uth, utl);

    // 9) out = x @ U via mma.sync
    mmaT<false><<<dim3(4, 32, BB), 256, MMA_SMEM>>>(
        xrh, xrl, uth, utl, out,
        DIN, DIN, DOUT, /*nChunk=*/16, /*d0=*/BB,
        xB, (long)DOUT * DIN, (long)LL * DOUT, 0);
}

// round 9
// speedup vs baseline: 2.0015x; 1.0992x over previous
#include <cuda_runtime.h>
#include <cuda_bf16.h>
#include <cstdint>

// Problem constants
#define BB   2
#define LL   4096
#define DIN  512
#define HH   8
#define DK   64
#define DV   64
#define DOUT 512

// ---------------------------------------------------------------------------
// Scratch (device globals)
// ---------------------------------------------------------------------------
__device__ float g_Gp [8 * BB * DIN * DIN];     // gram partials [ks][b] (upper tiles)
__device__ float g_T1p[4 * BB * DIN * DIN];     // T1 partials [ks][b]
__device__ float g_Mp [8 * BB * HH * DK * DV];  // M partials [ks][b][h]
__device__ float g_Utp[4 * BB * DOUT * DIN];    // U^T partials [ks][b]

// bf16 split buffers
__device__ __nv_bfloat16 g_xrh[BB * LL * DIN];   // x row-major hi
__device__ __nv_bfloat16 g_xrl[BB * LL * DIN];   // x row-major lo
__device__ __nv_bfloat16 g_xth[BB * DIN * LL];   // x^T hi
__device__ __nv_bfloat16 g_xtl[BB * DIN * LL];   // x^T lo
__device__ __nv_bfloat16 g_Gh [BB * DIN * DIN];  // G hi (symmetric)
__device__ __nv_bfloat16 g_Gl [BB * DIN * DIN];  // G lo
__device__ __nv_bfloat16 g_wkth[DIN * DIN];      // Wkcat^T hi : [i=(h,dk)][k]
__device__ __nv_bfloat16 g_wktl[DIN * DIN];
__device__ __nv_bfloat16 g_woth[DOUT * (HH*DV)]; // Wo^T hi : [o][v]
__device__ __nv_bfloat16 g_wotl[DOUT * (HH*DV)];
__device__ __nv_bfloat16 g_t2h[BB * DIN * (HH * DV)]; // T2cat hi
__device__ __nv_bfloat16 g_t2l[BB * DIN * (HH * DV)]; // T2cat lo
__device__ __nv_bfloat16 g_uth[BB * DOUT * DIN]; // U^T hi
__device__ __nv_bfloat16 g_utl[BB * DOUT * DIN]; // U^T lo

// Upper-triangle tile map for 4x4 tile grid
__constant__ int c_tri_i[10] = {0,0,0,0,1,1,1,2,2,3};
__constant__ int c_tri_j[10] = {0,1,2,3,1,2,3,2,3,3};

// ---------------------------------------------------------------------------
// f32x2 helpers (SIMT small GEMMs)
// ---------------------------------------------------------------------------
__device__ __forceinline__ unsigned long long pack2(float a) {
    unsigned long long r;
    asm("mov.b64 %0, {%1, %1};" : "=l"(r) : "f"(a));
    return r;
}
__device__ __forceinline__ void fma2(unsigned long long& acc,
                                     unsigned long long a,
                                     unsigned long long b) {
    asm("fma.rn.f32x2 %0, %1, %2, %0;" : "+l"(acc) : "l"(a), "l"(b));
}
__device__ __forceinline__ float lo32(unsigned long long v) {
    return __uint_as_float((unsigned)(v & 0xffffffffull));
}
__device__ __forceinline__ float hi32(unsigned long long v) {
    return __uint_as_float((unsigned)(v >> 32));
}
__device__ __forceinline__ unsigned short bfbits(__nv_bfloat16 h) {
    return ((__nv_bfloat16_raw)h).x;
}

// ---------------------------------------------------------------------------
// helpers for mma.sync path
// ---------------------------------------------------------------------------
__device__ __forceinline__ uint32_t smem_u32(const void* p) {
    uint32_t a;
    asm("{ .reg .u64 t; cvta.to.shared.u64 t, %1; cvt.u32.u64 %0, t; }"
        : "=r"(a) : "l"(p));
    return a;
}
__device__ __forceinline__ void cp_async16(uint32_t dst, const void* src) {
    asm volatile("cp.async.cg.shared.global [%0], [%1], 16;" :: "r"(dst), "l"(src));
}
__device__ __forceinline__ uint32_t lds32(uint32_t addr) {
    uint32_t v;
    asm volatile("ld.shared.b32 %0, [%1];" : "=r"(v) : "r"(addr));
    return v;
}
__device__ __forceinline__ void mma16816(float* c, const uint32_t* a, const uint32_t* b) {
    asm volatile(
        "mma.sync.aligned.m16n8k16.row.col.f32.bf16.bf16.f32 "
        "{%0,%1,%2,%3}, {%4,%5,%6,%7}, {%8,%9}, {%0,%1,%2,%3};"
        : "+f"(c[0]), "+f"(c[1]), "+f"(c[2]), "+f"(c[3])
        : "r"(a[0]), "r"(a[1]), "r"(a[2]), "r"(a[3]), "r"(b[0]), "r"(b[1]));
}

// ---------------------------------------------------------------------------
// mmaT: C[128x128 tile] fp32 = split-bf16 A(M rows,K) @ B(N rows,K)^T
// ---------------------------------------------------------------------------
#define ROWB   80
#define MATB   (128 * ROWB)
#define BUFB   (4 * MATB)
#define MMA_SMEM (2 * BUFB)

template <bool TRI>
__global__ void __launch_bounds__(256)
mmaT(const __nv_bfloat16* __restrict__ Ahi, const __nv_bfloat16* __restrict__ Alo,
     const __nv_bfloat16* __restrict__ Bhi, const __nv_bfloat16* __restrict__ Blo,
     float* __restrict__ C,
     int ldA, int ldB, int ldC, int nChunk, int d0,
     long aB, long bB, long cB, long cS)
{
    extern __shared__ char sm[];
    const uint32_t su = smem_u32(sm);

    const int t    = threadIdx.x;
    const int wid  = t >> 5;
    const int lane = t & 31;
    const int g    = lane >> 2;
    const int tq   = lane & 3;
    const int wm   = wid & 1;
    const int wn   = wid >> 1;

    const int z  = blockIdx.z;
    const int z0 = z % d0;
    const int z1 = z / d0;
    const long kOff = (long)z1 * nChunk * 32;

    long m0, n0;
    if (TRI) {
        m0 = (long)c_tri_i[blockIdx.x] * 128;
        n0 = (long)c_tri_j[blockIdx.x] * 128;
    } else {
        m0 = (long)blockIdx.y * 128;
        n0 = (long)blockIdx.x * 128;
    }

    const __nv_bfloat16* bAh = Ahi + (long)z0 * aB + kOff + m0 * ldA;
    const __nv_bfloat16* bAl = Alo + (long)z0 * aB + kOff + m0 * ldA;
    const __nv_bfloat16* bBh = Bhi + (long)z0 * bB + kOff + n0 * ldB;
    const __nv_bfloat16* bBl = Blo + (long)z0 * bB + kOff + n0 * ldB;
    C += (long)z0 * cB + (long)z1 * cS;

    const int r0 = t >> 2,        s0 = (t & 3) * 16;
    const int r1 = (t + 256) >> 2, s1 = ((t + 256) & 3) * 16;

    float acc[4][4][4];
#pragma unroll
    for (int i = 0; i < 4; i++)
#pragma unroll
        for (int j = 0; j < 4; j++)
#pragma unroll
            for (int k = 0; k < 4; k++) acc[i][j][k] = 0.f;

#define LOAD_CHUNK(cidx, buf)                                                   \
    do {                                                                        \
        const uint32_t sb_ = su + (buf) * BUFB;                                 \
        const long ko_ = (long)(cidx) * 32;                                     \
        cp_async16(sb_ + 0 * MATB + r0 * ROWB + s0, bAh + (long)r0 * ldA + ko_ + s0 / 2); \
        cp_async16(sb_ + 0 * MATB + r1 * ROWB + s1, bAh + (long)r1 * ldA + ko_ + s1 / 2); \
        cp_async16(sb_ + 1 * MATB + r0 * ROWB + s0, bAl + (long)r0 * ldA + ko_ + s0 / 2); \
        cp_async16(sb_ + 1 * MATB + r1 * ROWB + s1, bAl + (long)r1 * ldA + ko_ + s1 / 2); \
        cp_async16(sb_ + 2 * MATB + r0 * ROWB + s0, bBh + (long)r0 * ldB + ko_ + s0 / 2); \
        cp_async16(sb_ + 2 * MATB + r1 * ROWB + s1, bBh + (long)r1 * ldB + ko_ + s1 / 2); \
        cp_async16(sb_ + 3 * MATB + r0 * ROWB + s0, bBl + (long)r0 * ldB + ko_ + s0 / 2); \
        cp_async16(sb_ + 3 * MATB + r1 * ROWB + s1, bBl + (long)r1 * ldB + ko_ + s1 / 2); \
        asm volatile("cp.async.commit_group;" ::: "memory");                    \
    } while (0)

    LOAD_CHUNK(0, 0);

    for (int c = 0; c < nChunk; c++) {
        const int buf = c & 1;
        if (c + 1 < nChunk) {
            LOAD_CHUNK(c + 1, buf ^ 1);
            asm volatile("cp.async.wait_group 1;" ::: "memory");
        } else {
            asm volatile("cp.async.wait_group 0;" ::: "memory");
        }
        __syncthreads();

        const uint32_t sb = su + buf * BUFB;
#pragma unroll
        for (int s = 0; s < 2; s++) {
            const uint32_t kb = s * 32 + tq * 4;
            uint32_t ah[4][4], al[4][4], bh[4][2], bl[4][2];
#pragma unroll
            for (int mt = 0; mt < 4; mt++) {
                const uint32_t ra = (uint32_t)(wm * 64 + mt * 16 + g) * ROWB + kb;
                ah[mt][0] = lds32(sb + ra);
                ah[mt][1] = lds32(sb + ra + 8 * ROWB);
                ah[mt][2] = lds32(sb + ra + 16);
                ah[mt][3] = lds32(sb + ra + 8 * ROWB + 16);
                al[mt][0] = lds32(sb + MATB + ra);
                al[mt][1] = lds32(sb + MATB + ra + 8 * ROWB);
                al[mt][2] = lds32(sb + MATB + ra + 16);
                al[mt][3] = lds32(sb + MATB + ra + 8 * ROWB + 16);
            }
#pragma unroll
            for (int nt = 0; nt < 4; nt++) {
                const uint32_t rb = (uint32_t)(wn * 32 + nt * 8 + g) * ROWB + kb;
                bh[nt][0] = lds32(sb + 2 * MATB + rb);
                bh[nt][1] = lds32(sb + 2 * MATB + rb + 16);
                bl[nt][0] = lds32(sb + 3 * MATB + rb);
                bl[nt][1] = lds32(sb + 3 * MATB + rb + 16);
            }
#pragma unroll
            for (int mt = 0; mt < 4; mt++)
#pragma unroll
                for (int nt = 0; nt < 4; nt++) {
                    mma16816(acc[mt][nt], ah[mt], bh[nt]);
                    mma16816(acc[mt][nt], ah[mt], bl[nt]);
                    mma16816(acc[mt][nt], al[mt], bh[nt]);
                }
        }
        __syncthreads();
    }

#pragma unroll
    for (int mt = 0; mt < 4; mt++) {
#pragma unroll
        for (int nt = 0; nt < 4; nt++) {
            const long row = m0 + wm * 64 + mt * 16 + g;
            const long col = n0 + wn * 32 + nt * 8 + 2 * tq;
            float2 v0 = make_float2(acc[mt][nt][0], acc[mt][nt][1]);
            float2 v1 = make_float2(acc[mt][nt][2], acc[mt][nt][3]);
            *(float2*)&C[row * ldC + col]       = v0;
            *(float2*)&C[(row + 8) * ldC + col] = v1;
        }
    }
}

// ---------------------------------------------------------------------------
// sx4: fused row-split + transpose-split of x. grid (16, 128, BB), block (32,8)
// ---------------------------------------------------------------------------
__global__ void __launch_bounds__(256)
sx4(const float* __restrict__ x,
    __nv_bfloat16* __restrict__ xrh, __nv_bfloat16* __restrict__ xrl,
    __nv_bfloat16* __restrict__ xth, __nv_bfloat16* __restrict__ xtl)
{
    __shared__ float tl[32][33];
    const int b = blockIdx.z;
    const long xoff = (long)b * LL * DIN;
    const int c0 = blockIdx.x * 32;
    const int r0 = blockIdx.y * 32;
    const int tx = threadIdx.x, ty = threadIdx.y;
#pragma unroll
    for (int i = 0; i < 4; i++) {
        const int r = r0 + ty + 8 * i;
        const long o = xoff + (long)r * DIN + c0 + tx;
        const float v = x[o];
        tl[ty + 8 * i][tx] = v;
        const __nv_bfloat16 h = __float2bfloat16(v);
        const __nv_bfloat16 l = __float2bfloat16(v - __bfloat162float(h));
        xrh[o] = h;
        xrl[o] = l;
    }
    __syncthreads();
#pragma unroll
    for (int i = 0; i < 4; i++) {
        const float v = tl[tx][ty + 8 * i];
        const __nv_bfloat16 h = __float2bfloat16(v);
        const __nv_bfloat16 l = __float2bfloat16(v - __bfloat162float(h));
        const long o = xoff + (long)(c0 + ty + 8 * i) * LL + r0 + tx;
        xth[o] = h;
        xtl[o] = l;
    }
}

// ---------------------------------------------------------------------------
// splitT: in (R x C) fp32 -> out (C x R) bf16 hi/lo per z. block (32,8),
// grid (C/32, R/32, nz). Offsets z*R*C on both sides.
// ---------------------------------------------------------------------------
__global__ void __launch_bounds__(256)
splitT(const float* __restrict__ in, __nv_bfloat16* __restrict__ oh,
       __nv_bfloat16* __restrict__ ol, int R, int C)
{
    __shared__ float tl[32][33];
    const int b = blockIdx.z;
    in += (long)b * R * C;
    oh += (long)b * R * C;
    ol += (long)b * R * C;
    const int c0 = blockIdx.x * 32, r0 = blockIdx.y * 32;
    const int tx = threadIdx.x, ty = threadIdx.y;
#pragma unroll
    for (int i = 0; i < 4; i++)
        tl[ty + 8 * i][tx] = in[(long)(r0 + ty + 8 * i) * C + c0 + tx];
    __syncthreads();
#pragma unroll
    for (int i = 0; i < 4; i++) {
        const float v = tl[tx][ty + 8 * i];
        const __nv_bfloat16 h = __float2bfloat16(v);
        const __nv_bfloat16 l = __float2bfloat16(v - __bfloat162float(h));
        const long o = (long)(c0 + ty + 8 * i) * R + r0 + tx;
        oh[o] = h;
        ol[o] = l;
    }
}

// ---------------------------------------------------------------------------
// reduceGsymSplit: sum 8 gram partials (upper tiles) -> full symmetric G,
// emitted directly as bf16 hi/lo. grid (16,16,BB), block (32,8)
// ---------------------------------------------------------------------------
__global__ void __launch_bounds__(256)
reduceGsymSplit(const float* __restrict__ Gp,
                __nv_bfloat16* __restrict__ Gh, __nv_bfloat16* __restrict__ Gl)
{
    __shared__ float s[32][33];
    const int b  = blockIdx.z;
    const int j0 = blockIdx.x * 32, i0 = blockIdx.y * 32;
    const int tx = threadIdx.x, ty = threadIdx.y;
    const long base = (long)b * DIN * DIN;
    const long PS   = (long)BB * DIN * DIN;

    if ((i0 >> 7) <= (j0 >> 7)) {
#pragma unroll
        for (int i = 0; i < 4; i++) {
            const int r = i0 + ty + 8 * i;
            float sum = 0.f;
#pragma unroll
            for (int p = 0; p < 8; p++)
                sum += Gp[(long)p * PS + base + (long)r * DIN + j0 + tx];
            const __nv_bfloat16 h = __float2bfloat16(sum);
            const __nv_bfloat16 l = __float2bfloat16(sum - __bfloat162float(h));
            Gh[base + (long)r * DIN + j0 + tx] = h;
            Gl[base + (long)r * DIN + j0 + tx] = l;
        }
    } else {
#pragma unroll
        for (int i = 0; i < 4; i++) {
            const int r = j0 + ty + 8 * i;
            float sum = 0.f;
#pragma unroll
            for (int p = 0; p < 8; p++)
                sum += Gp[(long)p * PS + base + (long)r * DIN + i0 + tx];
            s[ty + 8 * i][tx] = sum;
        }
        __syncthreads();
#pragma unroll
        for (int i = 0; i < 4; i++) {
            const float v = s[tx][ty + 8 * i];
            const __nv_bfloat16 h = __float2bfloat16(v);
            const __nv_bfloat16 l = __float2bfloat16(v - __bfloat162float(h));
            const long o = base + (long)(i0 + ty + 8 * i) * DIN + j0 + tx;
            Gh[o] = h;
            Gl[o] = l;
        }
    }
}

// ---------------------------------------------------------------------------
// redSplit: elementwise sum of P partials (stride S4 float4's) + bf16 split.
// ---------------------------------------------------------------------------
__global__ void __launch_bounds__(256)
redSplit(const float4* __restrict__ src, uint2* __restrict__ oh,
         uint2* __restrict__ ol, int S4, int P)
{
    const int i = blockIdx.x * 256 + threadIdx.x;
    if (i >= S4) return;
    float4 s = src[i];
    for (int p = 1; p < P; p++) {
        const float4 v = src[(long)p * S4 + i];
        s.x += v.x; s.y += v.y; s.z += v.z; s.w += v.w;
    }
    const __nv_bfloat16 hx = __float2bfloat16(s.x);
    const __nv_bfloat16 hy = __float2bfloat16(s.y);
    const __nv_bfloat16 hz = __float2bfloat16(s.z);
    const __nv_bfloat16 hw = __float2bfloat16(s.w);
    const __nv_bfloat16 lx = __float2bfloat16(s.x - __bfloat162float(hx));
    const __nv_bfloat16 ly = __float2bfloat16(s.y - __bfloat162float(hy));
    const __nv_bfloat16 lz = __float2bfloat16(s.z - __bfloat162float(hz));
    const __nv_bfloat16 lw = __float2bfloat16(s.w - __bfloat162float(hw));
    uint2 H, L;
    H.x = (uint32_t)bfbits(hx) | ((uint32_t)bfbits(hy) << 16);
    H.y = (uint32_t)bfbits(hz) | ((uint32_t)bfbits(hw) << 16);
    L.x = (uint32_t)bfbits(lx) | ((uint32_t)bfbits(ly) << 16);
    L.y = (uint32_t)bfbits(lz) | ((uint32_t)bfbits(lw) << 16);
    oh[i] = H;
    ol[i] = L;
}

// ---------------------------------------------------------------------------
// gemmSmall: C(64x64) = sum-partials(A) @ sum-partials(B), K=64. fp32 out.
// ---------------------------------------------------------------------------
template <int NPA, int NPB>
__global__ void __launch_bounds__(256)
gemmSmall(const float* __restrict__ A, const float* __restrict__ B,
          float* __restrict__ C,
          int lda, int ldb, int ldc,
          int d0, int d1,
          long a0, long a1, long a2,
          long b0, long b1, long b2,
          long c0, long c1, long c2,
          long pSA, long pSB)
{
    __shared__ __align__(16) float As[64 * 68];
    __shared__ __align__(16) float Bs[64 * 64];

    const int t  = threadIdx.x;
    const int tx = t & 15;
    const int ty = t >> 4;

    {
        const int z  = blockIdx.z;
        const int z0 = z % d0;
        const int zr = z / d0;
        const int z1 = zr % d1;
        const int z2 = zr / d1;
        A += (long)z0 * a0 + (long)z1 * a1 + (long)z2 * a2;
        B += (long)z0 * b0 + (long)z1 * b1 + (long)z2 * b2;
        C += (long)z0 * c0 + (long)z1 * c1 + (long)z2 * c2;
    }
    const long m0 = (long)blockIdx.y * 64;

    {
        const int m = t >> 2, kseg = (t & 3) * 16;
        const float* Ag = A + (m0 + m) * lda + kseg;
#pragma unroll
        for (int s = 0; s < 4; s++) {
            float4 v = *(const float4*)(Ag + s * 4);
#pragma unroll
            for (int pp = 1; pp < NPA; pp++) {
                const float4 w = *(const float4*)(Ag + (long)pp * pSA + s * 4);
                v.x += w.x; v.y += w.y; v.z += w.z; v.w += w.w;
            }
            *(float4*)&As[m * 68 + kseg + s * 4] = v;
        }
    }
    {
        const int r = t >> 2, cs = (t & 3) * 16;
        const float* Bg = B + (long)r * ldb + cs;
#pragma unroll
        for (int s = 0; s < 4; s++) {
            float4 v = *(const float4*)(Bg + s * 4);
#pragma unroll
            for (int pp = 1; pp < NPB; pp++) {
                const float4 w = *(const float4*)(Bg + (long)pp * pSB + s * 4);
                v.x += w.x; v.y += w.y; v.z += w.z; v.w += w.w;
            }
            *(float4*)&Bs[r * 64 + cs + s * 4] = v;
        }
    }
    __syncthreads();

    unsigned long long acc[4][2];
#pragma unroll
    for (int i = 0; i < 4; i++) { acc[i][0] = 0ull; acc[i][1] = 0ull; }

#pragma unroll 8
    for (int kk = 0; kk < 64; kk++) {
        const ulonglong2 bv = *(const ulonglong2*)&Bs[kk * 64 + tx * 4];
        const unsigned long long bb0 = bv.x, bb1 = bv.y;
        unsigned long long p;
        p = pack2(As[(ty * 4 + 0) * 68 + kk]); fma2(acc[0][0], p, bb0); fma2(acc[0][1], p, bb1);
        p = pack2(As[(ty * 4 + 1) * 68 + kk]); fma2(acc[1][0], p, bb0); fma2(acc[1][1], p, bb1);
        p = pack2(As[(ty * 4 + 2) * 68 + kk]); fma2(acc[2][0], p, bb0); fma2(acc[2][1], p, bb1);
        p = pack2(As[(ty * 4 + 3) * 68 + kk]); fma2(acc[3][0], p, bb0); fma2(acc[3][1], p, bb1);
    }

#pragma unroll
    for (int i = 0; i < 4; i++) {
        float4 o;
        o.x = lo32(acc[i][0]); o.y = hi32(acc[i][0]);
        o.z = lo32(acc[i][1]); o.w = hi32(acc[i][1]);
        *(float4*)&C[(m0 + ty * 4 + i) * ldc + tx * 4] = o;
    }
}

// gemmSmallSplit: same but B-partials summed (NPB) and bf16 hi/lo output.
template <int NPB>
__global__ void __launch_bounds__(256)
gemmSmallSplit(const float* __restrict__ A, const float* __restrict__ B,
               __nv_bfloat16* __restrict__ Ch, __nv_bfloat16* __restrict__ Cl,
               int lda, int ldb, int ldc,
               int d0, int d1,
               long a0, long a1, long a2,
               long b0, long b1, long b2,
               long c0, long c1, long c2,
               long pSB)
{
    __shared__ __align__(16) float As[64 * 68];
    __shared__ __align__(16) float Bs[64 * 64];

    const int t  = threadIdx.x;
    const int tx = t & 15;
    const int ty = t >> 4;

    {
        const int z  = blockIdx.z;
        const int z0 = z % d0;
        const int zr = z / d0;
        const int z1 = zr % d1;
        const int z2 = zr / d1;
        A  += (long)z0 * a0 + (long)z1 * a1 + (long)z2 * a2;
        B  += (long)z0 * b0 + (long)z1 * b1 + (long)z2 * b2;
        Ch += (long)z0 * c0 + (long)z1 * c1 + (long)z2 * c2;
        Cl += (long)z0 * c0 + (long)z1 * c1 + (long)z2 * c2;
    }
    const long m0 = (long)blockIdx.y * 64;

    {
        const int m = t >> 2, kseg = (t & 3) * 16;
        const float* Ag = A + (m0 + m) * lda + kseg;
#pragma unroll
        for (int s = 0; s < 4; s++)
            *(float4*)&As[m * 68 + kseg + s * 4] = *(const float4*)(Ag + s * 4);
    }
    {
        const int r = t >> 2, cs = (t & 3) * 16;
        const float* Bg = B + (long)r * ldb + cs;
#pragma unroll
        for (int s = 0; s < 4; s++) {
            float4 v = *(const float4*)(Bg + s * 4);
#pragma unroll
            for (int pp = 1; pp < NPB; pp++) {
                const float4 w = *(const float4*)(Bg + (long)pp * pSB + s * 4);
                v.x += w.x; v.y += w.y; v.z += w.z; v.w += w.w;
            }
            *(float4*)&Bs[r * 64 + cs + s * 4] = v;
        }
    }
    __syncthreads();

    unsigned long long acc[4][2];
#pragma unroll
    for (int i = 0; i < 4; i++) { acc[i][0] = 0ull; acc[i][1] = 0ull; }

#pragma unroll 8
    for (int kk = 0; kk < 64; kk++) {
        const ulonglong2 bv = *(const ulonglong2*)&Bs[kk * 64 + tx * 4];
        const unsigned long long bb0 = bv.x, bb1 = bv.y;
        unsigned long long p;
        p = pack2(As[(ty * 4 + 0) * 68 + kk]); fma2(acc[0][0], p, bb0); fma2(acc[0][1], p, bb1);
        p = pack2(As[(ty * 4 + 1) * 68 + kk]); fma2(acc[1][0], p, bb0); fma2(acc[1][1], p, bb1);
        p = pack2(As[(ty * 4 + 2) * 68 + kk]); fma2(acc[2][0], p, bb0); fma2(acc[2][1], p, bb1);
        p = pack2(As[(ty * 4 + 3) * 68 + kk]); fma2(acc[3][0], p, bb0); fma2(acc[3][1], p, bb1);
    }

#pragma unroll
    for (int i = 0; i < 4; i++) {
        const float f0 = lo32(acc[i][0]), f1 = hi32(acc[i][0]);
        const float f2 = lo32(acc[i][1]), f3 = hi32(acc[i][1]);
        const __nv_bfloat16 h0 = __float2bfloat16(f0);
        const __nv_bfloat16 h1 = __float2bfloat16(f1);
        const __nv_bfloat16 h2 = __float2bfloat16(f2);
        const __nv_bfloat16 h3 = __float2bfloat16(f3);
        const __nv_bfloat16 l0 = __float2bfloat16(f0 - __bfloat162float(h0));
        const __nv_bfloat16 l1 = __float2bfloat16(f1 - __bfloat162float(h1));
        const __nv_bfloat16 l2 = __float2bfloat16(f2 - __bfloat162float(h2));
        const __nv_bfloat16 l3 = __float2bfloat16(f3 - __bfloat162float(h3));
        uint2 H, L;
        H.x = (uint32_t)bfbits(h0) | ((uint32_t)bfbits(h1) << 16);
        H.y = (uint32_t)bfbits(h2) | ((uint32_t)bfbits(h3) << 16);
        L.x = (uint32_t)bfbits(l0) | ((uint32_t)bfbits(l1) << 16);
        L.y = (uint32_t)bfbits(l2) | ((uint32_t)bfbits(l3) << 16);
        *(uint2*)&Ch[(m0 + ty * 4 + i) * ldc + tx * 4] = H;
        *(uint2*)&Cl[(m0 + ty * 4 + i) * ldc + tx * 4] = L;
    }
}

// ---------------------------------------------------------------------------
// kernel_launch: 11 launches, heavy work all on tensor pipe
// ---------------------------------------------------------------------------
extern "C" void kernel_launch(void* const* d_in, const int* in_sizes, int n_in,
                              void* d_out, int out_size)
{
    (void)in_sizes; (void)n_in; (void)out_size;
    const float* x  = (const float*)d_in[0];
    const float* Wq = (const float*)d_in[1];
    const float* Wk = (const float*)d_in[2];
    const float* Wv = (const float*)d_in[3];
    const float* Wo = (const float*)d_in[4];
    float* out = (float*)d_out;

    void* p;
    cudaGetSymbolAddress(&p, g_Gp  ); float* Gp  = (float*)p;
    cudaGetSymbolAddress(&p, g_T1p ); float* T1p = (float*)p;
    cudaGetSymbolAddress(&p, g_Mp  ); float* Mp  = (float*)p;
    cudaGetSymbolAddress(&p, g_Utp ); float* Utp = (float*)p;
    cudaGetSymbolAddress(&p, g_xrh ); __nv_bfloat16* xrh = (__nv_bfloat16*)p;
    cudaGetSymbolAddress(&p, g_xrl ); __nv_bfloat16* xrl = (__nv_bfloat16*)p;
    cudaGetSymbolAddress(&p, g_xth ); __nv_bfloat16* xth = (__nv_bfloat16*)p;
    cudaGetSymbolAddress(&p, g_xtl ); __nv_bfloat16* xtl = (__nv_bfloat16*)p;
    cudaGetSymbolAddress(&p, g_Gh  ); __nv_bfloat16* Gh  = (__nv_bfloat16*)p;
    cudaGetSymbolAddress(&p, g_Gl  ); __nv_bfloat16* Gl  = (__nv_bfloat16*)p;
    cudaGetSymbolAddress(&p, g_wkth); __nv_bfloat16* wkth = (__nv_bfloat16*)p;
    cudaGetSymbolAddress(&p, g_wktl); __nv_bfloat16* wktl = (__nv_bfloat16*)p;
    cudaGetSymbolAddress(&p, g_woth); __nv_bfloat16* woth = (__nv_bfloat16*)p;
    cudaGetSymbolAddress(&p, g_wotl); __nv_bfloat16* wotl = (__nv_bfloat16*)p;
    cudaGetSymbolAddress(&p, g_t2h ); __nv_bfloat16* t2h = (__nv_bfloat16*)p;
    cudaGetSymbolAddress(&p, g_t2l ); __nv_bfloat16* t2l = (__nv_bfloat16*)p;
    cudaGetSymbolAddress(&p, g_uth ); __nv_bfloat16* uth = (__nv_bfloat16*)p;
    cudaGetSymbolAddress(&p, g_utl ); __nv_bfloat16* utl = (__nv_bfloat16*)p;

    static bool attr_done = false;
    if (!attr_done) {
        cudaFuncSetAttribute(mmaT<true>,  cudaFuncAttributeMaxDynamicSharedMemorySize, MMA_SMEM);
        cudaFuncSetAttribute(mmaT<false>, cudaFuncAttributeMaxDynamicSharedMemorySize, MMA_SMEM);
        attr_done = true;
    }

    const long xB = (long)LL * DIN;      // 2097152
    const long GS = (long)DIN * DIN;     // 262144

    // 1) weight prep: Wkcat^T split ([i=(h,dk)][k]); per-head 512x64 transpose
    splitT<<<dim3(2, 16, HH), dim3(32, 8)>>>(Wk, wkth, wktl, DIN, DK);
    // 2) weight prep: Wo^T split ([o][v]); 512x512 transpose
    splitT<<<dim3(16, 16, 1), dim3(32, 8)>>>(Wo, woth, wotl, HH * DV, DOUT);

    // 3) fused x splits
    sx4<<<dim3(16, 128, BB), dim3(32, 8)>>>(x, xrh, xrl, xth, xtl);

    // 4) Gram partials (upper-triangular tiles): 10 tiles x (b, ks=8)
    mmaT<true><<<dim3(10, 1, 16), 256, MMA_SMEM>>>(
        xth, xtl, xth, xtl, Gp,
        LL, LL, DIN, /*nChunk=*/16, /*d0=*/BB,
        xB, xB, GS, (long)BB * GS);

    // 5) G = sum_ks Gp, mirrored, bf16-split
    reduceGsymSplit<<<dim3(16, 16, BB), dim3(32, 8)>>>(Gp, Gh, Gl);

    // 6) T1 partials via tensor: T1p[ks][b] = Wkcat^T @ G[b]
    //    A = wkt rows (K-major), B = G rows (K-major by symmetry). k-split 4.
    mmaT<false><<<dim3(4, 4, BB * 4), 256, MMA_SMEM>>>(
        wkth, wktl, Gh, Gl, T1p,
        DIN, DIN, DIN, /*nChunk=*/4, /*d0=*/BB,
        0, GS, GS, (long)BB * GS);

    // 7) M partials: Mp[ks][b][h] = (sum_p T1p)[h-rows, ks-chunk] @ Wv[h][ks-chunk]
    gemmSmall<4, 1><<<dim3(1, 1, 128), 256>>>(T1p, Wv, Mp,
        DIN, DV, DV,
        HH, BB,
        64L * DIN, GS, 64,
        (long)DIN * DV, 0, 64L * DV,
        (long)DK * DV, (long)HH * DK * DV, (long)BB * HH * DK * DV,
        /*pSA=*/(long)BB * GS, /*pSB=*/0);

    // 8) T2cat = Wq[h] @ (sum_p Mp)[b][h], emitted as bf16 hi/lo
    gemmSmallSplit<8><<<dim3(1, 8, 16), 256>>>(Wq, Mp, t2h, t2l,
        DK, DV, HH * DV,
        HH, BB,
        (long)DIN * DK, 0, 0,
        (long)DK * DV, (long)HH * DK * DV, 0,
        DV, (long)DIN * HH * DV, 0,
        /*pSB=*/(long)BB * HH * DK * DV);

    // 9) U^T partials via tensor: Utp[ks][b] = Wo^T @ T2cat[b]^T
    //    A = wot rows (K-major over v), B = T2 rows (row-major = K-major). k-split 4.
    mmaT<false><<<dim3(4, 4, BB * 4), 256, MMA_SMEM>>>(
        woth, wotl, t2h, t2l, Utp,
        HH * DV, HH * DV, DIN, /*nChunk=*/4, /*d0=*/BB,
        0, (long)DIN * HH * DV, (long)DOUT * DIN, (long)BB * DOUT * DIN);

    // 10) U^T = sum_ks Utp, bf16-split (elementwise, no transpose needed)
    redSplit<<<512, 256>>>((const float4*)Utp, (uint2*)uth, (uint2*)utl,
                           (BB * DOUT * DIN) / 4, 4);

    // 11) out = x @ U via tensor
    mmaT<false><<<dim3(4, 32, BB), 256, MMA_SMEM>>>(
        xrh, xrl, uth, utl, out,
        DIN, DIN, DOUT, /*nChunk=*/16, /*d0=*/BB,
        xB, (long)DOUT * DIN, (long)LL * DOUT, 0);
}

// round 10
// speedup vs baseline: 2.2035x; 1.1009x over previous
#include <cuda_runtime.h>
#include <cuda_bf16.h>
#include <cstdint>

// Problem constants
#define BB   2
#define LL   4096
#define DIN  512
#define HH   8
#define DK   64
#define DV   64
#define DOUT 512

// ---------------------------------------------------------------------------
// Scratch (device globals)
// ---------------------------------------------------------------------------
__device__ float g_Gp [16 * BB * DIN * DIN];    // gram partials [ks][b] (upper tiles)
__device__ float g_T1p[4 * BB * DIN * DIN];     // T1 partials [ks][b]
__device__ float g_Mp [8 * BB * HH * DK * DV];  // M partials [ks][b][h]
__device__ float g_Utp[4 * BB * DOUT * DIN];    // U^T partials [ks][b]

// bf16 split buffers
__device__ __nv_bfloat16 g_xrh[BB * LL * DIN];   // x row-major hi
__device__ __nv_bfloat16 g_xrl[BB * LL * DIN];   // x row-major lo
__device__ __nv_bfloat16 g_xth[BB * DIN * LL];   // x^T hi
__device__ __nv_bfloat16 g_xtl[BB * DIN * LL];   // x^T lo
__device__ __nv_bfloat16 g_Gh [BB * DIN * DIN];  // G hi (symmetric)
__device__ __nv_bfloat16 g_Gl [BB * DIN * DIN];  // G lo
__device__ __nv_bfloat16 g_wkth[DIN * DIN];      // Wkcat^T hi : [i=(h,dk)][k]
__device__ __nv_bfloat16 g_wktl[DIN * DIN];
__device__ __nv_bfloat16 g_woth[DOUT * (HH*DV)]; // Wo^T hi : [o][v]
__device__ __nv_bfloat16 g_wotl[DOUT * (HH*DV)];
__device__ __nv_bfloat16 g_t2h[BB * DIN * (HH * DV)]; // T2cat hi
__device__ __nv_bfloat16 g_t2l[BB * DIN * (HH * DV)]; // T2cat lo
__device__ __nv_bfloat16 g_uth[BB * DOUT * DIN]; // U^T hi
__device__ __nv_bfloat16 g_utl[BB * DOUT * DIN]; // U^T lo

// Upper-triangle tile map for 4x4 tile grid
__constant__ int c_tri_i[10] = {0,0,0,0,1,1,1,2,2,3};
__constant__ int c_tri_j[10] = {0,1,2,3,1,2,3,2,3,3};

// ---------------------------------------------------------------------------
// f32x2 helpers (SIMT small GEMMs)
// ---------------------------------------------------------------------------
__device__ __forceinline__ unsigned long long pack2(float a) {
    unsigned long long r;
    asm("mov.b64 %0, {%1, %1};" : "=l"(r) : "f"(a));
    return r;
}
__device__ __forceinline__ void fma2(unsigned long long& acc,
                                     unsigned long long a,
                                     unsigned long long b) {
    asm("fma.rn.f32x2 %0, %1, %2, %0;" : "+l"(acc) : "l"(a), "l"(b));
}
__device__ __forceinline__ float lo32(unsigned long long v) {
    return __uint_as_float((unsigned)(v & 0xffffffffull));
}
__device__ __forceinline__ float hi32(unsigned long long v) {
    return __uint_as_float((unsigned)(v >> 32));
}
__device__ __forceinline__ unsigned short bfbits(__nv_bfloat16 h) {
    return ((__nv_bfloat16_raw)h).x;
}

// ---------------------------------------------------------------------------
// helpers for mma.sync path
// ---------------------------------------------------------------------------
__device__ __forceinline__ uint32_t smem_u32(const void* p) {
    uint32_t a;
    asm("{ .reg .u64 t; cvta.to.shared.u64 t, %1; cvt.u32.u64 %0, t; }"
        : "=r"(a) : "l"(p));
    return a;
}
__device__ __forceinline__ void cp_async16(uint32_t dst, const void* src) {
    asm volatile("cp.async.cg.shared.global [%0], [%1], 16;" :: "r"(dst), "l"(src));
}
__device__ __forceinline__ void ldmx4(uint32_t* r, uint32_t addr) {
    asm volatile("ldmatrix.sync.aligned.m8n8.x4.shared.b16 {%0,%1,%2,%3}, [%4];"
        : "=r"(r[0]), "=r"(r[1]), "=r"(r[2]), "=r"(r[3]) : "r"(addr));
}
__device__ __forceinline__ void ldmx2(uint32_t* r, uint32_t addr) {
    asm volatile("ldmatrix.sync.aligned.m8n8.x2.shared.b16 {%0,%1}, [%2];"
        : "=r"(r[0]), "=r"(r[1]) : "r"(addr));
}
__device__ __forceinline__ void mma16816(float* c, const uint32_t* a, const uint32_t* b) {
    asm volatile(
        "mma.sync.aligned.m16n8k16.row.col.f32.bf16.bf16.f32 "
        "{%0,%1,%2,%3}, {%4,%5,%6,%7}, {%8,%9}, {%0,%1,%2,%3};"
        : "+f"(c[0]), "+f"(c[1]), "+f"(c[2]), "+f"(c[3])
        : "r"(a[0]), "r"(a[1]), "r"(a[2]), "r"(a[3]), "r"(b[0]), "r"(b[1]));
}

// ---------------------------------------------------------------------------
// mmaT: C[128x128 tile] fp32 = split-bf16 A(M rows,K) @ B(N rows,K)^T
// 256 threads = 8 warps, warp tile 64x32. ldmatrix fragment loads
// (conflict-free with ROWB=80). 2 CTAs/SM forced via launch_bounds.
// ---------------------------------------------------------------------------
#define ROWB   80
#define MATB   (128 * ROWB)
#define BUFB   (4 * MATB)
#define MMA_SMEM (2 * BUFB)

template <bool TRI>
__global__ void __launch_bounds__(256, 2)
mmaT(const __nv_bfloat16* __restrict__ Ahi, const __nv_bfloat16* __restrict__ Alo,
     const __nv_bfloat16* __restrict__ Bhi, const __nv_bfloat16* __restrict__ Blo,
     float* __restrict__ C,
     int ldA, int ldB, int ldC, int nChunk, int d0,
     long aB, long bB, long cB, long cS)
{
    extern __shared__ char sm[];
    const uint32_t su = smem_u32(sm);

    const int t    = threadIdx.x;
    const int wid  = t >> 5;
    const int lane = t & 31;
    const int g    = lane >> 2;
    const int tq   = lane & 3;
    const int wm   = wid & 1;
    const int wn   = wid >> 1;

    const int z  = blockIdx.z;
    const int z0 = z % d0;
    const int z1 = z / d0;
    const long kOff = (long)z1 * nChunk * 32;

    long m0, n0;
    if (TRI) {
        m0 = (long)c_tri_i[blockIdx.x] * 128;
        n0 = (long)c_tri_j[blockIdx.x] * 128;
    } else {
        m0 = (long)blockIdx.y * 128;
        n0 = (long)blockIdx.x * 128;
    }

    const __nv_bfloat16* bAh = Ahi + (long)z0 * aB + kOff + m0 * ldA;
    const __nv_bfloat16* bAl = Alo + (long)z0 * aB + kOff + m0 * ldA;
    const __nv_bfloat16* bBh = Bhi + (long)z0 * bB + kOff + n0 * ldB;
    const __nv_bfloat16* bBl = Blo + (long)z0 * bB + kOff + n0 * ldB;
    C += (long)z0 * cB + (long)z1 * cS;

    const int r0 = t >> 2,        s0 = (t & 3) * 16;
    const int r1 = (t + 256) >> 2, s1 = ((t + 256) & 3) * 16;

    // ldmatrix lane address components
    const int l7 = lane & 7;
    const uint32_t aOff = (uint32_t)(wm * 64 + l7 + ((lane >> 3) & 1) * 8) * ROWB
                        + (uint32_t)(lane >> 4) * 16;
    const uint32_t bOff = (uint32_t)(wn * 32 + l7) * ROWB
                        + (uint32_t)((lane >> 3) & 1) * 16;

    float acc[4][4][4];
#pragma unroll
    for (int i = 0; i < 4; i++)
#pragma unroll
        for (int j = 0; j < 4; j++)
#pragma unroll
            for (int k = 0; k < 4; k++) acc[i][j][k] = 0.f;

#define LOAD_CHUNK(cidx, buf)                                                   \
    do {                                                                        \
        const uint32_t sb_ = su + (buf) * BUFB;                                 \
        const long ko_ = (long)(cidx) * 32;                                     \
        cp_async16(sb_ + 0 * MATB + r0 * ROWB + s0, bAh + (long)r0 * ldA + ko_ + s0 / 2); \
        cp_async16(sb_ + 0 * MATB + r1 * ROWB + s1, bAh + (long)r1 * ldA + ko_ + s1 / 2); \
        cp_async16(sb_ + 1 * MATB + r0 * ROWB + s0, bAl + (long)r0 * ldA + ko_ + s0 / 2); \
        cp_async16(sb_ + 1 * MATB + r1 * ROWB + s1, bAl + (long)r1 * ldA + ko_ + s1 / 2); \
        cp_async16(sb_ + 2 * MATB + r0 * ROWB + s0, bBh + (long)r0 * ldB + ko_ + s0 / 2); \
        cp_async16(sb_ + 2 * MATB + r1 * ROWB + s1, bBh + (long)r1 * ldB + ko_ + s1 / 2); \
        cp_async16(sb_ + 3 * MATB + r0 * ROWB + s0, bBl + (long)r0 * ldB + ko_ + s0 / 2); \
        cp_async16(sb_ + 3 * MATB + r1 * ROWB + s1, bBl + (long)r1 * ldB + ko_ + s1 / 2); \
        asm volatile("cp.async.commit_group;" ::: "memory");                    \
    } while (0)

    LOAD_CHUNK(0, 0);

    for (int c = 0; c < nChunk; c++) {
        const int buf = c & 1;
        if (c + 1 < nChunk) {
            LOAD_CHUNK(c + 1, buf ^ 1);
            asm volatile("cp.async.wait_group 1;" ::: "memory");
        } else {
            asm volatile("cp.async.wait_group 0;" ::: "memory");
        }
        __syncthreads();

        const uint32_t sb = su + buf * BUFB;
#pragma unroll
        for (int s = 0; s < 2; s++) {
            const uint32_t so = s * 32;
            uint32_t ah[4][4], bh[4][2], bl[4][2];
#pragma unroll
            for (int mt = 0; mt < 4; mt++)
                ldmx4(ah[mt], sb + aOff + mt * (16 * ROWB) + so);
#pragma unroll
            for (int nt = 0; nt < 4; nt++) {
                ldmx2(bh[nt], sb + 2 * MATB + bOff + nt * (8 * ROWB) + so);
                ldmx2(bl[nt], sb + 3 * MATB + bOff + nt * (8 * ROWB) + so);
            }
            // pass 1: Ah * Bh
#pragma unroll
            for (int mt = 0; mt < 4; mt++)
#pragma unroll
                for (int nt = 0; nt < 4; nt++)
                    mma16816(acc[mt][nt], ah[mt], bh[nt]);
            // pass 2: Ah * Bl
#pragma unroll
            for (int mt = 0; mt < 4; mt++)
#pragma unroll
                for (int nt = 0; nt < 4; nt++)
                    mma16816(acc[mt][nt], ah[mt], bl[nt]);
            // pass 3: Al * Bh (load Al late to limit register pressure)
            uint32_t al[4][4];
#pragma unroll
            for (int mt = 0; mt < 4; mt++)
                ldmx4(al[mt], sb + MATB + aOff + mt * (16 * ROWB) + so);
#pragma unroll
            for (int mt = 0; mt < 4; mt++)
#pragma unroll
                for (int nt = 0; nt < 4; nt++)
                    mma16816(acc[mt][nt], al[mt], bh[nt]);
        }
        __syncthreads();
    }

#pragma unroll
    for (int mt = 0; mt < 4; mt++) {
#pragma unroll
        for (int nt = 0; nt < 4; nt++) {
            const long row = m0 + wm * 64 + mt * 16 + g;
            const long col = n0 + wn * 32 + nt * 8 + 2 * tq;
            float2 v0 = make_float2(acc[mt][nt][0], acc[mt][nt][1]);
            float2 v1 = make_float2(acc[mt][nt][2], acc[mt][nt][3]);
            *(float2*)&C[row * ldC + col]       = v0;
            *(float2*)&C[(row + 8) * ldC + col] = v1;
        }
    }
}

// ---------------------------------------------------------------------------
// sx4: fused row-split + transpose-split of x. grid (16, 128, BB), block (32,8)
// ---------------------------------------------------------------------------
__global__ void __launch_bounds__(256)
sx4(const float* __restrict__ x,
    __nv_bfloat16* __restrict__ xrh, __nv_bfloat16* __restrict__ xrl,
    __nv_bfloat16* __restrict__ xth, __nv_bfloat16* __restrict__ xtl)
{
    __shared__ float tl[32][33];
    const int b = blockIdx.z;
    const long xoff = (long)b * LL * DIN;
    const int c0 = blockIdx.x * 32;
    const int r0 = blockIdx.y * 32;
    const int tx = threadIdx.x, ty = threadIdx.y;
#pragma unroll
    for (int i = 0; i < 4; i++) {
        const int r = r0 + ty + 8 * i;
        const long o = xoff + (long)r * DIN + c0 + tx;
        const float v = x[o];
        tl[ty + 8 * i][tx] = v;
        const __nv_bfloat16 h = __float2bfloat16(v);
        const __nv_bfloat16 l = __float2bfloat16(v - __bfloat162float(h));
        xrh[o] = h;
        xrl[o] = l;
    }
    __syncthreads();
#pragma unroll
    for (int i = 0; i < 4; i++) {
        const float v = tl[tx][ty + 8 * i];
        const __nv_bfloat16 h = __float2bfloat16(v);
        const __nv_bfloat16 l = __float2bfloat16(v - __bfloat162float(h));
        const long o = xoff + (long)(c0 + ty + 8 * i) * LL + r0 + tx;
        xth[o] = h;
        xtl[o] = l;
    }
}

// ---------------------------------------------------------------------------
// splitT: in (R x C) fp32 -> out (C x R) bf16 hi/lo per z.
// ---------------------------------------------------------------------------
__global__ void __launch_bounds__(256)
splitT(const float* __restrict__ in, __nv_bfloat16* __restrict__ oh,
       __nv_bfloat16* __restrict__ ol, int R, int C)
{
    __shared__ float tl[32][33];
    const int b = blockIdx.z;
    in += (long)b * R * C;
    oh += (long)b * R * C;
    ol += (long)b * R * C;
    const int c0 = blockIdx.x * 32, r0 = blockIdx.y * 32;
    const int tx = threadIdx.x, ty = threadIdx.y;
#pragma unroll
    for (int i = 0; i < 4; i++)
        tl[ty + 8 * i][tx] = in[(long)(r0 + ty + 8 * i) * C + c0 + tx];
    __syncthreads();
#pragma unroll
    for (int i = 0; i < 4; i++) {
        const float v = tl[tx][ty + 8 * i];
        const __nv_bfloat16 h = __float2bfloat16(v);
        const __nv_bfloat16 l = __float2bfloat16(v - __bfloat162float(h));
        const long o = (long)(c0 + ty + 8 * i) * R + r0 + tx;
        oh[o] = h;
        ol[o] = l;
    }
}

// ---------------------------------------------------------------------------
// reduceGsymSplit: sum 16 gram partials (upper tiles) -> full symmetric G,
// emitted directly as bf16 hi/lo. grid (16,16,BB), block (32,8)
// ---------------------------------------------------------------------------
__global__ void __launch_bounds__(256)
reduceGsymSplit(const float* __restrict__ Gp,
                __nv_bfloat16* __restrict__ Gh, __nv_bfloat16* __restrict__ Gl)
{
    __shared__ float s[32][33];
    const int b  = blockIdx.z;
    const int j0 = blockIdx.x * 32, i0 = blockIdx.y * 32;
    const int tx = threadIdx.x, ty = threadIdx.y;
    const long base = (long)b * DIN * DIN;
    const long PS   = (long)BB * DIN * DIN;

    if ((i0 >> 7) <= (j0 >> 7)) {
#pragma unroll
        for (int i = 0; i < 4; i++) {
            const int r = i0 + ty + 8 * i;
            float sum = 0.f;
#pragma unroll
            for (int p = 0; p < 16; p++)
                sum += Gp[(long)p * PS + base + (long)r * DIN + j0 + tx];
            const __nv_bfloat16 h = __float2bfloat16(sum);
            const __nv_bfloat16 l = __float2bfloat16(sum - __bfloat162float(h));
            Gh[base + (long)r * DIN + j0 + tx] = h;
            Gl[base + (long)r * DIN + j0 + tx] = l;
        }
    } else {
#pragma unroll
        for (int i = 0; i < 4; i++) {
            const int r = j0 + ty + 8 * i;
            float sum = 0.f;
#pragma unroll
            for (int p = 0; p < 16; p++)
                sum += Gp[(long)p * PS + base + (long)r * DIN + i0 + tx];
            s[ty + 8 * i][tx] = sum;
        }
        __syncthreads();
#pragma unroll
        for (int i = 0; i < 4; i++) {
            const float v = s[tx][ty + 8 * i];
            const __nv_bfloat16 h = __float2bfloat16(v);
            const __nv_bfloat16 l = __float2bfloat16(v - __bfloat162float(h));
            const long o = base + (long)(i0 + ty + 8 * i) * DIN + j0 + tx;
            Gh[o] = h;
            Gl[o] = l;
        }
    }
}

// ---------------------------------------------------------------------------
// redSplit: elementwise sum of P partials + bf16 split.
// ---------------------------------------------------------------------------
__global__ void __launch_bounds__(256)
redSplit(const float4* __restrict__ src, uint2* __restrict__ oh,
         uint2* __restrict__ ol, int S4, int P)
{
    const int i = blockIdx.x * 256 + threadIdx.x;
    if (i >= S4) return;
    float4 s = src[i];
    for (int p = 1; p < P; p++) {
        const float4 v = src[(long)p * S4 + i];
        s.x += v.x; s.y += v.y; s.z += v.z; s.w += v.w;
    }
    const __nv_bfloat16 hx = __float2bfloat16(s.x);
    const __nv_bfloat16 hy = __float2bfloat16(s.y);
    const __nv_bfloat16 hz = __float2bfloat16(s.z);
    const __nv_bfloat16 hw = __float2bfloat16(s.w);
    const __nv_bfloat16 lx = __float2bfloat16(s.x - __bfloat162float(hx));
    const __nv_bfloat16 ly = __float2bfloat16(s.y - __bfloat162float(hy));
    const __nv_bfloat16 lz = __float2bfloat16(s.z - __bfloat162float(hz));
    const __nv_bfloat16 lw = __float2bfloat16(s.w - __bfloat162float(hw));
    uint2 H, L;
    H.x = (uint32_t)bfbits(hx) | ((uint32_t)bfbits(hy) << 16);
    H.y = (uint32_t)bfbits(hz) | ((uint32_t)bfbits(hw) << 16);
    L.x = (uint32_t)bfbits(lx) | ((uint32_t)bfbits(ly) << 16);
    L.y = (uint32_t)bfbits(lz) | ((uint32_t)bfbits(lw) << 16);
    oh[i] = H;
    ol[i] = L;
}

// ---------------------------------------------------------------------------
// gemmSmall: C(64x64) = sum-partials(A) @ sum-partials(B), K=64. fp32 out.
// ---------------------------------------------------------------------------
template <int NPA, int NPB>
__global__ void __launch_bounds__(256)
gemmSmall(const float* __restrict__ A, const float* __restrict__ B,
          float* __restrict__ C,
          int lda, int ldb, int ldc,
          int d0, int d1,
          long a0, long a1, long a2,
          long b0, long b1, long b2,
          long c0, long c1, long c2,
          long pSA, long pSB)
{
    __shared__ __align__(16) float As[64 * 68];
    __shared__ __align__(16) float Bs[64 * 64];

    const int t  = threadIdx.x;
    const int tx = t & 15;
    const int ty = t >> 4;

    {
        const int z  = blockIdx.z;
        const int z0 = z % d0;
        const int zr = z / d0;
        const int z1 = zr % d1;
        const int z2 = zr / d1;
        A += (long)z0 * a0 + (long)z1 * a1 + (long)z2 * a2;
        B += (long)z0 * b0 + (long)z1 * b1 + (long)z2 * b2;
        C += (long)z0 * c0 + (long)z1 * c1 + (long)z2 * c2;
    }
    const long m0 = (long)blockIdx.y * 64;

    {
        const int m = t >> 2, kseg = (t & 3) * 16;
        const float* Ag = A + (m0 + m) * lda + kseg;
#pragma unroll
        for (int s = 0; s < 4; s++) {
            float4 v = *(const float4*)(Ag + s * 4);
#pragma unroll
            for (int pp = 1; pp < NPA; pp++) {
                const float4 w = *(const float4*)(Ag + (long)pp * pSA + s * 4);
                v.x += w.x; v.y += w.y; v.z += w.z; v.w += w.w;
            }
            *(float4*)&As[m * 68 + kseg + s * 4] = v;
        }
    }
    {
        const int r = t >> 2, cs = (t & 3) * 16;
        const float* Bg = B + (long)r * ldb + cs;
#pragma unroll
        for (int s = 0; s < 4; s++) {
            float4 v = *(const float4*)(Bg + s * 4);
#pragma unroll
            for (int pp = 1; pp < NPB; pp++) {
                const float4 w = *(const float4*)(Bg + (long)pp * pSB + s * 4);
                v.x += w.x; v.y += w.y; v.z += w.z; v.w += w.w;
            }
            *(float4*)&Bs[r * 64 + cs + s * 4] = v;
        }
    }
    __syncthreads();

    unsigned long long acc[4][2];
#pragma unroll
    for (int i = 0; i < 4; i++) { acc[i][0] = 0ull; acc[i][1] = 0ull; }

#pragma unroll 8
    for (int kk = 0; kk < 64; kk++) {
        const ulonglong2 bv = *(const ulonglong2*)&Bs[kk * 64 + tx * 4];
        const unsigned long long bb0 = bv.x, bb1 = bv.y;
        unsigned long long p;
        p = pack2(As[(ty * 4 + 0) * 68 + kk]); fma2(acc[0][0], p, bb0); fma2(acc[0][1], p, bb1);
        p = pack2(As[(ty * 4 + 1) * 68 + kk]); fma2(acc[1][0], p, bb0); fma2(acc[1][1], p, bb1);
        p = pack2(As[(ty * 4 + 2) * 68 + kk]); fma2(acc[2][0], p, bb0); fma2(acc[2][1], p, bb1);
        p = pack2(As[(ty * 4 + 3) * 68 + kk]); fma2(acc[3][0], p, bb0); fma2(acc[3][1], p, bb1);
    }

#pragma unroll
    for (int i = 0; i < 4; i++) {
        float4 o;
        o.x = lo32(acc[i][0]); o.y = hi32(acc[i][0]);
        o.z = lo32(acc[i][1]); o.w = hi32(acc[i][1]);
        *(float4*)&C[(m0 + ty * 4 + i) * ldc + tx * 4] = o;
    }
}

// gemmSmallSplit: same but B-partials summed (NPB) and bf16 hi/lo output.
template <int NPB>
__global__ void __launch_bounds__(256)
gemmSmallSplit(const float* __restrict__ A, const float* __restrict__ B,
               __nv_bfloat16* __restrict__ Ch, __nv_bfloat16* __restrict__ Cl,
               int lda, int ldb, int ldc,
               int d0, int d1,
               long a0, long a1, long a2,
               long b0, long b1, long b2,
               long c0, long c1, long c2,
               long pSB)
{
    __shared__ __align__(16) float As[64 * 68];
    __shared__ __align__(16) float Bs[64 * 64];

    const int t  = threadIdx.x;
    const int tx = t & 15;
    const int ty = t >> 4;

    {
        const int z  = blockIdx.z;
        const int z0 = z % d0;
        const int zr = z / d0;
        const int z1 = zr % d1;
        const int z2 = zr / d1;
        A  += (long)z0 * a0 + (long)z1 * a1 + (long)z2 * a2;
        B  += (long)z0 * b0 + (long)z1 * b1 + (long)z2 * b2;
        Ch += (long)z0 * c0 + (long)z1 * c1 + (long)z2 * c2;
        Cl += (long)z0 * c0 + (long)z1 * c1 + (long)z2 * c2;
    }
    const long m0 = (long)blockIdx.y * 64;

    {
        const int m = t >> 2, kseg = (t & 3) * 16;
        const float* Ag = A + (m0 + m) * lda + kseg;
#pragma unroll
        for (int s = 0; s < 4; s++)
            *(float4*)&As[m * 68 + kseg + s * 4] = *(const float4*)(Ag + s * 4);
    }
    {
        const int r = t >> 2, cs = (t & 3) * 16;
        const float* Bg = B + (long)r * ldb + cs;
#pragma unroll
        for (int s = 0; s < 4; s++) {
            float4 v = *(const float4*)(Bg + s * 4);
#pragma unroll
            for (int pp = 1; pp < NPB; pp++) {
                const float4 w = *(const float4*)(Bg + (long)pp * pSB + s * 4);
                v.x += w.x; v.y += w.y; v.z += w.z; v.w += w.w;
            }
            *(float4*)&Bs[r * 64 + cs + s * 4] = v;
        }
    }
    __syncthreads();

    unsigned long long acc[4][2];
#pragma unroll
    for (int i = 0; i < 4; i++) { acc[i][0] = 0ull; acc[i][1] = 0ull; }

#pragma unroll 8
    for (int kk = 0; kk < 64; kk++) {
        const ulonglong2 bv = *(const ulonglong2*)&Bs[kk * 64 + tx * 4];
        const unsigned long long bb0 = bv.x, bb1 = bv.y;
        unsigned long long p;
        p = pack2(As[(ty * 4 + 0) * 68 + kk]); fma2(acc[0][0], p, bb0); fma2(acc[0][1], p, bb1);
        p = pack2(As[(ty * 4 + 1) * 68 + kk]); fma2(acc[1][0], p, bb0); fma2(acc[1][1], p, bb1);
        p = pack2(As[(ty * 4 + 2) * 68 + kk]); fma2(acc[2][0], p, bb0); fma2(acc[2][1], p, bb1);
        p = pack2(As[(ty * 4 + 3) * 68 + kk]); fma2(acc[3][0], p, bb0); fma2(acc[3][1], p, bb1);
    }

#pragma unroll
    for (int i = 0; i < 4; i++) {
        const float f0 = lo32(acc[i][0]), f1 = hi32(acc[i][0]);
        const float f2 = lo32(acc[i][1]), f3 = hi32(acc[i][1]);
        const __nv_bfloat16 h0 = __float2bfloat16(f0);
        const __nv_bfloat16 h1 = __float2bfloat16(f1);
        const __nv_bfloat16 h2 = __float2bfloat16(f2);
        const __nv_bfloat16 h3 = __float2bfloat16(f3);
        const __nv_bfloat16 l0 = __float2bfloat16(f0 - __bfloat162float(h0));
        const __nv_bfloat16 l1 = __float2bfloat16(f1 - __bfloat162float(h1));
        const __nv_bfloat16 l2 = __float2bfloat16(f2 - __bfloat162float(h2));
        const __nv_bfloat16 l3 = __float2bfloat16(f3 - __bfloat162float(h3));
        uint2 H, L;
        H.x = (uint32_t)bfbits(h0) | ((uint32_t)bfbits(h1) << 16);
        H.y = (uint32_t)bfbits(h2) | ((uint32_t)bfbits(h3) << 16);
        L.x = (uint32_t)bfbits(l0) | ((uint32_t)bfbits(l1) << 16);
        L.y = (uint32_t)bfbits(l2) | ((uint32_t)bfbits(l3) << 16);
        *(uint2*)&Ch[(m0 + ty * 4 + i) * ldc + tx * 4] = H;
        *(uint2*)&Cl[(m0 + ty * 4 + i) * ldc + tx * 4] = L;
    }
}

// ---------------------------------------------------------------------------
// kernel_launch: 11 launches, heavy work all on tensor pipe
// ---------------------------------------------------------------------------
extern "C" void kernel_launch(void* const* d_in, const int* in_sizes, int n_in,
                              void* d_out, int out_size)
{
    (void)in_sizes; (void)n_in; (void)out_size;
    const float* x  = (const float*)d_in[0];
    const float* Wq = (const float*)d_in[1];
    const float* Wk = (const float*)d_in[2];
    const float* Wv = (const float*)d_in[3];
    const float* Wo = (const float*)d_in[4];
    float* out = (float*)d_out;

    void* p;
    cudaGetSymbolAddress(&p, g_Gp  ); float* Gp  = (float*)p;
    cudaGetSymbolAddress(&p, g_T1p ); float* T1p = (float*)p;
    cudaGetSymbolAddress(&p, g_Mp  ); float* Mp  = (float*)p;
    cudaGetSymbolAddress(&p, g_Utp ); float* Utp = (float*)p;
    cudaGetSymbolAddress(&p, g_xrh ); __nv_bfloat16* xrh = (__nv_bfloat16*)p;
    cudaGetSymbolAddress(&p, g_xrl ); __nv_bfloat16* xrl = (__nv_bfloat16*)p;
    cudaGetSymbolAddress(&p, g_xth ); __nv_bfloat16* xth = (__nv_bfloat16*)p;
    cudaGetSymbolAddress(&p, g_xtl ); __nv_bfloat16* xtl = (__nv_bfloat16*)p;
    cudaGetSymbolAddress(&p, g_Gh  ); __nv_bfloat16* Gh  = (__nv_bfloat16*)p;
    cudaGetSymbolAddress(&p, g_Gl  ); __nv_bfloat16* Gl  = (__nv_bfloat16*)p;
    cudaGetSymbolAddress(&p, g_wkth); __nv_bfloat16* wkth = (__nv_bfloat16*)p;
    cudaGetSymbolAddress(&p, g_wktl); __nv_bfloat16* wktl = (__nv_bfloat16*)p;
    cudaGetSymbolAddress(&p, g_woth); __nv_bfloat16* woth = (__nv_bfloat16*)p;
    cudaGetSymbolAddress(&p, g_wotl); __nv_bfloat16* wotl = (__nv_bfloat16*)p;
    cudaGetSymbolAddress(&p, g_t2h ); __nv_bfloat16* t2h = (__nv_bfloat16*)p;
    cudaGetSymbolAddress(&p, g_t2l ); __nv_bfloat16* t2l = (__nv_bfloat16*)p;
    cudaGetSymbolAddress(&p, g_uth ); __nv_bfloat16* uth = (__nv_bfloat16*)p;
    cudaGetSymbolAddress(&p, g_utl ); __nv_bfloat16* utl = (__nv_bfloat16*)p;

    static bool attr_done = false;
    if (!attr_done) {
        cudaFuncSetAttribute(mmaT<true>,  cudaFuncAttributeMaxDynamicSharedMemorySize, MMA_SMEM);
        cudaFuncSetAttribute(mmaT<false>, cudaFuncAttributeMaxDynamicSharedMemorySize, MMA_SMEM);
        attr_done = true;
    }

    const long xB = (long)LL * DIN;      // 2097152
    const long GS = (long)DIN * DIN;     // 262144

    // 1) weight prep: Wkcat^T split; per-head 512x64 transpose
    splitT<<<dim3(2, 16, HH), dim3(32, 8)>>>(Wk, wkth, wktl, DIN, DK);
    // 2) weight prep: Wo^T split; 512x512 transpose
    splitT<<<dim3(16, 16, 1), dim3(32, 8)>>>(Wo, woth, wotl, HH * DV, DOUT);

    // 3) fused x splits
    sx4<<<dim3(16, 128, BB), dim3(32, 8)>>>(x, xrh, xrl, xth, xtl);

    // 4) Gram partials (upper-triangular tiles): 10 tiles x (b, ks=16)
    //    k-split 16 -> 320 blocks -> 2 CTAs/SM
    mmaT<true><<<dim3(10, 1, BB * 16), 256, MMA_SMEM>>>(
        xth, xtl, xth, xtl, Gp,
        LL, LL, DIN, /*nChunk=*/8, /*d0=*/BB,
        xB, xB, GS, (long)BB * GS);

    // 5) G = sum_ks Gp, mirrored, bf16-split
    reduceGsymSplit<<<dim3(16, 16, BB), dim3(32, 8)>>>(Gp, Gh, Gl);

    // 6) T1 partials via tensor: T1p[ks][b] = Wkcat^T @ G[b]
    mmaT<false><<<dim3(4, 4, BB * 4), 256, MMA_SMEM>>>(
        wkth, wktl, Gh, Gl, T1p,
        DIN, DIN, DIN, /*nChunk=*/4, /*d0=*/BB,
        0, GS, GS, (long)BB * GS);

    // 7) M partials: Mp[ks][b][h] = (sum_p T1p)[h-rows, ks-chunk] @ Wv[h][ks-chunk]
    gemmSmall<4, 1><<<dim3(1, 1, 128), 256>>>(T1p, Wv, Mp,
        DIN, DV, DV,
        HH, BB,
        64L * DIN, GS, 64,
        (long)DIN * DV, 0, 64L * DV,
        (long)DK * DV, (long)HH * DK * DV, (long)BB * HH * DK * DV,
        /*pSA=*/(long)BB * GS, /*pSB=*/0);

    // 8) T2cat = Wq[h] @ (sum_p Mp)[b][h], emitted as bf16 hi/lo
    gemmSmallSplit<8><<<dim3(1, 8, 16), 256>>>(Wq, Mp, t2h, t2l,
        DK, DV, HH * DV,
        HH, BB,
        (long)DIN * DK, 0, 0,
        (long)DK * DV, (long)HH * DK * DV, 0,
        DV, (long)DIN * HH * DV, 0,
        /*pSB=*/(long)BB * HH * DK * DV);

    // 9) U^T partials via tensor: Utp[ks][b] = Wo^T @ T2cat[b]^T
    mmaT<false><<<dim3(4, 4, BB * 4), 256, MMA_SMEM>>>(
        woth, wotl, t2h, t2l, Utp,
        HH * DV, HH * DV, DIN, /*nChunk=*/4, /*d0=*/BB,
        0, (long)DIN * HH * DV, (long)DOUT * DIN, (long)BB * DOUT * DIN);

    // 10) U^T = sum_ks Utp, bf16-split
    redSplit<<<512, 256>>>((const float4*)Utp, (uint2*)uth, (uint2*)utl,
                           (BB * DOUT * DIN) / 4, 4);

    // 11) out = x @ U via tensor
    mmaT<false><<<dim3(4, 32, BB), 256, MMA_SMEM>>>(
        xrh, xrl, uth, utl, out,
        DIN, DIN, DOUT, /*nChunk=*/16, /*d0=*/BB,
        xB, (long)DOUT * DIN, (long)LL * DOUT, 0);
}

// round 14
// speedup vs baseline: 2.2507x; 1.0214x over previous
#include <cuda_runtime.h>
#include <cuda_bf16.h>
#include <cstdint>

// Problem constants
#define BB   2
#define LL   4096
#define DIN  512
#define HH   8
#define DK   64
#define DV   64
#define DOUT 512

// ---------------------------------------------------------------------------
// Scratch (device globals)
// ---------------------------------------------------------------------------
__device__ float g_Gp [16 * BB * DIN * DIN];    // gram partials [ks][b] (upper tiles)
__device__ float g_T1p[8 * BB * DIN * DIN];     // T1 partials [ks][b]
__device__ float g_Mp [8 * BB * HH * DK * DV];  // M partials [ks][b][h]
__device__ float g_Utp[8 * BB * DOUT * DIN];    // U^T partials [ks][b]

// bf16 split buffers
__device__ __nv_bfloat16 g_xrh[BB * LL * DIN];   // x row-major hi
__device__ __nv_bfloat16 g_xrl[BB * LL * DIN];   // x row-major lo
__device__ __nv_bfloat16 g_xth[BB * DIN * LL];   // x^T hi
__device__ __nv_bfloat16 g_xtl[BB * DIN * LL];   // x^T lo
__device__ __nv_bfloat16 g_Gh [BB * DIN * DIN];  // G hi (symmetric)
__device__ __nv_bfloat16 g_Gl [BB * DIN * DIN];  // G lo
__device__ __nv_bfloat16 g_wkth[DIN * DIN];      // Wkcat^T hi
__device__ __nv_bfloat16 g_wktl[DIN * DIN];
__device__ __nv_bfloat16 g_woth[DOUT * (HH*DV)]; // Wo^T hi
__device__ __nv_bfloat16 g_wotl[DOUT * (HH*DV)];
__device__ __nv_bfloat16 g_t2h[BB * DIN * (HH * DV)]; // T2cat hi
__device__ __nv_bfloat16 g_t2l[BB * DIN * (HH * DV)]; // T2cat lo
__device__ __nv_bfloat16 g_uth[BB * DOUT * DIN]; // U^T hi
__device__ __nv_bfloat16 g_utl[BB * DOUT * DIN]; // U^T lo

// Upper-triangle tile map for 4x4 tile grid
__constant__ int c_tri_i[10] = {0,0,0,0,1,1,1,2,2,3};
__constant__ int c_tri_j[10] = {0,1,2,3,1,2,3,2,3,3};

// ---------------------------------------------------------------------------
// f32x2 helpers (SIMT small GEMMs)
// ---------------------------------------------------------------------------
__device__ __forceinline__ unsigned long long pack2(float a) {
    unsigned long long r;
    asm("mov.b64 %0, {%1, %1};" : "=l"(r) : "f"(a));
    return r;
}
__device__ __forceinline__ void fma2(unsigned long long& acc,
                                     unsigned long long a,
                                     unsigned long long b) {
    asm("fma.rn.f32x2 %0, %1, %2, %0;" : "+l"(acc) : "l"(a), "l"(b));
}
__device__ __forceinline__ float lo32(unsigned long long v) {
    return __uint_as_float((unsigned)(v & 0xffffffffull));
}
__device__ __forceinline__ float hi32(unsigned long long v) {
    return __uint_as_float((unsigned)(v >> 32));
}
__device__ __forceinline__ unsigned short bfbits(__nv_bfloat16 h) {
    return ((__nv_bfloat16_raw)h).x;
}

// ---------------------------------------------------------------------------
// helpers for mma.sync path
// ---------------------------------------------------------------------------
__device__ __forceinline__ uint32_t smem_u32(const void* p) {
    uint32_t a;
    asm("{ .reg .u64 t; cvta.to.shared.u64 t, %1; cvt.u32.u64 %0, t; }"
        : "=r"(a) : "l"(p));
    return a;
}
__device__ __forceinline__ void cp_async16(uint32_t dst, const void* src) {
    asm volatile("cp.async.cg.shared.global [%0], [%1], 16;" :: "r"(dst), "l"(src));
}
__device__ __forceinline__ void ldmx4(uint32_t* r, uint32_t addr) {
    asm volatile("ldmatrix.sync.aligned.m8n8.x4.shared.b16 {%0,%1,%2,%3}, [%4];"
        : "=r"(r[0]), "=r"(r[1]), "=r"(r[2]), "=r"(r[3]) : "r"(addr));
}
__device__ __forceinline__ void mma16816(float* c, const uint32_t* a, const uint32_t* b) {
    asm volatile(
        "mma.sync.aligned.m16n8k16.row.col.f32.bf16.bf16.f32 "
        "{%0,%1,%2,%3}, {%4,%5,%6,%7}, {%8,%9}, {%0,%1,%2,%3};"
        : "+f"(c[0]), "+f"(c[1]), "+f"(c[2]), "+f"(c[3])
        : "r"(a[0]), "r"(a[1]), "r"(a[2]), "r"(a[3]), "r"(b[0]), "r"(b[1]));
}

// ---------------------------------------------------------------------------
// mmaT: C[128x128 tile] fp32 = split-bf16 A(M rows,K) @ B(N rows,K)^T
// 256 threads = 8 warps, warp tile 64x32. ldmatrix.x4 fragment loads
// (conflict-free with ROWB=80). 2 CTAs/SM via launch_bounds.
// Non-uniform k-split: split z1 gets nChunk + (z1<rem) chunks.
// ---------------------------------------------------------------------------
#define ROWB   80
#define MATB   (128 * ROWB)
#define BUFB   (4 * MATB)
#define MMA_SMEM (2 * BUFB)

template <bool TRI>
__global__ void __launch_bounds__(256, 2)
mmaT(const __nv_bfloat16* __restrict__ Ahi, const __nv_bfloat16* __restrict__ Alo,
     const __nv_bfloat16* __restrict__ Bhi, const __nv_bfloat16* __restrict__ Blo,
     float* __restrict__ C,
     int ldA, int ldB, int ldC, int nChunk, int rem, int d0,
     long aB, long bB, long cB, long cS)
{
    extern __shared__ char sm[];
    const uint32_t su = smem_u32(sm);

    const int t    = threadIdx.x;
    const int wid  = t >> 5;
    const int lane = t & 31;
    const int g    = lane >> 2;
    const int tq   = lane & 3;
    const int wm   = wid & 1;
    const int wn   = wid >> 1;

    const int z  = blockIdx.z;
    const int z0 = z % d0;
    const int z1 = z / d0;
    const int nCh = nChunk + (z1 < rem ? 1 : 0);
    const long kOff = ((long)z1 * nChunk + (z1 < rem ? z1 : rem)) * 32;

    long m0, n0;
    if (TRI) {
        m0 = (long)c_tri_i[blockIdx.x] * 128;
        n0 = (long)c_tri_j[blockIdx.x] * 128;
    } else {
        m0 = (long)blockIdx.y * 128;
        n0 = (long)blockIdx.x * 128;
    }

    const __nv_bfloat16* bAh = Ahi + (long)z0 * aB + kOff + m0 * ldA;
    const __nv_bfloat16* bAl = Alo + (long)z0 * aB + kOff + m0 * ldA;
    const __nv_bfloat16* bBh = Bhi + (long)z0 * bB + kOff + n0 * ldB;
    const __nv_bfloat16* bBl = Blo + (long)z0 * bB + kOff + n0 * ldB;
    C += (long)z0 * cB + (long)z1 * cS;

    const int r0 = t >> 2,        s0 = (t & 3) * 16;
    const int r1 = (t + 256) >> 2, s1 = ((t + 256) & 3) * 16;

    // ldmatrix lane address components
    const int l7 = lane & 7;
    const uint32_t aOff = (uint32_t)(wm * 64 + l7 + ((lane >> 3) & 1) * 8) * ROWB
                        + (uint32_t)(lane >> 4) * 16;
    // B x4 layout: quad 0: rows n..n+7,k0 | 1: rows,k8 | 2: rows+8,k0 | 3: rows+8,k8
    const uint32_t bQ = (uint32_t)(lane >> 3);
    const uint32_t bOff4 = (uint32_t)(wn * 32 + l7) * ROWB
                         + (bQ >> 1) * (8 * ROWB) + (bQ & 1) * 16;

    float acc[4][4][4];
#pragma unroll
    for (int i = 0; i < 4; i++)
#pragma unroll
        for (int j = 0; j < 4; j++)
#pragma unroll
            for (int k = 0; k < 4; k++) acc[i][j][k] = 0.f;

#define LOAD_CHUNK(cidx, buf)                                                   \
    do {                                                                        \
        const uint32_t sb_ = su + (buf) * BUFB;                                 \
        const long ko_ = (long)(cidx) * 32;                                     \
        cp_async16(sb_ + 0 * MATB + r0 * ROWB + s0, bAh + (long)r0 * ldA + ko_ + s0 / 2); \
        cp_async16(sb_ + 0 * MATB + r1 * ROWB + s1, bAh + (long)r1 * ldA + ko_ + s1 / 2); \
        cp_async16(sb_ + 1 * MATB + r0 * ROWB + s0, bAl + (long)r0 * ldA + ko_ + s0 / 2); \
        cp_async16(sb_ + 1 * MATB + r1 * ROWB + s1, bAl + (long)r1 * ldA + ko_ + s1 / 2); \
        cp_async16(sb_ + 2 * MATB + r0 * ROWB + s0, bBh + (long)r0 * ldB + ko_ + s0 / 2); \
        cp_async16(sb_ + 2 * MATB + r1 * ROWB + s1, bBh + (long)r1 * ldB + ko_ + s1 / 2); \
        cp_async16(sb_ + 3 * MATB + r0 * ROWB + s0, bBl + (long)r0 * ldB + ko_ + s0 / 2); \
        cp_async16(sb_ + 3 * MATB + r1 * ROWB + s1, bBl + (long)r1 * ldB + ko_ + s1 / 2); \
        asm volatile("cp.async.commit_group;" ::: "memory");                    \
    } while (0)

    LOAD_CHUNK(0, 0);

    for (int c = 0; c < nCh; c++) {
        const int buf = c & 1;
        if (c + 1 < nCh) {
            LOAD_CHUNK(c + 1, buf ^ 1);
            asm volatile("cp.async.wait_group 1;" ::: "memory");
        } else {
            asm volatile("cp.async.wait_group 0;" ::: "memory");
        }
        __syncthreads();

        const uint32_t sb = su + buf * BUFB;
#pragma unroll
        for (int s = 0; s < 2; s++) {
            const uint32_t so = s * 32;
            uint32_t ah[4][4], bfh[2][4], bfl[2][4];
#pragma unroll
            for (int mt = 0; mt < 4; mt++)
                ldmx4(ah[mt], sb + aOff + mt * (16 * ROWB) + so);
#pragma unroll
            for (int pq = 0; pq < 2; pq++) {
                ldmx4(bfh[pq], sb + 2 * MATB + bOff4 + pq * (16 * ROWB) + so);
                ldmx4(bfl[pq], sb + 3 * MATB + bOff4 + pq * (16 * ROWB) + so);
            }
            // pass 1: Ah * Bh
#pragma unroll
            for (int mt = 0; mt < 4; mt++)
#pragma unroll
                for (int nt = 0; nt < 4; nt++)
                    mma16816(acc[mt][nt], ah[mt], &bfh[nt >> 1][(nt & 1) * 2]);
            // issue Al loads now; latency hides under pass 2
            uint32_t al[4][4];
#pragma unroll
            for (int mt = 0; mt < 4; mt++)
                ldmx4(al[mt], sb + MATB + aOff + mt * (16 * ROWB) + so);
            // pass 2: Ah * Bl
#pragma unroll
            for (int mt = 0; mt < 4; mt++)
#pragma unroll
                for (int nt = 0; nt < 4; nt++)
                    mma16816(acc[mt][nt], ah[mt], &bfl[nt >> 1][(nt & 1) * 2]);
            // pass 3: Al * Bh
#pragma unroll
            for (int mt = 0; mt < 4; mt++)
#pragma unroll
                for (int nt = 0; nt < 4; nt++)
                    mma16816(acc[mt][nt], al[mt], &bfh[nt >> 1][(nt & 1) * 2]);
        }
        __syncthreads();
    }

#pragma unroll
    for (int mt = 0; mt < 4; mt++) {
#pragma unroll
        for (int nt = 0; nt < 4; nt++) {
            const long row = m0 + wm * 64 + mt * 16 + g;
            const long col = n0 + wn * 32 + nt * 8 + 2 * tq;
            float2 v0 = make_float2(acc[mt][nt][0], acc[mt][nt][1]);
            float2 v1 = make_float2(acc[mt][nt][2], acc[mt][nt][3]);
            *(float2*)&C[row * ldC + col]       = v0;
            *(float2*)&C[(row + 8) * ldC + col] = v1;
        }
    }
}

// ---------------------------------------------------------------------------
// sx4: fused row-split + transpose-split of x. grid (16, 128, BB), block (32,8)
// ---------------------------------------------------------------------------
__global__ void __launch_bounds__(256)
sx4(const float* __restrict__ x,
    __nv_bfloat16* __restrict__ xrh, __nv_bfloat16* __restrict__ xrl,
    __nv_bfloat16* __restrict__ xth, __nv_bfloat16* __restrict__ xtl)
{
    __shared__ float tl[32][33];
    const int b = blockIdx.z;
    const long xoff = (long)b * LL * DIN;
    const int c0 = blockIdx.x * 32;
    const int r0 = blockIdx.y * 32;
    const int tx = threadIdx.x, ty = threadIdx.y;
#pragma unroll
    for (int i = 0; i < 4; i++) {
        const int r = r0 + ty + 8 * i;
        const long o = xoff + (long)r * DIN + c0 + tx;
        const float v = x[o];
        tl[ty + 8 * i][tx] = v;
        const __nv_bfloat16 h = __float2bfloat16(v);
        const __nv_bfloat16 l = __float2bfloat16(v - __bfloat162float(h));
        xrh[o] = h;
        xrl[o] = l;
    }
    __syncthreads();
#pragma unroll
    for (int i = 0; i < 4; i++) {
        const float v = tl[tx][ty + 8 * i];
        const __nv_bfloat16 h = __float2bfloat16(v);
        const __nv_bfloat16 l = __float2bfloat16(v - __bfloat162float(h));
        const long o = xoff + (long)(c0 + ty + 8 * i) * LL + r0 + tx;
        xth[o] = h;
        xtl[o] = l;
    }
}

// ---------------------------------------------------------------------------
// splitT: in (R x C) fp32 -> out (C x R) bf16 hi/lo per z.
// ---------------------------------------------------------------------------
__global__ void __launch_bounds__(256)
splitT(const float* __restrict__ in, __nv_bfloat16* __restrict__ oh,
       __nv_bfloat16* __restrict__ ol, int R, int C)
{
    __shared__ float tl[32][33];
    const int b = blockIdx.z;
    in += (long)b * R * C;
    oh += (long)b * R * C;
    ol += (long)b * R * C;
    const int c0 = blockIdx.x * 32, r0 = blockIdx.y * 32;
    const int tx = threadIdx.x, ty = threadIdx.y;
#pragma unroll
    for (int i = 0; i < 4; i++)
        tl[ty + 8 * i][tx] = in[(long)(r0 + ty + 8 * i) * C + c0 + tx];
    __syncthreads();
#pragma unroll
    for (int i = 0; i < 4; i++) {
        const float v = tl[tx][ty + 8 * i];
        const __nv_bfloat16 h = __float2bfloat16(v);
        const __nv_bfloat16 l = __float2bfloat16(v - __bfloat162float(h));
        const long o = (long)(c0 + ty + 8 * i) * R + r0 + tx;
        oh[o] = h;
        ol[o] = l;
    }
}

// ---------------------------------------------------------------------------
// reduceGsymSplit: sum P gram partials (upper tiles) -> full symmetric G,
// emitted directly as bf16 hi/lo. grid (16,16,BB), block (32,8)
// ---------------------------------------------------------------------------
__global__ void __launch_bounds__(256)
reduceGsymSplit(const float* __restrict__ Gp,
                __nv_bfloat16* __restrict__ Gh, __nv_bfloat16* __restrict__ Gl,
                int P)
{
    __shared__ float s[32][33];
    const int b  = blockIdx.z;
    const int j0 = blockIdx.x * 32, i0 = blockIdx.y * 32;
    const int tx = threadIdx.x, ty = threadIdx.y;
    const long base = (long)b * DIN * DIN;
    const long PS   = (long)BB * DIN * DIN;

    if ((i0 >> 7) <= (j0 >> 7)) {
#pragma unroll
        for (int i = 0; i < 4; i++) {
            const int r = i0 + ty + 8 * i;
            float sum = 0.f;
            for (int p = 0; p < P; p++)
                sum += Gp[(long)p * PS + base + (long)r * DIN + j0 + tx];
            const __nv_bfloat16 h = __float2bfloat16(sum);
            const __nv_bfloat16 l = __float2bfloat16(sum - __bfloat162float(h));
            Gh[base + (long)r * DIN + j0 + tx] = h;
            Gl[base + (long)r * DIN + j0 + tx] = l;
        }
    } else {
#pragma unroll
        for (int i = 0; i < 4; i++) {
            const int r = j0 + ty + 8 * i;
            float sum = 0.f;
            for (int p = 0; p < P; p++)
                sum += Gp[(long)p * PS + base + (long)r * DIN + i0 + tx];
            s[ty + 8 * i][tx] = sum;
        }
        __syncthreads();
#pragma unroll
        for (int i = 0; i < 4; i++) {
            const float v = s[tx][ty + 8 * i];
            const __nv_bfloat16 h = __float2bfloat16(v);
            const __nv_bfloat16 l = __float2bfloat16(v - __bfloat162float(h));
            const long o = base + (long)(i0 + ty + 8 * i) * DIN + j0 + tx;
            Gh[o] = h;
            Gl[o] = l;
        }
    }
}

// ---------------------------------------------------------------------------
// redSplit: elementwise sum of P partials + bf16 split.
// ---------------------------------------------------------------------------
__global__ void __launch_bounds__(256)
redSplit(const float4* __restrict__ src, uint2* __restrict__ oh,
         uint2* __restrict__ ol, int S4, int P)
{
    const int i = blockIdx.x * 256 + threadIdx.x;
    if (i >= S4) return;
    float4 s = src[i];
    for (int p = 1; p < P; p++) {
        const float4 v = src[(long)p * S4 + i];
        s.x += v.x; s.y += v.y; s.z += v.z; s.w += v.w;
    }
    const __nv_bfloat16 hx = __float2bfloat16(s.x);
    const __nv_bfloat16 hy = __float2bfloat16(s.y);
    const __nv_bfloat16 hz = __float2bfloat16(s.z);
    const __nv_bfloat16 hw = __float2bfloat16(s.w);
    const __nv_bfloat16 lx = __float2bfloat16(s.x - __bfloat162float(hx));
    const __nv_bfloat16 ly = __float2bfloat16(s.y - __bfloat162float(hy));
    const __nv_bfloat16 lz = __float2bfloat16(s.z - __bfloat162float(hz));
    const __nv_bfloat16 lw = __float2bfloat16(s.w - __bfloat162float(hw));
    uint2 H, L;
    H.x = (uint32_t)bfbits(hx) | ((uint32_t)bfbits(hy) << 16);
    H.y = (uint32_t)bfbits(hz) | ((uint32_t)bfbits(hw) << 16);
    L.x = (uint32_t)bfbits(lx) | ((uint32_t)bfbits(ly) << 16);
    L.y = (uint32_t)bfbits(lz) | ((uint32_t)bfbits(lw) << 16);
    oh[i] = H;
    ol[i] = L;
}

// ---------------------------------------------------------------------------
// gemmSmall: C(64x64) = sum-partials(A) @ sum-partials(B), K=64. fp32 out.
// ---------------------------------------------------------------------------
template <int NPA, int NPB>
__global__ void __launch_bounds__(256)
gemmSmall(const float* __restrict__ A, const float* __restrict__ B,
          float* __restrict__ C,
          int lda, int ldb, int ldc,
          int d0, int d1,
          long a0, long a1, long a2,
          long b0, long b1, long b2,
          long c0, long c1, long c2,
          long pSA, long pSB)
{
    __shared__ __align__(16) float As[64 * 68];
    __shared__ __align__(16) float Bs[64 * 64];

    const int t  = threadIdx.x;
    const int tx = t & 15;
    const int ty = t >> 4;

    {
        const int z  = blockIdx.z;
        const int z0 = z % d0;
        const int zr = z / d0;
        const int z1 = zr % d1;
        const int z2 = zr / d1;
        A += (long)z0 * a0 + (long)z1 * a1 + (long)z2 * a2;
        B += (long)z0 * b0 + (long)z1 * b1 + (long)z2 * b2;
        C += (long)z0 * c0 + (long)z1 * c1 + (long)z2 * c2;
    }
    const long m0 = (long)blockIdx.y * 64;

    {
        const int m = t >> 2, kseg = (t & 3) * 16;
        const float* Ag = A + (m0 + m) * lda + kseg;
#pragma unroll
        for (int s = 0; s < 4; s++) {
            float4 v = *(const float4*)(Ag + s * 4);
#pragma unroll
            for (int pp = 1; pp < NPA; pp++) {
                const float4 w = *(const float4*)(Ag + (long)pp * pSA + s * 4);
                v.x += w.x; v.y += w.y; v.z += w.z; v.w += w.w;
            }
            *(float4*)&As[m * 68 + kseg + s * 4] = v;
        }
    }
    {
        const int r = t >> 2, cs = (t & 3) * 16;
        const float* Bg = B + (long)r * ldb + cs;
#pragma unroll
        for (int s = 0; s < 4; s++) {
            float4 v = *(const float4*)(Bg + s * 4);
#pragma unroll
            for (int pp = 1; pp < NPB; pp++) {
                const float4 w = *(const float4*)(Bg + (long)pp * pSB + s * 4);
                v.x += w.x; v.y += w.y; v.z += w.z; v.w += w.w;
            }
            *(float4*)&Bs[r * 64 + cs + s * 4] = v;
        }
    }
    __syncthreads();

    unsigned long long acc[4][2];
#pragma unroll
    for (int i = 0; i < 4; i++) { acc[i][0] = 0ull; acc[i][1] = 0ull; }

#pragma unroll 8
    for (int kk = 0; kk < 64; kk++) {
        const ulonglong2 bv = *(const ulonglong2*)&Bs[kk * 64 + tx * 4];
        const unsigned long long bb0 = bv.x, bb1 = bv.y;
        unsigned long long p;
        p = pack2(As[(ty * 4 + 0) * 68 + kk]); fma2(acc[0][0], p, bb0); fma2(acc[0][1], p, bb1);
        p = pack2(As[(ty * 4 + 1) * 68 + kk]); fma2(acc[1][0], p, bb0); fma2(acc[1][1], p, bb1);
        p = pack2(As[(ty * 4 + 2) * 68 + kk]); fma2(acc[2][0], p, bb0); fma2(acc[2][1], p, bb1);
        p = pack2(As[(ty * 4 + 3) * 68 + kk]); fma2(acc[3][0], p, bb0); fma2(acc[3][1], p, bb1);
    }

#pragma unroll
    for (int i = 0; i < 4; i++) {
        float4 o;
        o.x = lo32(acc[i][0]); o.y = hi32(acc[i][0]);
        o.z = lo32(acc[i][1]); o.w = hi32(acc[i][1]);
        *(float4*)&C[(m0 + ty * 4 + i) * ldc + tx * 4] = o;
    }
}

// gemmSmallSplit: same but B-partials summed (NPB) and bf16 hi/lo output.
template <int NPB>
__global__ void __launch_bounds__(256)
gemmSmallSplit(const float* __restrict__ A, const float* __restrict__ B,
               __nv_bfloat16* __restrict__ Ch, __nv_bfloat16* __restrict__ Cl,
               int lda, int ldb, int ldc,
               int d0, int d1,
               long a0, long a1, long a2,
               long b0, long b1, long b2,
               long c0, long c1, long c2,
               long pSB)
{
    __shared__ __align__(16) float As[64 * 68];
    __shared__ __align__(16) float Bs[64 * 64];

    const int t  = threadIdx.x;
    const int tx = t & 15;
    const int ty = t >> 4;

    {
        const int z  = blockIdx.z;
        const int z0 = z % d0;
        const int zr = z / d0;
        const int z1 = zr % d1;
        const int z2 = zr / d1;
        A  += (long)z0 * a0 + (long)z1 * a1 + (long)z2 * a2;
        B  += (long)z0 * b0 + (long)z1 * b1 + (long)z2 * b2;
        Ch += (long)z0 * c0 + (long)z1 * c1 + (long)z2 * c2;
        Cl += (long)z0 * c0 + (long)z1 * c1 + (long)z2 * c2;
    }
    const long m0 = (long)blockIdx.y * 64;

    {
        const int m = t >> 2, kseg = (t & 3) * 16;
        const float* Ag = A + (m0 + m) * lda + kseg;
#pragma unroll
        for (int s = 0; s < 4; s++)
            *(float4*)&As[m * 68 + kseg + s * 4] = *(const float4*)(Ag + s * 4);
    }
    {
        const int r = t >> 2, cs = (t & 3) * 16;
        const float* Bg = B + (long)r * ldb + cs;
#pragma unroll
        for (int s = 0; s < 4; s++) {
            float4 v = *(const float4*)(Bg + s * 4);
#pragma unroll
            for (int pp = 1; pp < NPB; pp++) {
                const float4 w = *(const float4*)(Bg + (long)pp * pSB + s * 4);
                v.x += w.x; v.y += w.y; v.z += w.z; v.w += w.w;
            }
            *(float4*)&Bs[r * 64 + cs + s * 4] = v;
        }
    }
    __syncthreads();

    unsigned long long acc[4][2];
#pragma unroll
    for (int i = 0; i < 4; i++) { acc[i][0] = 0ull; acc[i][1] = 0ull; }

#pragma unroll 8
    for (int kk = 0; kk < 64; kk++) {
        const ulonglong2 bv = *(const ulonglong2*)&Bs[kk * 64 + tx * 4];
        const unsigned long long bb0 = bv.x, bb1 = bv.y;
        unsigned long long p;
        p = pack2(As[(ty * 4 + 0) * 68 + kk]); fma2(acc[0][0], p, bb0); fma2(acc[0][1], p, bb1);
        p = pack2(As[(ty * 4 + 1) * 68 + kk]); fma2(acc[1][0], p, bb0); fma2(acc[1][1], p, bb1);
        p = pack2(As[(ty * 4 + 2) * 68 + kk]); fma2(acc[2][0], p, bb0); fma2(acc[2][1], p, bb1);
        p = pack2(As[(ty * 4 + 3) * 68 + kk]); fma2(acc[3][0], p, bb0); fma2(acc[3][1], p, bb1);
    }

#pragma unroll
    for (int i = 0; i < 4; i++) {
        const float f0 = lo32(acc[i][0]), f1 = hi32(acc[i][0]);
        const float f2 = lo32(acc[i][1]), f3 = hi32(acc[i][1]);
        const __nv_bfloat16 h0 = __float2bfloat16(f0);
        const __nv_bfloat16 h1 = __float2bfloat16(f1);
        const __nv_bfloat16 h2 = __float2bfloat16(f2);
        const __nv_bfloat16 h3 = __float2bfloat16(f3);
        const __nv_bfloat16 l0 = __float2bfloat16(f0 - __bfloat162float(h0));
        const __nv_bfloat16 l1 = __float2bfloat16(f1 - __bfloat162float(h1));
        const __nv_bfloat16 l2 = __float2bfloat16(f2 - __bfloat162float(h2));
        const __nv_bfloat16 l3 = __float2bfloat16(f3 - __bfloat162float(h3));
        uint2 H, L;
        H.x = (uint32_t)bfbits(h0) | ((uint32_t)bfbits(h1) << 16);
        H.y = (uint32_t)bfbits(h2) | ((uint32_t)bfbits(h3) << 16);
        L.x = (uint32_t)bfbits(l0) | ((uint32_t)bfbits(l1) << 16);
        L.y = (uint32_t)bfbits(l2) | ((uint32_t)bfbits(l3) << 16);
        *(uint2*)&Ch[(m0 + ty * 4 + i) * ldc + tx * 4] = H;
        *(uint2*)&Cl[(m0 + ty * 4 + i) * ldc + tx * 4] = L;
    }
}

// ---------------------------------------------------------------------------
// kernel_launch: 11 launches, heavy work on tensor pipe, wave-fitted grids
// ---------------------------------------------------------------------------
extern "C" void kernel_launch(void* const* d_in, const int* in_sizes, int n_in,
                              void* d_out, int out_size)
{
    (void)in_sizes; (void)n_in; (void)out_size;
    const float* x  = (const float*)d_in[0];
    const float* Wq = (const float*)d_in[1];
    const float* Wk = (const float*)d_in[2];
    const float* Wv = (const float*)d_in[3];
    const float* Wo = (const float*)d_in[4];
    float* out = (float*)d_out;

    void* p;
    cudaGetSymbolAddress(&p, g_Gp  ); float* Gp  = (float*)p;
    cudaGetSymbolAddress(&p, g_T1p ); float* T1p = (float*)p;
    cudaGetSymbolAddress(&p, g_Mp  ); float* Mp  = (float*)p;
    cudaGetSymbolAddress(&p, g_Utp ); float* Utp = (float*)p;
    cudaGetSymbolAddress(&p, g_xrh ); __nv_bfloat16* xrh = (__nv_bfloat16*)p;
    cudaGetSymbolAddress(&p, g_xrl ); __nv_bfloat16* xrl = (__nv_bfloat16*)p;
    cudaGetSymbolAddress(&p, g_xth ); __nv_bfloat16* xth = (__nv_bfloat16*)p;
    cudaGetSymbolAddress(&p, g_xtl ); __nv_bfloat16* xtl = (__nv_bfloat16*)p;
    cudaGetSymbolAddress(&p, g_Gh  ); __nv_bfloat16* Gh  = (__nv_bfloat16*)p;
    cudaGetSymbolAddress(&p, g_Gl  ); __nv_bfloat16* Gl  = (__nv_bfloat16*)p;
    cudaGetSymbolAddress(&p, g_wkth); __nv_bfloat16* wkth = (__nv_bfloat16*)p;
    cudaGetSymbolAddress(&p, g_wktl); __nv_bfloat16* wktl = (__nv_bfloat16*)p;
    cudaGetSymbolAddress(&p, g_woth); __nv_bfloat16* woth = (__nv_bfloat16*)p;
    cudaGetSymbolAddress(&p, g_wotl); __nv_bfloat16* wotl = (__nv_bfloat16*)p;
    cudaGetSymbolAddress(&p, g_t2h ); __nv_bfloat16* t2h = (__nv_bfloat16*)p;
    cudaGetSymbolAddress(&p, g_t2l ); __nv_bfloat16* t2l = (__nv_bfloat16*)p;
    cudaGetSymbolAddress(&p, g_uth ); __nv_bfloat16* uth = (__nv_bfloat16*)p;
    cudaGetSymbolAddress(&p, g_utl ); __nv_bfloat16* utl = (__nv_bfloat16*)p;

    static bool attr_done = false;
    if (!attr_done) {
        cudaFuncSetAttribute(mmaT<true>,  cudaFuncAttributeMaxDynamicSharedMemorySize, MMA_SMEM);
        cudaFuncSetAttribute(mmaT<false>, cudaFuncAttributeMaxDynamicSharedMemorySize, MMA_SMEM);
        attr_done = true;
    }

    const long xB = (long)LL * DIN;      // 2097152
    const long GS = (long)DIN * DIN;     // 262144

    // 1) weight prep: Wkcat^T split; per-head 512x64 transpose
    splitT<<<dim3(2, 16, HH), dim3(32, 8)>>>(Wk, wkth, wktl, DIN, DK);
    // 2) weight prep: Wo^T split; 512x512 transpose
    splitT<<<dim3(16, 16, 1), dim3(32, 8)>>>(Wo, woth, wotl, HH * DV, DOUT);

    // 3) fused x splits
    sx4<<<dim3(16, 128, BB), dim3(32, 8)>>>(x, xrh, xrl, xth, xtl);

    // 4) Gram partials: 10 tri-tiles x (b, ks=14) = 280 blocks (single wave).
    //    splits 0-1 take 10 chunks, 2-13 take 9 (9*14+2 = 128 chunks = K 4096).
    mmaT<true><<<dim3(10, 1, BB * 14), 256, MMA_SMEM>>>(
        xth, xtl, xth, xtl, Gp,
        LL, LL, DIN, /*nChunk=*/9, /*rem=*/2, /*d0=*/BB,
        xB, xB, GS, (long)BB * GS);

    // 5) G = sum_ks Gp (14 partials), mirrored, bf16-split
    reduceGsymSplit<<<dim3(16, 16, BB), dim3(32, 8)>>>(Gp, Gh, Gl, 14);

    // 6) T1 partials via tensor: k-split 8 -> 256 blocks, nChunk=2
    mmaT<false><<<dim3(4, 4, BB * 8), 256, MMA_SMEM>>>(
        wkth, wktl, Gh, Gl, T1p,
        DIN, DIN, DIN, /*nChunk=*/2, /*rem=*/0, /*d0=*/BB,
        0, GS, GS, (long)BB * GS);

    // 7) M partials: Mp[ks][b][h] = (sum_p T1p)[h-rows, ks-chunk] @ Wv[h][ks-chunk]
    gemmSmall<8, 1><<<dim3(1, 1, 128), 256>>>(T1p, Wv, Mp,
        DIN, DV, DV,
        HH, BB,
        64L * DIN, GS, 64,
        (long)DIN * DV, 0, 64L * DV,
        (long)DK * DV, (long)HH * DK * DV, (long)BB * HH * DK * DV,
        /*pSA=*/(long)BB * GS, /*pSB=*/0);

    // 8) T2cat = Wq[h] @ (sum_p Mp)[b][h], emitted as bf16 hi/lo
    gemmSmallSplit<8><<<dim3(1, 8, 16), 256>>>(Wq, Mp, t2h, t2l,
        DK, DV, HH * DV,
        HH, BB,
        (long)DIN * DK, 0, 0,
        (long)DK * DV, (long)HH * DK * DV, 0,
        DV, (long)DIN * HH * DV, 0,
        /*pSB=*/(long)BB * HH * DK * DV);

    // 9) U^T partials via tensor: k-split 8 -> 256 blocks, nChunk=2
    mmaT<false><<<dim3(4, 4, BB * 8), 256, MMA_SMEM>>>(
        woth, wotl, t2h, t2l, Utp,
        HH * DV, HH * DV, DIN, /*nChunk=*/2, /*rem=*/0, /*d0=*/BB,
        0, (long)DIN * HH * DV, (long)DOUT * DIN, (long)BB * DOUT * DIN);

    // 10) U^T = sum_ks Utp (8 partials), bf16-split
    redSplit<<<512, 256>>>((const float4*)Utp, (uint2*)uth, (uint2*)utl,
                           (BB * DOUT * DIN) / 4, 8);

    // 11) out = x @ U via tensor (256 blocks, single wave)
    mmaT<false><<<dim3(4, 32, BB), 256, MMA_SMEM>>>(
        xrh, xrl, uth, utl, out,
        DIN, DIN, DOUT, /*nChunk=*/16, /*rem=*/0, /*d0=*/BB,
        xB, (long)DOUT * DIN, (long)LL * DOUT, 0);
}